// round 8
// baseline (speedup 1.0000x reference)
#include <cuda_runtime.h>
#include <cuda_fp16.h>
#include <math.h>

typedef unsigned long long ull;

#define NB 4
#define NV 16384
#define NK 16
#define NE 32
#define ND 64
#define NH 4
#define NL 2
#define NEGV (-1e9f)
#define NODES (NB * NV)

// ---------------- scratch ----------------
__device__ float g_h[NODES * ND];
__device__ __half g_t[(size_t)NODES * NH * ND];   // fp16 storage: halves gather traffic
__device__ float g_ssrc[NODES * NH];
__device__ float g_sdst[NODES * NH];
__device__ float g_m[NODES * ND];
__device__ float g_nodew[NODES];
__device__ float g_sn[NODES];
__device__ float g_inflowA[NODES];
__device__ float g_inflowB[NODES];

__device__ __forceinline__ float sigmoidf_(float x) { return 1.0f / (1.0f + expf(-x)); }

__device__ __forceinline__ ull pack2(float x) {
    ull r; asm("mov.b64 %0, {%1, %1};" : "=l"(r) : "f"(x)); return r;
}
__device__ __forceinline__ ull packf2(float a, float b) {
    ull r; asm("mov.b64 %0, {%1, %2};" : "=l"(r) : "f"(a), "f"(b)); return r;
}
__device__ __forceinline__ void ffma2(ull& d, ull a, ull b) {
    asm("fma.rn.f32x2 %0, %1, %2, %0;" : "+l"(d) : "l"(a), "l"(b));
}
__device__ __forceinline__ float2 unpk(ull v) {
    float2 f; asm("mov.b64 {%0, %1}, %2;" : "=f"(f.x), "=f"(f.y) : "l"(v)); return f;
}
__device__ __forceinline__ void st4(float* p, float a, float b, float c, float d) {
    *reinterpret_cast<float4*>(p) = make_float4(a, b, c, d);
}
__device__ __forceinline__ unsigned h2u(__half2 h) {
    unsigned u; *reinterpret_cast<__half2*>(&u) = h; return u;
}

// stage 128 node rows of 64 floats TRANSPOSED into xs[64][128] (thread = node)
__device__ __forceinline__ void stage_xT(const float* __restrict__ g, float* xs) {
    int tid = threadIdx.x;
    const float4* g4 = reinterpret_cast<const float4*>(g + (size_t)tid * ND);
#pragma unroll
    for (int c = 0; c < 16; c++) {
        float4 v = __ldg(g4 + c);
        xs[(4 * c + 0) * 128 + tid] = v.x;
        xs[(4 * c + 1) * 128 + tid] = v.y;
        xs[(4 * c + 2) * 128 + tid] = v.z;
        xs[(4 * c + 3) * 128 + tid] = v.w;
    }
}
// load weight matrix into smem, 128 threads
__device__ __forceinline__ void load_w(const float* __restrict__ g, float* ws, int nfloats) {
    const float4* g4 = reinterpret_cast<const float4*>(g);
    float4* s4 = reinterpret_cast<float4*>(ws);
    for (int i = threadIdx.x; i < (nfloats >> 2); i += 128) s4[i] = __ldg(g4 + i);
}

// register-tiled pass: acc[j*4+p] (cols tc8+j, node-pair p) += xs^T @ ws
template <int K>
__device__ __forceinline__ void gpass(const float* __restrict__ xs, const float* __restrict__ Ws,
                                      ull acc[32], int tn8, int tc8) {
#pragma unroll 4
    for (int k = 0; k < K; k++) {
        const ulonglong2* xr = reinterpret_cast<const ulonglong2*>(xs + k * 128 + tn8);
        ulonglong2 xa = xr[0], xb = xr[1];
        const float4* wr = reinterpret_cast<const float4*>(Ws + k * ND + tc8);
        float4 wa = wr[0], wb = wr[1];
        ull w0 = pack2(wa.x), w1 = pack2(wa.y), w2 = pack2(wa.z), w3 = pack2(wa.w);
        ull w4 = pack2(wb.x), w5 = pack2(wb.y), w6 = pack2(wb.z), w7 = pack2(wb.w);
#define FFJ(j, wv)                    \
    ffma2(acc[(j)*4 + 0], wv, xa.x);  \
    ffma2(acc[(j)*4 + 1], wv, xa.y);  \
    ffma2(acc[(j)*4 + 2], wv, xb.x);  \
    ffma2(acc[(j)*4 + 3], wv, xb.y);
        FFJ(0, w0) FFJ(1, w1) FFJ(2, w2) FFJ(3, w3)
        FFJ(4, w4) FFJ(5, w5) FFJ(6, w6) FFJ(7, w7)
#undef FFJ
    }
}

__device__ __forceinline__ void acc_bias(ull acc[32], const float* __restrict__ b, int tc8) {
#pragma unroll
    for (int j = 0; j < 8; j++) {
        ull v = pack2(__ldg(&b[tc8 + j]));
        acc[j * 4 + 0] = v; acc[j * 4 + 1] = v; acc[j * 4 + 2] = v; acc[j * 4 + 3] = v;
    }
}
__device__ __forceinline__ void acc_zero(ull acc[32]) {
#pragma unroll
    for (int i = 0; i < 32; i++) acc[i] = 0ull;
}

// ---------------- encoder ----------------
#define ENC_SMEM ((34 * 128 + 34 * 64 + 64 * 128 + 64 * 64) * 4)
__global__ void __launch_bounds__(128, 3)
k_encoder(const float* __restrict__ emb, const float* __restrict__ feat,
          const float* __restrict__ W1, const float* __restrict__ b1,
          const float* __restrict__ W2, const float* __restrict__ b2) {
    extern __shared__ float sm[];
    float* xs1 = sm;                   // [34][128]
    float* W1s = xs1 + 34 * 128;       // [34][64]
    float* xs2 = W1s + 34 * 64;        // [64][128]
    float* W2s = xs2 + 64 * 128;       // [64][64]
    int tid = threadIdx.x;
    int nb0 = blockIdx.x * 128;
    int tn8 = (tid >> 3) * 8, tc8 = (tid & 7) * 8;

    {  // stage [emb|feat] transposed
        const float4* e4 = reinterpret_cast<const float4*>(emb + (size_t)(nb0 + tid) * NE);
#pragma unroll
        for (int c = 0; c < 8; c++) {
            float4 v = __ldg(e4 + c);
            xs1[(4 * c + 0) * 128 + tid] = v.x;
            xs1[(4 * c + 1) * 128 + tid] = v.y;
            xs1[(4 * c + 2) * 128 + tid] = v.z;
            xs1[(4 * c + 3) * 128 + tid] = v.w;
        }
        float2 fv = __ldg(reinterpret_cast<const float2*>(feat + (size_t)(nb0 + tid) * 2));
        xs1[32 * 128 + tid] = fv.x;
        xs1[33 * 128 + tid] = fv.y;
    }
    load_w(W1, W1s, 34 * 64);
    load_w(W2, W2s, 64 * 64);
    g_inflowA[nb0 + tid] = 0.0f;
    g_inflowB[nb0 + tid] = 0.0f;
    __syncthreads();

    ull acc[32];
    acc_bias(acc, b1, tc8);
    gpass<34>(xs1, W1s, acc, tn8, tc8);
#pragma unroll
    for (int j = 0; j < 8; j++)
#pragma unroll
        for (int p = 0; p < 4; p++) {
            float2 v = unpk(acc[j * 4 + p]);
            *reinterpret_cast<ull*>(xs2 + (tc8 + j) * 128 + tn8 + 2 * p) =
                packf2(tanhf(v.x), tanhf(v.y));
        }
    __syncthreads();

    acc_bias(acc, b2, tc8);
    gpass<64>(xs2, W2s, acc, tn8, tc8);
#pragma unroll
    for (int p = 0; p < 4; p++) {
        float o0[8], o1[8];
#pragma unroll
        for (int j = 0; j < 8; j++) {
            float2 v = unpk(acc[j * 4 + p]);
            o0[j] = tanhf(v.x); o1[j] = tanhf(v.y);
        }
        float* r0 = g_h + (size_t)(nb0 + tn8 + 2 * p) * ND + tc8;
        st4(r0, o0[0], o0[1], o0[2], o0[3]); st4(r0 + 4, o0[4], o0[5], o0[6], o0[7]);
        float* r1 = r0 + ND;
        st4(r1, o1[0], o1[1], o1[2], o1[3]); st4(r1 + 4, o1[4], o1[5], o1[6], o1[7]);
    }
}

// ---------------- GAT transform: t (fp16 out) + a_src/a_dst dots ----------------
#define GAT_SMEM ((64 * 128 + 64 * 64) * 4)
__global__ void __launch_bounds__(128, 3)
k_gat_t(const float* __restrict__ Wgat, const float* __restrict__ asrc,
        const float* __restrict__ adst) {
    extern __shared__ float sm[];
    float* xs = sm;             // [64][128]
    float* Ws = sm + 64 * 128;  // [64][64]
    int tid = threadIdx.x;
    int nb0 = blockIdx.x * 128;
    int tn8 = (tid >> 3) * 8, tc8 = (tid & 7) * 8;
    stage_xT(g_h + (size_t)nb0 * ND, xs);

    for (int hd = 0; hd < NH; hd++) {
        __syncthreads();
        load_w(Wgat + (size_t)hd * ND * ND, Ws, ND * ND);
        __syncthreads();
        ull acc[32];
        acc_zero(acc);
        gpass<64>(xs, Ws, acc, tn8, tc8);

        float as_[8], ad_[8];
#pragma unroll
        for (int j = 0; j < 8; j++) {
            as_[j] = __ldg(&asrc[hd * ND + tc8 + j]);
            ad_[j] = __ldg(&adst[hd * ND + tc8 + j]);
        }
        float ss8[8], sd8[8];
#pragma unroll
        for (int p = 0; p < 4; p++) {
            float o0[8], o1[8];
            float s0 = 0.f, s1 = 0.f, d0 = 0.f, d1 = 0.f;
#pragma unroll
            for (int j = 0; j < 8; j++) {
                float2 v = unpk(acc[j * 4 + p]);
                o0[j] = v.x; o1[j] = v.y;
                s0 += v.x * as_[j]; d0 += v.x * ad_[j];
                s1 += v.y * as_[j]; d1 += v.y * ad_[j];
            }
            // fp16 store: 8 cols = 16B per node row
            __half* t0 = g_t + ((size_t)(nb0 + tn8 + 2 * p) * NH + hd) * ND + tc8;
            uint4 u0;
            u0.x = h2u(__floats2half2_rn(o0[0], o0[1]));
            u0.y = h2u(__floats2half2_rn(o0[2], o0[3]));
            u0.z = h2u(__floats2half2_rn(o0[4], o0[5]));
            u0.w = h2u(__floats2half2_rn(o0[6], o0[7]));
            *reinterpret_cast<uint4*>(t0) = u0;
            __half* t1 = t0 + NH * ND;
            uint4 u1;
            u1.x = h2u(__floats2half2_rn(o1[0], o1[1]));
            u1.y = h2u(__floats2half2_rn(o1[2], o1[3]));
            u1.z = h2u(__floats2half2_rn(o1[4], o1[5]));
            u1.w = h2u(__floats2half2_rn(o1[6], o1[7]));
            *reinterpret_cast<uint4*>(t1) = u1;
            ss8[2 * p] = s0; ss8[2 * p + 1] = s1;
            sd8[2 * p] = d0; sd8[2 * p + 1] = d1;
        }
#pragma unroll
        for (int q = 0; q < 8; q++) {
#pragma unroll
            for (int off = 4; off > 0; off >>= 1) {
                ss8[q] += __shfl_xor_sync(0xffffffffu, ss8[q], off);
                sd8[q] += __shfl_xor_sync(0xffffffffu, sd8[q], off);
            }
        }
        if ((tid & 7) == 0) {
#pragma unroll
            for (int q = 0; q < 8; q++) {
                g_ssrc[(size_t)(nb0 + tn8 + q) * NH + hd] = ss8[q];
                g_sdst[(size_t)(nb0 + tn8 + q) * NH + hd] = sd8[q];
            }
        }
    }
}

// ---------------- GAT attention + aggregation (fp16 gather) ----------------
__global__ void k_gat_attn(const int* __restrict__ adj) {
    __shared__ float s_agg[4][NH][ND];
    int wid = threadIdx.x >> 5, lane = threadIdx.x & 31;
    int ni = wid >> 2, hd = wid & 3;
    int n = (blockIdx.x << 2) + ni;
    int b = n >> 14;

    float score = NEGV;
    int idx = NV;
    if (lane < NK) {
        idx = __ldg(&adj[(size_t)n * NK + lane]);
        if (idx < NV)
            score = __ldg(&g_ssrc[(size_t)n * NH + hd]) +
                    __ldg(&g_sdst[((size_t)(b << 14) + idx) * NH + hd]);
    }
    float mx = score;
#pragma unroll
    for (int o = 16; o > 0; o >>= 1) mx = fmaxf(mx, __shfl_xor_sync(0xffffffffu, mx, o));
    float e = (lane < NK) ? expf(score - mx) : 0.0f;
    float s = e;
#pragma unroll
    for (int o = 16; o > 0; o >>= 1) s += __shfl_xor_sync(0xffffffffu, s, o);
    float attn = e / s;

    float ax = 0.0f, ay = 0.0f;
#pragma unroll
    for (int k = 0; k < NK; k++) {
        int j = __shfl_sync(0xffffffffu, idx, k);
        float a = __shfl_sync(0xffffffffu, attn, k);
        if (j < NV) {
            const __half2* tp =
                reinterpret_cast<const __half2*>(g_t + (((size_t)(b << 14) + j) * NH + hd) * ND);
            float2 tv = __half22float2(__ldg(tp + lane));
            ax += a * tv.x; ay += a * tv.y;
        }
    }
    s_agg[ni][hd][2 * lane] = ax;
    s_agg[ni][hd][2 * lane + 1] = ay;
    __syncthreads();
    if (threadIdx.x < 256) {
        int nn = threadIdx.x >> 6, j = threadIdx.x & 63;
        float t = s_agg[nn][0][j] + s_agg[nn][1][j] + s_agg[nn][2][j] + s_agg[nn][3][j];
        g_m[((size_t)(blockIdx.x << 2) + nn) * ND + j] = tanhf(t * 0.25f);
    }
}

// ---------------- fused GRU ----------------
#define GRU_SMEM ((3 * 64 * 128 + 64 * 64) * 4)
__global__ void __launch_bounds__(128, 2)
k_gru(const float* __restrict__ Wz, const float* __restrict__ Uz, const float* __restrict__ bz,
      const float* __restrict__ Wr, const float* __restrict__ Ur, const float* __restrict__ br,
      const float* __restrict__ Wc, const float* __restrict__ Uc, const float* __restrict__ bc) {
    extern __shared__ float sm[];
    float* xm = sm;               // [64][128]
    float* xh = sm + 64 * 128;
    float* xrh = sm + 2 * 64 * 128;
    float* Ws = sm + 3 * 64 * 128;  // [64][64]
    int tid = threadIdx.x;
    int nb0 = blockIdx.x * 128;
    int tn8 = (tid >> 3) * 8, tc8 = (tid & 7) * 8;

    stage_xT(g_m + (size_t)nb0 * ND, xm);
    stage_xT(g_h + (size_t)nb0 * ND, xh);
    load_w(Wz, Ws, ND * ND);
    __syncthreads();

    ull acc[32], zp[32];
    // ---- z ----
    acc_bias(acc, bz, tc8);
    gpass<64>(xm, Ws, acc, tn8, tc8);
    __syncthreads();
    load_w(Uz, Ws, ND * ND);
    __syncthreads();
    gpass<64>(xh, Ws, acc, tn8, tc8);
#pragma unroll
    for (int i = 0; i < 32; i++) {
        float2 v = unpk(acc[i]);
        zp[i] = packf2(sigmoidf_(v.x), sigmoidf_(v.y));
    }
    // ---- r, rh ----
    __syncthreads();
    load_w(Wr, Ws, ND * ND);
    __syncthreads();
    acc_bias(acc, br, tc8);
    gpass<64>(xm, Ws, acc, tn8, tc8);
    __syncthreads();
    load_w(Ur, Ws, ND * ND);
    __syncthreads();
    gpass<64>(xh, Ws, acc, tn8, tc8);
#pragma unroll
    for (int j = 0; j < 8; j++)
#pragma unroll
        for (int p = 0; p < 4; p++) {
            float2 rv = unpk(acc[j * 4 + p]);
            float2 hv = unpk(*reinterpret_cast<const ull*>(xh + (tc8 + j) * 128 + tn8 + 2 * p));
            *reinterpret_cast<ull*>(xrh + (tc8 + j) * 128 + tn8 + 2 * p) =
                packf2(sigmoidf_(rv.x) * hv.x, sigmoidf_(rv.y) * hv.y);
        }
    // ---- c, h' ----
    __syncthreads();
    load_w(Wc, Ws, ND * ND);
    __syncthreads();
    acc_bias(acc, bc, tc8);
    gpass<64>(xm, Ws, acc, tn8, tc8);
    __syncthreads();
    load_w(Uc, Ws, ND * ND);
    __syncthreads();
    gpass<64>(xrh, Ws, acc, tn8, tc8);
#pragma unroll
    for (int p = 0; p < 4; p++) {
        float o0[8], o1[8];
#pragma unroll
        for (int j = 0; j < 8; j++) {
            float2 cv = unpk(acc[j * 4 + p]);
            float2 hv = unpk(*reinterpret_cast<const ull*>(xh + (tc8 + j) * 128 + tn8 + 2 * p));
            float2 zv = unpk(zp[j * 4 + p]);
            o0[j] = hv.x + zv.x * (tanhf(cv.x) - hv.x);
            o1[j] = hv.y + zv.y * (tanhf(cv.y) - hv.y);
        }
        float* r0 = g_h + (size_t)(nb0 + tn8 + 2 * p) * ND + tc8;
        st4(r0, o0[0], o0[1], o0[2], o0[3]); st4(r0 + 4, o0[4], o0[5], o0[6], o0[7]);
        float* r1 = r0 + ND;
        st4(r1, o1[0], o1[1], o1[2], o1[3]); st4(r1 + 4, o1[4], o1[5], o1[6], o1[7]);
    }
}

// ---------------- decoder ----------------
#define DEC_SMEM ((64 * 128 + 64 * 64) * 4)
__global__ void __launch_bounds__(128, 3)
k_decoder(const float* __restrict__ W1, const float* __restrict__ b1,
          const float* __restrict__ W2, const float* __restrict__ b2) {
    extern __shared__ float sm[];
    float* xs = sm;
    float* Ws = sm + 64 * 128;
    int tid = threadIdx.x;
    int nb0 = blockIdx.x * 128;
    int tn8 = (tid >> 3) * 8, tc8 = (tid & 7) * 8;
    stage_xT(g_h + (size_t)nb0 * ND, xs);
    load_w(W1, Ws, ND * ND);
    __syncthreads();
    ull acc[32];
    acc_bias(acc, b1, tc8);
    gpass<64>(xs, Ws, acc, tn8, tc8);
    float w2_[8];
#pragma unroll
    for (int j = 0; j < 8; j++) w2_[j] = __ldg(&W2[tc8 + j]);
    float pw[8];
#pragma unroll
    for (int p = 0; p < 4; p++) {
        float s0 = 0.f, s1 = 0.f;
#pragma unroll
        for (int j = 0; j < 8; j++) {
            float2 v = unpk(acc[j * 4 + p]);
            s0 += tanhf(v.x) * w2_[j];
            s1 += tanhf(v.y) * w2_[j];
        }
        pw[2 * p] = s0; pw[2 * p + 1] = s1;
    }
#pragma unroll
    for (int q = 0; q < 8; q++)
#pragma unroll
        for (int off = 4; off > 0; off >>= 1)
            pw[q] += __shfl_xor_sync(0xffffffffu, pw[q], off);
    if ((tid & 7) == 0) {
        float b2v = __ldg(&b2[0]);
#pragma unroll
        for (int q = 0; q < 8; q++) g_nodew[nb0 + tn8 + q] = pw[q] + b2v;
    }
}

// ---------------- edge softmax + sumsq + flow0 scatter ----------------
__global__ void k_normw(const int* __restrict__ adj, const float* __restrict__ demands,
                        float* __restrict__ out_normw) {
    int n = blockIdx.x * blockDim.x + threadIdx.x;
    int base = (n >> 14) << 14;
    int idxv[NK];
    float sc[NK];
    float mx = NEGV;
#pragma unroll
    for (int k = 0; k < NK; k++) {
        int idx = __ldg(&adj[(size_t)n * NK + k]);
        idxv[k] = idx;
        float s = (idx < NV) ? __ldg(&g_nodew[(size_t)base + idx]) : NEGV;
        sc[k] = s;
        mx = fmaxf(mx, s);
    }
    float sum = 0.0f;
#pragma unroll
    for (int k = 0; k < NK; k++) { sc[k] = expf(sc[k] - mx); sum += sc[k]; }
    float inv = 1.0f / sum;
    float nf0 = fmaxf(-__ldg(&demands[n]), 0.0f);
    float sn = 0.0f;
#pragma unroll
    for (int k = 0; k < NK; k++) {
        float nw = sc[k] * inv;
        sc[k] = nw;
        sn += nw * nw;
        out_normw[(size_t)n * NK + k] = nw;
    }
    g_sn[n] = sn;
#pragma unroll
    for (int k = 0; k < NK; k++)
        if (idxv[k] < NV) atomicAdd(&g_inflowA[base + idxv[k]], sc[k] * nf0);
}

// ---------------- fused flow iteration ----------------
__global__ void k_flow_iter(const int* __restrict__ adj, const float* __restrict__ demands,
                            const float* __restrict__ normw, float* __restrict__ cur,
                            float* __restrict__ nxt, float* __restrict__ store) {
    int n = blockIdx.x * blockDim.x + threadIdx.x;
    int base = (n >> 14) << 14;
    float nf = fmaxf(cur[n] - __ldg(&demands[n]), 0.0f);
    cur[n] = 0.0f;
#pragma unroll
    for (int k = 0; k < NK; k++) {
        int idx = __ldg(&adj[(size_t)n * NK + k]);
        float f = __ldg(&normw[(size_t)n * NK + k]) * nf;
        if (store) store[(size_t)n * NK + k] = f;
        if (idx < NV) atomicAdd(&nxt[base + idx], f);
    }
}

// ---------------- final flow + cost ----------------
__global__ void k_flow_last(const float* __restrict__ demands, const float* __restrict__ normw,
                            float* __restrict__ cur, float* __restrict__ out_flow,
                            float* __restrict__ cost) {
    int n = blockIdx.x * blockDim.x + threadIdx.x;
    int b = n >> 14;
    float nf = fmaxf(cur[n] - __ldg(&demands[n]), 0.0f);
    cur[n] = 0.0f;
    const float4* nw4 = reinterpret_cast<const float4*>(normw + (size_t)n * NK);
    float4* o4 = reinterpret_cast<float4*>(out_flow + (size_t)n * NK);
#pragma unroll
    for (int k = 0; k < 4; k++) {
        float4 v = __ldg(nw4 + k);
        v.x *= nf; v.y *= nf; v.z *= nf; v.w *= nf;
        o4[k] = v;
    }
    float val = nf * nf * __ldg(&g_sn[n]);
#pragma unroll
    for (int o = 16; o > 0; o >>= 1) val += __shfl_xor_sync(0xffffffffu, val, o);
    __shared__ float ws[8];
    if ((threadIdx.x & 31) == 0) ws[threadIdx.x >> 5] = val;
    __syncthreads();
    if (threadIdx.x == 0) {
        float t = 0.0f;
#pragma unroll
        for (int i = 0; i < 8; i++) t += ws[i];
        atomicAdd(&cost[b], t);
    }
}

// ---------------- launch ----------------
extern "C" void kernel_launch(void* const* d_in, const int* in_sizes, int n_in,
                              void* d_out, int out_size) {
    const float* emb     = (const float*)d_in[0];
    const float* feat    = (const float*)d_in[1];
    const float* demands = (const float*)d_in[2];
    const int*   adj     = (const int*)d_in[3];
    int wb = (in_sizes[5] == 1) ? 6 : 5;
    const float* W_enc1 = (const float*)d_in[wb + 0];
    const float* b_enc1 = (const float*)d_in[wb + 1];
    const float* W_enc2 = (const float*)d_in[wb + 2];
    const float* b_enc2 = (const float*)d_in[wb + 3];
    const float* W_gat  = (const float*)d_in[wb + 4];
    const float* a_src  = (const float*)d_in[wb + 5];
    const float* a_dst  = (const float*)d_in[wb + 6];
    const float* W_z    = (const float*)d_in[wb + 7];
    const float* U_z    = (const float*)d_in[wb + 8];
    const float* b_z    = (const float*)d_in[wb + 9];
    const float* W_r    = (const float*)d_in[wb + 10];
    const float* U_r    = (const float*)d_in[wb + 11];
    const float* b_r    = (const float*)d_in[wb + 12];
    const float* W_c    = (const float*)d_in[wb + 13];
    const float* U_c    = (const float*)d_in[wb + 14];
    const float* b_c    = (const float*)d_in[wb + 15];
    const float* W_dec1 = (const float*)d_in[wb + 16];
    const float* b_dec1 = (const float*)d_in[wb + 17];
    const float* W_dec2 = (const float*)d_in[wb + 18];
    const float* b_dec2 = (const float*)d_in[wb + 19];

    float* out = (float*)d_out;
    float* out_flow  = out;                               // [B,V,K] f10
    float* out_cost  = out + (size_t)NB * NV * NK;        // [B]
    float* out_normw = out_cost + NB;                     // [B,V,K]
    float* out_pflow = out_normw + (size_t)NB * NV * NK;  // [B,V,K] f9

    float *pA, *pB;
    cudaGetSymbolAddress((void**)&pA, g_inflowA);
    cudaGetSymbolAddress((void**)&pB, g_inflowB);

    cudaFuncSetAttribute(k_encoder, cudaFuncAttributeMaxDynamicSharedMemorySize, ENC_SMEM);
    cudaFuncSetAttribute(k_gat_t, cudaFuncAttributeMaxDynamicSharedMemorySize, GAT_SMEM);
    cudaFuncSetAttribute(k_gru, cudaFuncAttributeMaxDynamicSharedMemorySize, GRU_SMEM);
    cudaFuncSetAttribute(k_decoder, cudaFuncAttributeMaxDynamicSharedMemorySize, DEC_SMEM);

    k_encoder<<<512, 128, ENC_SMEM>>>(emb, feat, W_enc1, b_enc1, W_enc2, b_enc2);
    for (int l = 0; l < NL; l++) {
        k_gat_t<<<512, 128, GAT_SMEM>>>(W_gat, a_src, a_dst);
        k_gat_attn<<<NODES / 4, 512>>>(adj);
        k_gru<<<512, 128, GRU_SMEM>>>(W_z, U_z, b_z, W_r, U_r, b_r, W_c, U_c, b_c);
    }
    k_decoder<<<512, 128, DEC_SMEM>>>(W_dec1, b_dec1, W_dec2, b_dec2);
    k_normw<<<256, 256>>>(adj, demands, out_normw);

    float* cur = pA;
    float* nxt = pB;
    for (int it = 0; it < 9; it++) {
        k_flow_iter<<<256, 256>>>(adj, demands, out_normw, cur, nxt,
                                  (it == 8) ? out_pflow : nullptr);
        float* tmp = cur; cur = nxt; nxt = tmp;
    }
    cudaMemsetAsync(out_cost, 0, NB * sizeof(float), 0);
    k_flow_last<<<256, 256>>>(demands, out_normw, cur, out_flow, out_cost);
}

// round 10
// speedup vs baseline: 1.2739x; 1.2739x over previous
#include <cuda_runtime.h>
#include <cuda_fp16.h>
#include <mma.h>
#include <math.h>

using namespace nvcuda;

#define NB 4
#define NV 16384
#define NK 16
#define NE 32
#define ND 64
#define NH 4
#define NL 2
#define NEGV (-1e9f)
#define NODES (NB * NV)

// ---------------- scratch ----------------
__device__ float g_h[NODES * ND];
__device__ __half g_t[(size_t)NODES * NH * ND];
__device__ float g_zscr[NODES * ND];
__device__ float g_ssrc[NODES * NH];
__device__ float g_sdst[NODES * NH];
__device__ float g_m[NODES * ND];
__device__ float g_nodew[NODES];
__device__ float g_sn[NODES];
__device__ float g_inflowA[NODES];
__device__ float g_inflowB[NODES];

__device__ __forceinline__ float sigmoidf_(float x) { return 1.0f / (1.0f + expf(-x)); }

// ---------------- staging helpers (128 threads) ----------------
// 128 rows x 64 fp32 -> fp16 smem [128][ld], column offset coff
__device__ __forceinline__ void stage_x16(const float* __restrict__ g, __half* xs, int ld, int coff) {
    int t = threadIdx.x;
    const float4* g4 = reinterpret_cast<const float4*>(g + (size_t)t * ND);
    __half2* row = reinterpret_cast<__half2*>(xs + (size_t)t * ld + coff);
#pragma unroll
    for (int c = 0; c < 16; c++) {
        float4 v = __ldg(g4 + c);
        row[2 * c] = __floats2half2_rn(v.x, v.y);
        row[2 * c + 1] = __floats2half2_rn(v.z, v.w);
    }
}
// W [K][64] fp32 -> fp16 smem ld 72, zero-pad rows >= KR
template <int K, int KR>
__device__ __forceinline__ void stage_w16(const float* __restrict__ g, __half* ws) {
    for (int i = threadIdx.x; i < K * 32; i += 128) {
        int r = i >> 5, c2 = i & 31;
        float2 v = make_float2(0.f, 0.f);
        if (r < KR) v = __ldg(reinterpret_cast<const float2*>(g + r * 64 + 2 * c2));
        *reinterpret_cast<__half2*>(ws + r * 72 + 2 * c2) = __floats2half2_rn(v.x, v.y);
    }
}
// stacked [A;B] (each 64x64 fp32) -> fp16 smem [128][72]
__device__ __forceinline__ void stage_wcat(const float* __restrict__ A, const float* __restrict__ B,
                                           __half* ws) {
    for (int i = threadIdx.x; i < 128 * 32; i += 128) {
        int r = i >> 5, c2 = i & 31;
        const float* src = (r < 64) ? (A + r * 64 + 2 * c2) : (B + (r - 64) * 64 + 2 * c2);
        float2 v = __ldg(reinterpret_cast<const float2*>(src));
        *reinterpret_cast<__half2*>(ws + r * 72 + 2 * c2) = __floats2half2_rn(v.x, v.y);
    }
}

// ---------------- WMMA GEMM: [128 x 16KT] @ [16KT x 64] -> O fp32 [128][72] ----------------
template <int KT, int ALD>
__device__ __forceinline__ void wgemm(const __half* Xs, const __half* Ws, float* Os) {
    int m0 = (threadIdx.x >> 5) * 32;
    wmma::fragment<wmma::accumulator, 16, 16, 16, float> c[2][4];
#pragma unroll
    for (int i = 0; i < 2; i++)
#pragma unroll
        for (int n = 0; n < 4; n++) wmma::fill_fragment(c[i][n], 0.0f);
#pragma unroll
    for (int kt = 0; kt < KT; kt++) {
        wmma::fragment<wmma::matrix_a, 16, 16, 16, __half, wmma::row_major> a0, a1;
        wmma::load_matrix_sync(a0, Xs + m0 * ALD + kt * 16, ALD);
        wmma::load_matrix_sync(a1, Xs + (m0 + 16) * ALD + kt * 16, ALD);
#pragma unroll
        for (int n = 0; n < 4; n++) {
            wmma::fragment<wmma::matrix_b, 16, 16, 16, __half, wmma::row_major> b;
            wmma::load_matrix_sync(b, Ws + kt * 16 * 72 + n * 16, 72);
            wmma::mma_sync(c[0][n], a0, b, c[0][n]);
            wmma::mma_sync(c[1][n], a1, b, c[1][n]);
        }
    }
#pragma unroll
    for (int i = 0; i < 2; i++)
#pragma unroll
        for (int n = 0; n < 4; n++)
            wmma::store_matrix_sync(Os + (m0 + i * 16) * 72 + n * 16, c[i][n], 72,
                                    wmma::mem_row_major);
}

// ---------------- encoder ----------------
#define ENC_SMEM (128 * 56 * 2 + 128 * 72 * 2 + 64 * 72 * 2 + 128 * 72 * 4)
__global__ void __launch_bounds__(128)
k_encoder(const float* __restrict__ emb, const float* __restrict__ feat,
          const float* __restrict__ W1, const float* __restrict__ b1,
          const float* __restrict__ W2, const float* __restrict__ b2) {
    extern __shared__ __align__(16) char smraw[];
    __half* X1 = (__half*)smraw;                          // [128][56], K=48 used (pad)
    __half* X2 = (__half*)(smraw + 128 * 56 * 2);         // [128][72]
    __half* Wb = (__half*)(smraw + 128 * 56 * 2 + 128 * 72 * 2);  // [<=64][72]
    float* O = (float*)(smraw + 128 * 56 * 2 + 128 * 72 * 2 + 64 * 72 * 2);
    int tid = threadIdx.x;
    int nb0 = blockIdx.x * 128;

    {  // stage [emb|feat|0pad] row per thread
        const float4* e4 = reinterpret_cast<const float4*>(emb + (size_t)(nb0 + tid) * NE);
        __half2* row = reinterpret_cast<__half2*>(X1 + (size_t)tid * 56);
#pragma unroll
        for (int c = 0; c < 8; c++) {
            float4 v = __ldg(e4 + c);
            row[2 * c] = __floats2half2_rn(v.x, v.y);
            row[2 * c + 1] = __floats2half2_rn(v.z, v.w);
        }
        float2 fv = __ldg(reinterpret_cast<const float2*>(feat + (size_t)(nb0 + tid) * 2));
        row[16] = __floats2half2_rn(fv.x, fv.y);
#pragma unroll
        for (int c2 = 17; c2 < 28; c2++) row[c2] = __floats2half2_rn(0.f, 0.f);
    }
    stage_w16<48, 34>(W1, Wb);
    g_inflowA[nb0 + tid] = 0.0f;
    g_inflowB[nb0 + tid] = 0.0f;
    __syncthreads();
    wgemm<3, 56>(X1, Wb, O);
    __syncthreads();
    // tanh(o + b1) -> X2 fp16
    for (int i = tid; i < 128 * 32; i += 128) {
        int row = i >> 5, c2 = i & 31;
        float o0 = O[row * 72 + 2 * c2] + __ldg(&b1[2 * c2]);
        float o1 = O[row * 72 + 2 * c2 + 1] + __ldg(&b1[2 * c2 + 1]);
        *reinterpret_cast<__half2*>(X2 + row * 72 + 2 * c2) =
            __floats2half2_rn(tanhf(o0), tanhf(o1));
    }
    stage_w16<64, 64>(W2, Wb);
    __syncthreads();
    wgemm<4, 72>(X2, Wb, O);
    __syncthreads();
    for (int i = tid; i < 128 * 16; i += 128) {
        int row = i >> 4, c4 = (i & 15) * 4;
        float4 o = *reinterpret_cast<const float4*>(O + row * 72 + c4);
        float4 r;
        r.x = tanhf(o.x + __ldg(&b2[c4]));
        r.y = tanhf(o.y + __ldg(&b2[c4 + 1]));
        r.z = tanhf(o.z + __ldg(&b2[c4 + 2]));
        r.w = tanhf(o.w + __ldg(&b2[c4 + 3]));
        *reinterpret_cast<float4*>(g_h + (size_t)(nb0 + row) * ND + c4) = r;
    }
}

// ---------------- GAT transform (tensor core) ----------------
#define GAT_SMEM (128 * 72 * 2 + 64 * 72 * 2 + 128 * 72 * 4)
__global__ void __launch_bounds__(128)
k_gat_t(const float* __restrict__ Wgat, const float* __restrict__ asrc,
        const float* __restrict__ adst) {
    extern __shared__ __align__(16) char smraw[];
    __half* Xs = (__half*)smraw;                       // [128][72]
    __half* Wb = (__half*)(smraw + 128 * 72 * 2);      // [64][72]
    float* O = (float*)(smraw + 128 * 72 * 2 + 64 * 72 * 2);
    int tid = threadIdx.x;
    int nb0 = blockIdx.x * 128;
    stage_x16(g_h + (size_t)nb0 * ND, Xs, 72, 0);

    for (int hd = 0; hd < NH; hd++) {
        __syncthreads();  // separates prev epilogue O-reads from this wgemm O-writes
        stage_w16<64, 64>(Wgat + (size_t)hd * ND * ND, Wb);
        __syncthreads();
        wgemm<4, 72>(Xs, Wb, O);
        __syncthreads();
        // t fp16 store (coalesced)
        for (int i = tid; i < 128 * 32; i += 128) {
            int row = i >> 5, c2 = i & 31;
            float o0 = O[row * 72 + 2 * c2], o1 = O[row * 72 + 2 * c2 + 1];
            *reinterpret_cast<__half2*>(g_t + ((size_t)(nb0 + row) * NH + hd) * ND + 2 * c2) =
                __floats2half2_rn(o0, o1);
        }
        // per-row score dots (thread = row)
        {
            float ss = 0.f, sd = 0.f;
            const float* orow = O + tid * 72;
#pragma unroll 8
            for (int j = 0; j < 64; j++) {
                float o = orow[j];
                ss += o * __ldg(&asrc[hd * ND + j]);
                sd += o * __ldg(&adst[hd * ND + j]);
            }
            g_ssrc[(size_t)(nb0 + tid) * NH + hd] = ss;
            g_sdst[(size_t)(nb0 + tid) * NH + hd] = sd;
        }
    }
}

// ---------------- GAT attention + aggregation (fp16 gather) ----------------
__global__ void k_gat_attn(const int* __restrict__ adj) {
    __shared__ float s_agg[4][NH][ND];
    int wid = threadIdx.x >> 5, lane = threadIdx.x & 31;
    int ni = wid >> 2, hd = wid & 3;
    int n = (blockIdx.x << 2) + ni;
    int b = n >> 14;

    float score = NEGV;
    int idx = NV;
    if (lane < NK) {
        idx = __ldg(&adj[(size_t)n * NK + lane]);
        if (idx < NV)
            score = __ldg(&g_ssrc[(size_t)n * NH + hd]) +
                    __ldg(&g_sdst[((size_t)(b << 14) + idx) * NH + hd]);
    }
    float mx = score;
#pragma unroll
    for (int o = 16; o > 0; o >>= 1) mx = fmaxf(mx, __shfl_xor_sync(0xffffffffu, mx, o));
    float e = (lane < NK) ? expf(score - mx) : 0.0f;
    float s = e;
#pragma unroll
    for (int o = 16; o > 0; o >>= 1) s += __shfl_xor_sync(0xffffffffu, s, o);
    float attn = e / s;

    float ax = 0.0f, ay = 0.0f;
#pragma unroll
    for (int k = 0; k < NK; k++) {
        int j = __shfl_sync(0xffffffffu, idx, k);
        float a = __shfl_sync(0xffffffffu, attn, k);
        if (j < NV) {
            const __half2* tp =
                reinterpret_cast<const __half2*>(g_t + (((size_t)(b << 14) + j) * NH + hd) * ND);
            float2 tv = __half22float2(__ldg(tp + lane));
            ax += a * tv.x; ay += a * tv.y;
        }
    }
    s_agg[ni][hd][2 * lane] = ax;
    s_agg[ni][hd][2 * lane + 1] = ay;
    __syncthreads();
    if (threadIdx.x < 256) {
        int nn = threadIdx.x >> 6, j = threadIdx.x & 63;
        float t = s_agg[nn][0][j] + s_agg[nn][1][j] + s_agg[nn][2][j] + s_agg[nn][3][j];
        g_m[((size_t)(blockIdx.x << 2) + nn) * ND + j] = tanhf(t * 0.25f);
    }
}

// ---------------- fused GRU: 3 concat GEMMs (K=128) ----------------
#define GRU_SMEM (128 * 136 * 2 + 128 * 72 * 2 + 128 * 72 * 4)
__global__ void __launch_bounds__(128)
k_gru(const float* __restrict__ Wz, const float* __restrict__ Uz, const float* __restrict__ bz,
      const float* __restrict__ Wr, const float* __restrict__ Ur, const float* __restrict__ br,
      const float* __restrict__ Wc, const float* __restrict__ Uc, const float* __restrict__ bc) {
    extern __shared__ __align__(16) char smraw[];
    __half* Xc = (__half*)smraw;                       // [128][136]: [m | h], later [m | r*h]
    __half* Wb = (__half*)(smraw + 128 * 136 * 2);     // [128][72]
    float* O = (float*)(smraw + 128 * 136 * 2 + 128 * 72 * 2);
    int tid = threadIdx.x;
    int nb0 = blockIdx.x * 128;

    stage_x16(g_m + (size_t)nb0 * ND, Xc, 136, 0);
    stage_x16(g_h + (size_t)nb0 * ND, Xc, 136, 64);
    // ---- z ----
    stage_wcat(Wz, Uz, Wb);
    __syncthreads();
    wgemm<8, 136>(Xc, Wb, O);
    __syncthreads();
    for (int i = tid; i < 128 * 16; i += 128) {
        int row = i >> 4, c4 = (i & 15) * 4;
        float4 o = *reinterpret_cast<const float4*>(O + row * 72 + c4);
        float4 r;
        r.x = sigmoidf_(o.x + __ldg(&bz[c4]));
        r.y = sigmoidf_(o.y + __ldg(&bz[c4 + 1]));
        r.z = sigmoidf_(o.z + __ldg(&bz[c4 + 2]));
        r.w = sigmoidf_(o.w + __ldg(&bz[c4 + 3]));
        *reinterpret_cast<float4*>(g_zscr + (size_t)(nb0 + row) * ND + c4) = r;
    }
    __syncthreads();
    // ---- r, r*h -> Xc right half ----
    stage_wcat(Wr, Ur, Wb);
    __syncthreads();
    wgemm<8, 136>(Xc, Wb, O);
    __syncthreads();
    for (int i = tid; i < 128 * 32; i += 128) {
        int row = i >> 5, c2 = i & 31;
        float o0 = O[row * 72 + 2 * c2] + __ldg(&br[2 * c2]);
        float o1 = O[row * 72 + 2 * c2 + 1] + __ldg(&br[2 * c2 + 1]);
        __half2* hp = reinterpret_cast<__half2*>(Xc + row * 136 + 64 + 2 * c2);
        float2 hf = __half22float2(*hp);
        *hp = __floats2half2_rn(sigmoidf_(o0) * hf.x, sigmoidf_(o1) * hf.y);
    }
    __syncthreads();
    // ---- c + combine ----
    stage_wcat(Wc, Uc, Wb);
    __syncthreads();
    wgemm<8, 136>(Xc, Wb, O);
    __syncthreads();
    for (int i = tid; i < 128 * 16; i += 128) {
        int row = i >> 4, c4 = (i & 15) * 4;
        float4 o = *reinterpret_cast<const float4*>(O + row * 72 + c4);
        float* hp = g_h + (size_t)(nb0 + row) * ND + c4;
        float4 h = *reinterpret_cast<const float4*>(hp);
        float4 z = __ldg(reinterpret_cast<const float4*>(g_zscr + (size_t)(nb0 + row) * ND + c4));
        float4 r;
        r.x = h.x + z.x * (tanhf(o.x + __ldg(&bc[c4])) - h.x);
        r.y = h.y + z.y * (tanhf(o.y + __ldg(&bc[c4 + 1])) - h.y);
        r.z = h.z + z.z * (tanhf(o.z + __ldg(&bc[c4 + 2])) - h.z);
        r.w = h.w + z.w * (tanhf(o.w + __ldg(&bc[c4 + 3])) - h.w);
        *reinterpret_cast<float4*>(hp) = r;
    }
}

// ---------------- decoder ----------------
#define DEC_SMEM (128 * 72 * 2 + 64 * 72 * 2 + 128 * 72 * 4)
__global__ void __launch_bounds__(128)
k_decoder(const float* __restrict__ W1, const float* __restrict__ b1,
          const float* __restrict__ W2, const float* __restrict__ b2) {
    extern __shared__ __align__(16) char smraw[];
    __half* Xs = (__half*)smraw;
    __half* Wb = (__half*)(smraw + 128 * 72 * 2);
    float* O = (float*)(smraw + 128 * 72 * 2 + 64 * 72 * 2);
    int tid = threadIdx.x;
    int nb0 = blockIdx.x * 128;
    stage_x16(g_h + (size_t)nb0 * ND, Xs, 72, 0);
    stage_w16<64, 64>(W1, Wb);
    __syncthreads();
    wgemm<4, 72>(Xs, Wb, O);
    __syncthreads();
    {
        float w = __ldg(&b2[0]);
        const float* orow = O + tid * 72;
#pragma unroll 8
        for (int j = 0; j < 64; j++)
            w += tanhf(orow[j] + __ldg(&b1[j])) * __ldg(&W2[j]);
        g_nodew[nb0 + tid] = w;
    }
}

// ---------------- edge softmax + sumsq + flow0 scatter ----------------
__global__ void k_normw(const int* __restrict__ adj, const float* __restrict__ demands,
                        float* __restrict__ out_normw) {
    int n = blockIdx.x * blockDim.x + threadIdx.x;
    int base = (n >> 14) << 14;
    int idxv[NK];
    float sc[NK];
    float mx = NEGV;
#pragma unroll
    for (int k = 0; k < NK; k++) {
        int idx = __ldg(&adj[(size_t)n * NK + k]);
        idxv[k] = idx;
        float s = (idx < NV) ? __ldg(&g_nodew[(size_t)base + idx]) : NEGV;
        sc[k] = s;
        mx = fmaxf(mx, s);
    }
    float sum = 0.0f;
#pragma unroll
    for (int k = 0; k < NK; k++) { sc[k] = expf(sc[k] - mx); sum += sc[k]; }
    float inv = 1.0f / sum;
    float nf0 = fmaxf(-__ldg(&demands[n]), 0.0f);
    float sn = 0.0f;
#pragma unroll
    for (int k = 0; k < NK; k++) {
        float nw = sc[k] * inv;
        sc[k] = nw;
        sn += nw * nw;
        out_normw[(size_t)n * NK + k] = nw;
    }
    g_sn[n] = sn;
#pragma unroll
    for (int k = 0; k < NK; k++)
        if (idxv[k] < NV) atomicAdd(&g_inflowA[base + idxv[k]], sc[k] * nf0);
}

// ---------------- fused flow iteration ----------------
__global__ void k_flow_iter(const int* __restrict__ adj, const float* __restrict__ demands,
                            const float* __restrict__ normw, float* __restrict__ cur,
                            float* __restrict__ nxt, float* __restrict__ store) {
    int n = blockIdx.x * blockDim.x + threadIdx.x;
    int base = (n >> 14) << 14;
    float nf = fmaxf(cur[n] - __ldg(&demands[n]), 0.0f);
    cur[n] = 0.0f;
#pragma unroll
    for (int k = 0; k < NK; k++) {
        int idx = __ldg(&adj[(size_t)n * NK + k]);
        float f = __ldg(&normw[(size_t)n * NK + k]) * nf;
        if (store) store[(size_t)n * NK + k] = f;
        if (idx < NV) atomicAdd(&nxt[base + idx], f);
    }
}

// ---------------- final flow + cost ----------------
__global__ void k_flow_last(const float* __restrict__ demands, const float* __restrict__ normw,
                            float* __restrict__ cur, float* __restrict__ out_flow,
                            float* __restrict__ cost) {
    int n = blockIdx.x * blockDim.x + threadIdx.x;
    int b = n >> 14;
    float nf = fmaxf(cur[n] - __ldg(&demands[n]), 0.0f);
    cur[n] = 0.0f;
    const float4* nw4 = reinterpret_cast<const float4*>(normw + (size_t)n * NK);
    float4* o4 = reinterpret_cast<float4*>(out_flow + (size_t)n * NK);
#pragma unroll
    for (int k = 0; k < 4; k++) {
        float4 v = __ldg(nw4 + k);
        v.x *= nf; v.y *= nf; v.z *= nf; v.w *= nf;
        o4[k] = v;
    }
    float val = nf * nf * __ldg(&g_sn[n]);
#pragma unroll
    for (int o = 16; o > 0; o >>= 1) val += __shfl_xor_sync(0xffffffffu, val, o);
    __shared__ float ws[8];
    if ((threadIdx.x & 31) == 0) ws[threadIdx.x >> 5] = val;
    __syncthreads();
    if (threadIdx.x == 0) {
        float t = 0.0f;
#pragma unroll
        for (int i = 0; i < 8; i++) t += ws[i];
        atomicAdd(&cost[b], t);
    }
}

// ---------------- launch ----------------
extern "C" void kernel_launch(void* const* d_in, const int* in_sizes, int n_in,
                              void* d_out, int out_size) {
    const float* emb     = (const float*)d_in[0];
    const float* feat    = (const float*)d_in[1];
    const float* demands = (const float*)d_in[2];
    const int*   adj     = (const int*)d_in[3];
    int wb = (in_sizes[5] == 1) ? 6 : 5;
    const float* W_enc1 = (const float*)d_in[wb + 0];
    const float* b_enc1 = (const float*)d_in[wb + 1];
    const float* W_enc2 = (const float*)d_in[wb + 2];
    const float* b_enc2 = (const float*)d_in[wb + 3];
    const float* W_gat  = (const float*)d_in[wb + 4];
    const float* a_src  = (const float*)d_in[wb + 5];
    const float* a_dst  = (const float*)d_in[wb + 6];
    const float* W_z    = (const float*)d_in[wb + 7];
    const float* U_z    = (const float*)d_in[wb + 8];
    const float* b_z    = (const float*)d_in[wb + 9];
    const float* W_r    = (const float*)d_in[wb + 10];
    const float* U_r    = (const float*)d_in[wb + 11];
    const float* b_r    = (const float*)d_in[wb + 12];
    const float* W_c    = (const float*)d_in[wb + 13];
    const float* U_c    = (const float*)d_in[wb + 14];
    const float* b_c    = (const float*)d_in[wb + 15];
    const float* W_dec1 = (const float*)d_in[wb + 16];
    const float* b_dec1 = (const float*)d_in[wb + 17];
    const float* W_dec2 = (const float*)d_in[wb + 18];
    const float* b_dec2 = (const float*)d_in[wb + 19];

    float* out = (float*)d_out;
    float* out_flow  = out;                               // [B,V,K] f10
    float* out_cost  = out + (size_t)NB * NV * NK;        // [B]
    float* out_normw = out_cost + NB;                     // [B,V,K]
    float* out_pflow = out_normw + (size_t)NB * NV * NK;  // [B,V,K] f9

    float *pA, *pB;
    cudaGetSymbolAddress((void**)&pA, g_inflowA);
    cudaGetSymbolAddress((void**)&pB, g_inflowB);

    cudaFuncSetAttribute(k_encoder, cudaFuncAttributeMaxDynamicSharedMemorySize, ENC_SMEM);
    cudaFuncSetAttribute(k_gat_t, cudaFuncAttributeMaxDynamicSharedMemorySize, GAT_SMEM);
    cudaFuncSetAttribute(k_gru, cudaFuncAttributeMaxDynamicSharedMemorySize, GRU_SMEM);
    cudaFuncSetAttribute(k_decoder, cudaFuncAttributeMaxDynamicSharedMemorySize, DEC_SMEM);

    k_encoder<<<512, 128, ENC_SMEM>>>(emb, feat, W_enc1, b_enc1, W_enc2, b_enc2);
    for (int l = 0; l < NL; l++) {
        k_gat_t<<<512, 128, GAT_SMEM>>>(W_gat, a_src, a_dst);
        k_gat_attn<<<NODES / 4, 512>>>(adj);
        k_gru<<<512, 128, GRU_SMEM>>>(W_z, U_z, b_z, W_r, U_r, b_r, W_c, U_c, b_c);
    }
    k_decoder<<<512, 128, DEC_SMEM>>>(W_dec1, b_dec1, W_dec2, b_dec2);
    k_normw<<<256, 256>>>(adj, demands, out_normw);

    float* cur = pA;
    float* nxt = pB;
    for (int it = 0; it < 9; it++) {
        k_flow_iter<<<256, 256>>>(adj, demands, out_normw, cur, nxt,
                                  (it == 8) ? out_pflow : nullptr);
        float* tmp = cur; cur = nxt; nxt = tmp;
    }
    cudaMemsetAsync(out_cost, 0, NB * sizeof(float), 0);
    k_flow_last<<<256, 256>>>(demands, out_normw, cur, out_flow, out_cost);
}

// round 11
// speedup vs baseline: 2.0136x; 1.5806x over previous
#include <cuda_runtime.h>
#include <cuda_fp16.h>
#include <mma.h>
#include <math.h>

using namespace nvcuda;

#define NB 4
#define NV 16384
#define NK 16
#define NE 32
#define ND 64
#define NH 4
#define NL 2
#define NEGV (-1e9f)
#define NODES (NB * NV)

// ---------------- scratch ----------------
__device__ float g_h[NODES * ND];
__device__ __half g_t[(size_t)NODES * NH * ND];
__device__ float g_zscr[NODES * ND];
__device__ float g_ssrc[NODES * NH];
__device__ float g_sdst[NODES * NH];
__device__ float g_m[NODES * ND];
__device__ float g_nodew[NODES];
__device__ float g_sn[NODES];
__device__ float g_inflowA[NODES];
__device__ float g_inflowB[NODES];
__device__ unsigned g_barc;

__device__ __forceinline__ float sigmoidf_(float x) { return 1.0f / (1.0f + expf(-x)); }

// ---------------- staging helpers (256 threads) ----------------
// 128 rows x 64 fp32 -> fp16 smem [128][ld] at column offset coff
__device__ __forceinline__ void stage_x16(const float* __restrict__ g, __half* xs, int ld, int coff) {
    for (int i = threadIdx.x; i < 128 * 16; i += 256) {
        int r = i >> 4, c4 = (i & 15) * 4;
        float4 v = __ldg(reinterpret_cast<const float4*>(g + (size_t)r * ND + c4));
        __half2* d = reinterpret_cast<__half2*>(xs + (size_t)r * ld + coff + c4);
        d[0] = __floats2half2_rn(v.x, v.y);
        d[1] = __floats2half2_rn(v.z, v.w);
    }
}
// W [KR][64] fp32 -> fp16 smem [K][72] (zero-pad rows >= KR)
template <int K, int KR>
__device__ __forceinline__ void stage_w16(const float* __restrict__ g, __half* ws) {
    for (int i = threadIdx.x; i < K * 32; i += 256) {
        int r = i >> 5, c2 = i & 31;
        float2 v = make_float2(0.f, 0.f);
        if (r < KR) v = __ldg(reinterpret_cast<const float2*>(g + r * 64 + 2 * c2));
        *reinterpret_cast<__half2*>(ws + r * 72 + 2 * c2) = __floats2half2_rn(v.x, v.y);
    }
}
// stacked [A;B] (each 64x64 fp32) -> fp16 smem [128][72]
__device__ __forceinline__ void stage_wcat(const float* __restrict__ A, const float* __restrict__ B,
                                           __half* ws) {
    for (int i = threadIdx.x; i < 128 * 32; i += 256) {
        int r = i >> 5, c2 = i & 31;
        const float* src = (r < 64) ? (A + r * 64 + 2 * c2) : (B + (r - 64) * 64 + 2 * c2);
        float2 v = __ldg(reinterpret_cast<const float2*>(src));
        *reinterpret_cast<__half2*>(ws + r * 72 + 2 * c2) = __floats2half2_rn(v.x, v.y);
    }
}

// ---------------- WMMA GEMM (8 warps): [128 x 16KT] @ [16KT x 64] -> O fp32 [128][72] ----------------
template <int KT, int ALD>
__device__ __forceinline__ void wgemm(const __half* Xs, const __half* Ws, float* Os) {
    int m0 = (threadIdx.x >> 5) * 16;  // warp -> one 16-row m-tile
    wmma::fragment<wmma::accumulator, 16, 16, 16, float> c[4];
#pragma unroll
    for (int n = 0; n < 4; n++) wmma::fill_fragment(c[n], 0.0f);
#pragma unroll
    for (int kt = 0; kt < KT; kt++) {
        wmma::fragment<wmma::matrix_a, 16, 16, 16, __half, wmma::row_major> a;
        wmma::load_matrix_sync(a, Xs + m0 * ALD + kt * 16, ALD);
#pragma unroll
        for (int n = 0; n < 4; n++) {
            wmma::fragment<wmma::matrix_b, 16, 16, 16, __half, wmma::row_major> b;
            wmma::load_matrix_sync(b, Ws + kt * 16 * 72 + n * 16, 72);
            wmma::mma_sync(c[n], a, b, c[n]);
        }
    }
#pragma unroll
    for (int n = 0; n < 4; n++)
        wmma::store_matrix_sync(Os + m0 * 72 + n * 16, c[n], 72, wmma::mem_row_major);
}

// ---------------- encoder ----------------
#define ENC_SMEM (128 * 56 * 2 + 128 * 72 * 2 + 64 * 72 * 2 + 128 * 72 * 4)
__global__ void __launch_bounds__(256)
k_encoder(const float* __restrict__ emb, const float* __restrict__ feat,
          const float* __restrict__ W1, const float* __restrict__ b1,
          const float* __restrict__ W2, const float* __restrict__ b2) {
    extern __shared__ __align__(16) char smraw[];
    __half* X1 = (__half*)smraw;                                   // [128][56], K=48 used
    __half* X2 = (__half*)(smraw + 128 * 56 * 2);                  // [128][72]
    __half* Wb = (__half*)(smraw + 128 * 56 * 2 + 128 * 72 * 2);   // [64][72]
    float* O = (float*)(smraw + 128 * 56 * 2 + 128 * 72 * 2 + 64 * 72 * 2);
    int tid = threadIdx.x;
    int nb0 = blockIdx.x * 128;

    {  // stage [emb|feat|0pad]: 2 threads per row
        int r = tid >> 1, part = tid & 1;
        const float4* e4 = reinterpret_cast<const float4*>(emb + (size_t)(nb0 + r) * NE);
        __half2* row = reinterpret_cast<__half2*>(X1 + (size_t)r * 56);
#pragma unroll
        for (int c = part * 4; c < part * 4 + 4; c++) {
            float4 v = __ldg(e4 + c);
            row[2 * c] = __floats2half2_rn(v.x, v.y);
            row[2 * c + 1] = __floats2half2_rn(v.z, v.w);
        }
        if (part) {
            float2 fv = __ldg(reinterpret_cast<const float2*>(feat + (size_t)(nb0 + r) * 2));
            row[16] = __floats2half2_rn(fv.x, fv.y);
#pragma unroll
            for (int c2 = 17; c2 < 28; c2++) row[c2] = __floats2half2_rn(0.f, 0.f);
        }
    }
    stage_w16<48, 34>(W1, Wb);
    if (tid < 128) {
        g_inflowA[nb0 + tid] = 0.0f;
        g_inflowB[nb0 + tid] = 0.0f;
    }
    __syncthreads();
    wgemm<3, 56>(X1, Wb, O);
    __syncthreads();
    for (int i = tid; i < 128 * 32; i += 256) {
        int row = i >> 5, c2 = i & 31;
        float o0 = O[row * 72 + 2 * c2] + __ldg(&b1[2 * c2]);
        float o1 = O[row * 72 + 2 * c2 + 1] + __ldg(&b1[2 * c2 + 1]);
        *reinterpret_cast<__half2*>(X2 + row * 72 + 2 * c2) =
            __floats2half2_rn(tanhf(o0), tanhf(o1));
    }
    stage_w16<64, 64>(W2, Wb);
    __syncthreads();
    wgemm<4, 72>(X2, Wb, O);
    __syncthreads();
    for (int i = tid; i < 128 * 16; i += 256) {
        int row = i >> 4, c4 = (i & 15) * 4;
        float4 o = *reinterpret_cast<const float4*>(O + row * 72 + c4);
        float4 r;
        r.x = tanhf(o.x + __ldg(&b2[c4]));
        r.y = tanhf(o.y + __ldg(&b2[c4 + 1]));
        r.z = tanhf(o.z + __ldg(&b2[c4 + 2]));
        r.w = tanhf(o.w + __ldg(&b2[c4 + 3]));
        *reinterpret_cast<float4*>(g_h + (size_t)(nb0 + row) * ND + c4) = r;
    }
}

// ---------------- GAT transform (all 4 heads' W preloaded) ----------------
#define GAT_SMEM (128 * 72 * 2 + 4 * 64 * 72 * 2 + 128 * 72 * 4)
__global__ void __launch_bounds__(256)
k_gat_t(const float* __restrict__ Wgat, const float* __restrict__ asrc,
        const float* __restrict__ adst) {
    extern __shared__ __align__(16) char smraw[];
    __half* Xs = (__half*)smraw;                       // [128][72]
    __half* Wb4 = (__half*)(smraw + 128 * 72 * 2);     // 4 x [64][72]
    float* O = (float*)(smraw + 128 * 72 * 2 + 4 * 64 * 72 * 2);
    int tid = threadIdx.x;
    int nb0 = blockIdx.x * 128;
    stage_x16(g_h + (size_t)nb0 * ND, Xs, 72, 0);
    // stage all 4 heads' weights
    for (int i = tid; i < 4 * 64 * 32; i += 256) {
        int hd = i >> 11, rem = i & 2047;
        int r = rem >> 5, c2 = rem & 31;
        float2 v = __ldg(reinterpret_cast<const float2*>(Wgat + (size_t)hd * ND * ND + r * 64 + 2 * c2));
        *reinterpret_cast<__half2*>(Wb4 + (size_t)hd * 64 * 72 + r * 72 + 2 * c2) =
            __floats2half2_rn(v.x, v.y);
    }
    __syncthreads();

    for (int hd = 0; hd < NH; hd++) {
        wgemm<4, 72>(Xs, Wb4 + (size_t)hd * 64 * 72, O);
        __syncthreads();
        // t fp16 store (coalesced)
        for (int i = tid; i < 128 * 32; i += 256) {
            int row = i >> 5, c2 = i & 31;
            float o0 = O[row * 72 + 2 * c2], o1 = O[row * 72 + 2 * c2 + 1];
            *reinterpret_cast<__half2*>(g_t + ((size_t)(nb0 + row) * NH + hd) * ND + 2 * c2) =
                __floats2half2_rn(o0, o1);
        }
        // score dots: 2 threads per row
        {
            int r = tid >> 1, hf = (tid & 1) * 32;
            float ss = 0.f, sd = 0.f;
            const float* orow = O + r * 72 + hf;
#pragma unroll 8
            for (int j = 0; j < 32; j++) {
                float o = orow[j];
                ss += o * __ldg(&asrc[hd * ND + hf + j]);
                sd += o * __ldg(&adst[hd * ND + hf + j]);
            }
            ss += __shfl_xor_sync(0xffffffffu, ss, 1);
            sd += __shfl_xor_sync(0xffffffffu, sd, 1);
            if ((tid & 1) == 0) {
                g_ssrc[(size_t)(nb0 + r) * NH + hd] = ss;
                g_sdst[(size_t)(nb0 + r) * NH + hd] = sd;
            }
        }
        __syncthreads();  // O-reads done before next head's wgemm overwrites
    }
}

// ---------------- GAT attention + aggregation (fp16 gather) ----------------
__global__ void k_gat_attn(const int* __restrict__ adj) {
    __shared__ float s_agg[4][NH][ND];
    int wid = threadIdx.x >> 5, lane = threadIdx.x & 31;
    int ni = wid >> 2, hd = wid & 3;
    int n = (blockIdx.x << 2) + ni;
    int b = n >> 14;

    float score = NEGV;
    int idx = NV;
    if (lane < NK) {
        idx = __ldg(&adj[(size_t)n * NK + lane]);
        if (idx < NV)
            score = __ldg(&g_ssrc[(size_t)n * NH + hd]) +
                    __ldg(&g_sdst[((size_t)(b << 14) + idx) * NH + hd]);
    }
    float mx = score;
#pragma unroll
    for (int o = 16; o > 0; o >>= 1) mx = fmaxf(mx, __shfl_xor_sync(0xffffffffu, mx, o));
    float e = (lane < NK) ? expf(score - mx) : 0.0f;
    float s = e;
#pragma unroll
    for (int o = 16; o > 0; o >>= 1) s += __shfl_xor_sync(0xffffffffu, s, o);
    float attn = e / s;

    float ax = 0.0f, ay = 0.0f;
#pragma unroll
    for (int k = 0; k < NK; k++) {
        int j = __shfl_sync(0xffffffffu, idx, k);
        float a = __shfl_sync(0xffffffffu, attn, k);
        if (j < NV) {
            const __half2* tp =
                reinterpret_cast<const __half2*>(g_t + (((size_t)(b << 14) + j) * NH + hd) * ND);
            float2 tv = __half22float2(__ldg(tp + lane));
            ax += a * tv.x; ay += a * tv.y;
        }
    }
    s_agg[ni][hd][2 * lane] = ax;
    s_agg[ni][hd][2 * lane + 1] = ay;
    __syncthreads();
    if (threadIdx.x < 256) {
        int nn = threadIdx.x >> 6, j = threadIdx.x & 63;
        float t = s_agg[nn][0][j] + s_agg[nn][1][j] + s_agg[nn][2][j] + s_agg[nn][3][j];
        g_m[((size_t)(blockIdx.x << 2) + nn) * ND + j] = tanhf(t * 0.25f);
    }
}

// ---------------- fused GRU: 3 concat GEMMs (K=128) ----------------
#define GRU_SMEM (128 * 136 * 2 + 128 * 72 * 2 + 128 * 72 * 4)
__global__ void __launch_bounds__(256)
k_gru(const float* __restrict__ Wz, const float* __restrict__ Uz, const float* __restrict__ bz,
      const float* __restrict__ Wr, const float* __restrict__ Ur, const float* __restrict__ br,
      const float* __restrict__ Wc, const float* __restrict__ Uc, const float* __restrict__ bc) {
    extern __shared__ __align__(16) char smraw[];
    __half* Xc = (__half*)smraw;                       // [128][136]: [m | h] -> [m | r*h]
    __half* Wb = (__half*)(smraw + 128 * 136 * 2);     // [128][72]
    float* O = (float*)(smraw + 128 * 136 * 2 + 128 * 72 * 2);
    int tid = threadIdx.x;
    int nb0 = blockIdx.x * 128;

    stage_x16(g_m + (size_t)nb0 * ND, Xc, 136, 0);
    stage_x16(g_h + (size_t)nb0 * ND, Xc, 136, 64);
    // ---- z ----
    stage_wcat(Wz, Uz, Wb);
    __syncthreads();
    wgemm<8, 136>(Xc, Wb, O);
    __syncthreads();
    for (int i = tid; i < 128 * 16; i += 256) {
        int row = i >> 4, c4 = (i & 15) * 4;
        float4 o = *reinterpret_cast<const float4*>(O + row * 72 + c4);
        float4 r;
        r.x = sigmoidf_(o.x + __ldg(&bz[c4]));
        r.y = sigmoidf_(o.y + __ldg(&bz[c4 + 1]));
        r.z = sigmoidf_(o.z + __ldg(&bz[c4 + 2]));
        r.w = sigmoidf_(o.w + __ldg(&bz[c4 + 3]));
        *reinterpret_cast<float4*>(g_zscr + (size_t)(nb0 + row) * ND + c4) = r;
    }
    __syncthreads();
    // ---- r, r*h -> Xc right half ----
    stage_wcat(Wr, Ur, Wb);
    __syncthreads();
    wgemm<8, 136>(Xc, Wb, O);
    __syncthreads();
    for (int i = tid; i < 128 * 32; i += 256) {
        int row = i >> 5, c2 = i & 31;
        float o0 = O[row * 72 + 2 * c2] + __ldg(&br[2 * c2]);
        float o1 = O[row * 72 + 2 * c2 + 1] + __ldg(&br[2 * c2 + 1]);
        __half2* hp = reinterpret_cast<__half2*>(Xc + row * 136 + 64 + 2 * c2);
        float2 hf = __half22float2(*hp);
        *hp = __floats2half2_rn(sigmoidf_(o0) * hf.x, sigmoidf_(o1) * hf.y);
    }
    __syncthreads();
    // ---- c + combine ----
    stage_wcat(Wc, Uc, Wb);
    __syncthreads();
    wgemm<8, 136>(Xc, Wb, O);
    __syncthreads();
    for (int i = tid; i < 128 * 16; i += 256) {
        int row = i >> 4, c4 = (i & 15) * 4;
        float4 o = *reinterpret_cast<const float4*>(O + row * 72 + c4);
        float* hp = g_h + (size_t)(nb0 + row) * ND + c4;
        float4 h = *reinterpret_cast<const float4*>(hp);
        float4 z = __ldg(reinterpret_cast<const float4*>(g_zscr + (size_t)(nb0 + row) * ND + c4));
        float4 r;
        r.x = h.x + z.x * (tanhf(o.x + __ldg(&bc[c4])) - h.x);
        r.y = h.y + z.y * (tanhf(o.y + __ldg(&bc[c4 + 1])) - h.y);
        r.z = h.z + z.z * (tanhf(o.z + __ldg(&bc[c4 + 2])) - h.z);
        r.w = h.w + z.w * (tanhf(o.w + __ldg(&bc[c4 + 3])) - h.w);
        *reinterpret_cast<float4*>(hp) = r;
    }
}

// ---------------- decoder ----------------
#define DEC_SMEM (128 * 72 * 2 + 64 * 72 * 2 + 128 * 72 * 4)
__global__ void __launch_bounds__(256)
k_decoder(const float* __restrict__ W1, const float* __restrict__ b1,
          const float* __restrict__ W2, const float* __restrict__ b2) {
    extern __shared__ __align__(16) char smraw[];
    __half* Xs = (__half*)smraw;
    __half* Wb = (__half*)(smraw + 128 * 72 * 2);
    float* O = (float*)(smraw + 128 * 72 * 2 + 64 * 72 * 2);
    int tid = threadIdx.x;
    int nb0 = blockIdx.x * 128;
    stage_x16(g_h + (size_t)nb0 * ND, Xs, 72, 0);
    stage_w16<64, 64>(W1, Wb);
    __syncthreads();
    wgemm<4, 72>(Xs, Wb, O);
    __syncthreads();
    {
        int r = tid >> 1, hf = (tid & 1) * 32;
        float w = 0.f;
        const float* orow = O + r * 72 + hf;
#pragma unroll 8
        for (int j = 0; j < 32; j++)
            w += tanhf(orow[j] + __ldg(&b1[hf + j])) * __ldg(&W2[hf + j]);
        w += __shfl_xor_sync(0xffffffffu, w, 1);
        if ((tid & 1) == 0) g_nodew[nb0 + r] = w + __ldg(&b2[0]);
    }
}

// ---------------- edge softmax + sumsq + flow0 scatter ----------------
__global__ void k_normw(const int* __restrict__ adj, const float* __restrict__ demands,
                        float* __restrict__ out_normw) {
    int n = blockIdx.x * blockDim.x + threadIdx.x;
    int base = (n >> 14) << 14;
    int idxv[NK];
    float sc[NK];
    float mx = NEGV;
#pragma unroll
    for (int k = 0; k < NK; k++) {
        int idx = __ldg(&adj[(size_t)n * NK + k]);
        idxv[k] = idx;
        float s = (idx < NV) ? __ldg(&g_nodew[(size_t)base + idx]) : NEGV;
        sc[k] = s;
        mx = fmaxf(mx, s);
    }
    float sum = 0.0f;
#pragma unroll
    for (int k = 0; k < NK; k++) { sc[k] = expf(sc[k] - mx); sum += sc[k]; }
    float inv = 1.0f / sum;
    float nf0 = fmaxf(-__ldg(&demands[n]), 0.0f);
    float sn = 0.0f;
#pragma unroll
    for (int k = 0; k < NK; k++) {
        float nw = sc[k] * inv;
        sc[k] = nw;
        sn += nw * nw;
        out_normw[(size_t)n * NK + k] = nw;
    }
    g_sn[n] = sn;
#pragma unroll
    for (int k = 0; k < NK; k++)
        if (idxv[k] < NV) atomicAdd(&g_inflowA[base + idxv[k]], sc[k] * nf0);
}

// ---------------- fused 10-iteration flow solver (persistent, grid barrier) ----------------
__global__ void __launch_bounds__(256)
k_flow_all(const int* __restrict__ adj, const float* __restrict__ demands,
           const float* __restrict__ normw, float* bufA, float* bufB,
           float* __restrict__ out_flow, float* __restrict__ out_pflow,
           float* __restrict__ cost) {
    int n = blockIdx.x * 256 + threadIdx.x;
    int base = (n >> 14) << 14;
    int idxv[NK];
#pragma unroll
    for (int k = 0; k < NK; k++) idxv[k] = __ldg(&adj[(size_t)n * NK + k]);
    float nw[NK];
    const float4* nw4 = reinterpret_cast<const float4*>(normw + (size_t)n * NK);
#pragma unroll
    for (int k = 0; k < 4; k++) {
        float4 v = __ldg(nw4 + k);
        nw[4 * k] = v.x; nw[4 * k + 1] = v.y; nw[4 * k + 2] = v.z; nw[4 * k + 3] = v.w;
    }
    float dem = __ldg(&demands[n]);
    float* cur = bufA;
    float* nxt = bufB;
    for (int it = 0; it < 9; it++) {
        float nf = fmaxf(__ldcg(&cur[n]) - dem, 0.0f);
        cur[n] = 0.0f;
        if (it == 8) {
            float4* o4 = reinterpret_cast<float4*>(out_pflow + (size_t)n * NK);
#pragma unroll
            for (int k = 0; k < 4; k++)
                o4[k] = make_float4(nw[4 * k] * nf, nw[4 * k + 1] * nf,
                                    nw[4 * k + 2] * nf, nw[4 * k + 3] * nf);
        }
#pragma unroll
        for (int k = 0; k < NK; k++)
            if (idxv[k] < NV) atomicAdd(&nxt[base + idxv[k]], nw[k] * nf);
        __syncthreads();
        if (threadIdx.x == 0) {
            __threadfence();
            atomicAdd(&g_barc, 1u);
            unsigned tgt = (unsigned)(it + 1) * gridDim.x;
            while (*((volatile unsigned*)&g_barc) < tgt) {}
            __threadfence();
        }
        __syncthreads();
        float* t = cur; cur = nxt; nxt = t;
    }
    float nf = fmaxf(__ldcg(&cur[n]) - dem, 0.0f);
    {
        float4* o4 = reinterpret_cast<float4*>(out_flow + (size_t)n * NK);
#pragma unroll
        for (int k = 0; k < 4; k++)
            o4[k] = make_float4(nw[4 * k] * nf, nw[4 * k + 1] * nf,
                                nw[4 * k + 2] * nf, nw[4 * k + 3] * nf);
    }
    float val = nf * nf * __ldg(&g_sn[n]);
#pragma unroll
    for (int o = 16; o > 0; o >>= 1) val += __shfl_xor_sync(0xffffffffu, val, o);
    __shared__ float wsum[8];
    if ((threadIdx.x & 31) == 0) wsum[threadIdx.x >> 5] = val;
    __syncthreads();
    if (threadIdx.x == 0) {
        float t = 0.0f;
#pragma unroll
        for (int i = 0; i < 8; i++) t += wsum[i];
        atomicAdd(&cost[n >> 14], t);
    }
}

// ---------------- launch ----------------
extern "C" void kernel_launch(void* const* d_in, const int* in_sizes, int n_in,
                              void* d_out, int out_size) {
    const float* emb     = (const float*)d_in[0];
    const float* feat    = (const float*)d_in[1];
    const float* demands = (const float*)d_in[2];
    const int*   adj     = (const int*)d_in[3];
    int wb = (in_sizes[5] == 1) ? 6 : 5;
    const float* W_enc1 = (const float*)d_in[wb + 0];
    const float* b_enc1 = (const float*)d_in[wb + 1];
    const float* W_enc2 = (const float*)d_in[wb + 2];
    const float* b_enc2 = (const float*)d_in[wb + 3];
    const float* W_gat  = (const float*)d_in[wb + 4];
    const float* a_src  = (const float*)d_in[wb + 5];
    const float* a_dst  = (const float*)d_in[wb + 6];
    const float* W_z    = (const float*)d_in[wb + 7];
    const float* U_z    = (const float*)d_in[wb + 8];
    const float* b_z    = (const float*)d_in[wb + 9];
    const float* W_r    = (const float*)d_in[wb + 10];
    const float* U_r    = (const float*)d_in[wb + 11];
    const float* b_r    = (const float*)d_in[wb + 12];
    const float* W_c    = (const float*)d_in[wb + 13];
    const float* U_c    = (const float*)d_in[wb + 14];
    const float* b_c    = (const float*)d_in[wb + 15];
    const float* W_dec1 = (const float*)d_in[wb + 16];
    const float* b_dec1 = (const float*)d_in[wb + 17];
    const float* W_dec2 = (const float*)d_in[wb + 18];
    const float* b_dec2 = (const float*)d_in[wb + 19];

    float* out = (float*)d_out;
    float* out_flow  = out;                               // [B,V,K] f10
    float* out_cost  = out + (size_t)NB * NV * NK;        // [B]
    float* out_normw = out_cost + NB;                     // [B,V,K]
    float* out_pflow = out_normw + (size_t)NB * NV * NK;  // [B,V,K] f9

    float *pA, *pB;
    cudaGetSymbolAddress((void**)&pA, g_inflowA);
    cudaGetSymbolAddress((void**)&pB, g_inflowB);
    unsigned* pbar;
    cudaGetSymbolAddress((void**)&pbar, g_barc);

    cudaFuncSetAttribute(k_encoder, cudaFuncAttributeMaxDynamicSharedMemorySize, ENC_SMEM);
    cudaFuncSetAttribute(k_gat_t, cudaFuncAttributeMaxDynamicSharedMemorySize, GAT_SMEM);
    cudaFuncSetAttribute(k_gru, cudaFuncAttributeMaxDynamicSharedMemorySize, GRU_SMEM);
    cudaFuncSetAttribute(k_decoder, cudaFuncAttributeMaxDynamicSharedMemorySize, DEC_SMEM);

    k_encoder<<<512, 256, ENC_SMEM>>>(emb, feat, W_enc1, b_enc1, W_enc2, b_enc2);
    for (int l = 0; l < NL; l++) {
        k_gat_t<<<512, 256, GAT_SMEM>>>(W_gat, a_src, a_dst);
        k_gat_attn<<<NODES / 4, 512>>>(adj);
        k_gru<<<512, 256, GRU_SMEM>>>(W_z, U_z, b_z, W_r, U_r, b_r, W_c, U_c, b_c);
    }
    k_decoder<<<512, 256, DEC_SMEM>>>(W_dec1, b_dec1, W_dec2, b_dec2);
    k_normw<<<256, 256>>>(adj, demands, out_normw);

    cudaMemsetAsync(pbar, 0, sizeof(unsigned), 0);
    cudaMemsetAsync(out_cost, 0, NB * sizeof(float), 0);
    k_flow_all<<<256, 256>>>(adj, demands, out_normw, pA, pB, out_flow, out_pflow, out_cost);
}

// round 12
// speedup vs baseline: 2.0740x; 1.0300x over previous
#include <cuda_runtime.h>
#include <cuda_fp16.h>
#include <mma.h>
#include <math.h>

using namespace nvcuda;

#define NB 4
#define NV 16384
#define NK 16
#define NE 32
#define ND 64
#define NH 4
#define NL 2
#define NEGV (-1e9f)
#define NODES (NB * NV)

// ---------------- scratch ----------------
__device__ float g_h[NODES * ND];
__device__ __half g_t[(size_t)NODES * NH * ND];
__device__ float g_ssrc[NODES * NH];
__device__ float g_sdst[NODES * NH];
__device__ float g_m[NODES * ND];
__device__ float g_nodew[NODES];
__device__ float g_sn[NODES];
__device__ float g_inflowA[NODES];
__device__ float g_inflowB[NODES];
__device__ unsigned g_barc;

// ---------------- fast math (HW approx; immune to fast-math flags) ----------------
__device__ __forceinline__ float ftanh(float x) {
    float r; asm("tanh.approx.f32 %0, %1;" : "=f"(r) : "f"(x)); return r;
}
__device__ __forceinline__ float fexp(float x) {
    float r; asm("ex2.approx.f32 %0, %1;" : "=f"(r) : "f"(x * 1.4426950408889634f)); return r;
}
__device__ __forceinline__ float fsig(float x) {
    float e; asm("ex2.approx.f32 %0, %1;" : "=f"(e) : "f"(-x * 1.4426950408889634f));
    float r; asm("rcp.approx.f32 %0, %1;" : "=f"(r) : "f"(1.0f + e)); return r;
}

// ---------------- staging helpers (256 threads) ----------------
__device__ __forceinline__ void stage_x16(const float* __restrict__ g, __half* xs, int ld, int coff) {
    for (int i = threadIdx.x; i < 128 * 16; i += 256) {
        int r = i >> 4, c4 = (i & 15) * 4;
        float4 v = __ldg(reinterpret_cast<const float4*>(g + (size_t)r * ND + c4));
        __half2* d = reinterpret_cast<__half2*>(xs + (size_t)r * ld + coff + c4);
        d[0] = __floats2half2_rn(v.x, v.y);
        d[1] = __floats2half2_rn(v.z, v.w);
    }
}
template <int K, int KR>
__device__ __forceinline__ void stage_w16(const float* __restrict__ g, __half* ws) {
    for (int i = threadIdx.x; i < K * 32; i += 256) {
        int r = i >> 5, c2 = i & 31;
        float2 v = make_float2(0.f, 0.f);
        if (r < KR) v = __ldg(reinterpret_cast<const float2*>(g + r * 64 + 2 * c2));
        *reinterpret_cast<__half2*>(ws + r * 72 + 2 * c2) = __floats2half2_rn(v.x, v.y);
    }
}
// stacked [A;B] prefetch: LDG+convert into 16 half2 regs
__device__ __forceinline__ void wcat_ldg(const float* __restrict__ A, const float* __restrict__ B,
                                         __half2 wn[16]) {
#pragma unroll
    for (int p = 0; p < 16; p++) {
        int i = threadIdx.x + p * 256;
        int r = i >> 5, c2 = i & 31;
        const float* src = (r < 64) ? (A + r * 64 + 2 * c2) : (B + (r - 64) * 64 + 2 * c2);
        float2 v = __ldg(reinterpret_cast<const float2*>(src));
        wn[p] = __floats2half2_rn(v.x, v.y);
    }
}
__device__ __forceinline__ void wcat_sts(__half* ws, const __half2 wn[16]) {
#pragma unroll
    for (int p = 0; p < 16; p++) {
        int i = threadIdx.x + p * 256;
        int r = i >> 5, c2 = i & 31;
        *reinterpret_cast<__half2*>(ws + r * 72 + 2 * c2) = wn[p];
    }
}

// ---------------- WMMA GEMM (8 warps): [128 x 16KT] @ [16KT x 64] -> O fp32 [128][72] ----------------
template <int KT, int ALD>
__device__ __forceinline__ void wgemm(const __half* Xs, const __half* Ws, float* Os) {
    int m0 = (threadIdx.x >> 5) * 16;
    wmma::fragment<wmma::accumulator, 16, 16, 16, float> c[4];
#pragma unroll
    for (int n = 0; n < 4; n++) wmma::fill_fragment(c[n], 0.0f);
#pragma unroll
    for (int kt = 0; kt < KT; kt++) {
        wmma::fragment<wmma::matrix_a, 16, 16, 16, __half, wmma::row_major> a;
        wmma::load_matrix_sync(a, Xs + m0 * ALD + kt * 16, ALD);
#pragma unroll
        for (int n = 0; n < 4; n++) {
            wmma::fragment<wmma::matrix_b, 16, 16, 16, __half, wmma::row_major> b;
            wmma::load_matrix_sync(b, Ws + kt * 16 * 72 + n * 16, 72);
            wmma::mma_sync(c[n], a, b, c[n]);
        }
    }
#pragma unroll
    for (int n = 0; n < 4; n++)
        wmma::store_matrix_sync(Os + m0 * 72 + n * 16, c[n], 72, wmma::mem_row_major);
}

// ---------------- encoder ----------------
#define ENC_SMEM (128 * 56 * 2 + 128 * 72 * 2 + 64 * 72 * 2 + 128 * 72 * 4)
__global__ void __launch_bounds__(256)
k_encoder(const float* __restrict__ emb, const float* __restrict__ feat,
          const float* __restrict__ W1, const float* __restrict__ b1,
          const float* __restrict__ W2, const float* __restrict__ b2) {
    extern __shared__ __align__(16) char smraw[];
    __half* X1 = (__half*)smraw;                                   // [128][56], K=48
    __half* X2 = (__half*)(smraw + 128 * 56 * 2);                  // [128][72]
    __half* Wb = (__half*)(smraw + 128 * 56 * 2 + 128 * 72 * 2);   // [64][72]
    float* O = (float*)(smraw + 128 * 56 * 2 + 128 * 72 * 2 + 64 * 72 * 2);
    int tid = threadIdx.x;
    int nb0 = blockIdx.x * 128;

    // prefetch W2 into regs (64x64 -> 8 half2/thread)
    __half2 w2r[8];
#pragma unroll
    for (int p = 0; p < 8; p++) {
        int i = tid + p * 256;
        int r = i >> 5, c2 = i & 31;
        float2 v = __ldg(reinterpret_cast<const float2*>(W2 + r * 64 + 2 * c2));
        w2r[p] = __floats2half2_rn(v.x, v.y);
    }
    {  // stage [emb|feat|0pad]: 2 threads per row
        int r = tid >> 1, part = tid & 1;
        const float4* e4 = reinterpret_cast<const float4*>(emb + (size_t)(nb0 + r) * NE);
        __half2* row = reinterpret_cast<__half2*>(X1 + (size_t)r * 56);
#pragma unroll
        for (int c = part * 4; c < part * 4 + 4; c++) {
            float4 v = __ldg(e4 + c);
            row[2 * c] = __floats2half2_rn(v.x, v.y);
            row[2 * c + 1] = __floats2half2_rn(v.z, v.w);
        }
        if (part) {
            float2 fv = __ldg(reinterpret_cast<const float2*>(feat + (size_t)(nb0 + r) * 2));
            row[16] = __floats2half2_rn(fv.x, fv.y);
#pragma unroll
            for (int c2 = 17; c2 < 28; c2++) row[c2] = __floats2half2_rn(0.f, 0.f);
        }
    }
    stage_w16<48, 34>(W1, Wb);
    if (tid < 128) {
        g_inflowA[nb0 + tid] = 0.0f;
        g_inflowB[nb0 + tid] = 0.0f;
    }
    __syncthreads();
    wgemm<3, 56>(X1, Wb, O);
    __syncthreads();
    // STS W2 from regs + X2 epilogue
#pragma unroll
    for (int p = 0; p < 8; p++) {
        int i = tid + p * 256;
        int r = i >> 5, c2 = i & 31;
        *reinterpret_cast<__half2*>(Wb + r * 72 + 2 * c2) = w2r[p];
    }
    for (int i = tid; i < 128 * 32; i += 256) {
        int row = i >> 5, c2 = i & 31;
        float o0 = O[row * 72 + 2 * c2] + __ldg(&b1[2 * c2]);
        float o1 = O[row * 72 + 2 * c2 + 1] + __ldg(&b1[2 * c2 + 1]);
        *reinterpret_cast<__half2*>(X2 + row * 72 + 2 * c2) =
            __floats2half2_rn(ftanh(o0), ftanh(o1));
    }
    __syncthreads();
    wgemm<4, 72>(X2, Wb, O);
    __syncthreads();
    for (int i = tid; i < 128 * 16; i += 256) {
        int row = i >> 4, c4 = (i & 15) * 4;
        float4 o = *reinterpret_cast<const float4*>(O + row * 72 + c4);
        float4 r;
        r.x = ftanh(o.x + __ldg(&b2[c4]));
        r.y = ftanh(o.y + __ldg(&b2[c4 + 1]));
        r.z = ftanh(o.z + __ldg(&b2[c4 + 2]));
        r.w = ftanh(o.w + __ldg(&b2[c4 + 3]));
        *reinterpret_cast<float4*>(g_h + (size_t)(nb0 + row) * ND + c4) = r;
    }
}

// ---------------- GAT transform: scores via h·(W@a), heads via WMMA ----------------
#define GAT_SMEM (128 * 72 * 2 + 4 * 64 * 72 * 2 + 128 * 72 * 4 + 8 * 64 * 4)
__global__ void __launch_bounds__(256)
k_gat_t(const float* __restrict__ Wgat, const float* __restrict__ asrc,
        const float* __restrict__ adst) {
    extern __shared__ __align__(16) char smraw[];
    __half* Xs = (__half*)smraw;                       // [128][72]
    __half* Wb4 = (__half*)(smraw + 128 * 72 * 2);     // 4 x [64][72]
    float* O = (float*)(smraw + 128 * 72 * 2 + 4 * 64 * 72 * 2);
    float* WA = O + 128 * 72;                          // [4][2][64]
    int tid = threadIdx.x;
    int nb0 = blockIdx.x * 128;
    stage_x16(g_h + (size_t)nb0 * ND, Xs, 72, 0);
    // stage all 4 heads' weights
    for (int i = tid; i < 4 * 64 * 32; i += 256) {
        int hd = i >> 11, rem = i & 2047;
        int r = rem >> 5, c2 = rem & 31;
        float2 v = __ldg(reinterpret_cast<const float2*>(Wgat + (size_t)hd * ND * ND + r * 64 + 2 * c2));
        *reinterpret_cast<__half2*>(Wb4 + (size_t)hd * 64 * 72 + r * 72 + 2 * c2) =
            __floats2half2_rn(v.x, v.y);
    }
    // WA[hd][0][k] = sum_c W[hd][k][c]*asrc[hd][c]; WA[hd][1][k] likewise with adst
    {
        int hd = tid >> 6, k = tid & 63;
        const float* Wrow = Wgat + (size_t)hd * ND * ND + k * ND;
        float ss = 0.f, sd = 0.f;
#pragma unroll 8
        for (int c = 0; c < 64; c++) {
            float w = __ldg(&Wrow[c]);
            ss += w * __ldg(&asrc[hd * ND + c]);
            sd += w * __ldg(&adst[hd * ND + c]);
        }
        WA[(hd * 2 + 0) * 64 + k] = ss;
        WA[(hd * 2 + 1) * 64 + k] = sd;
    }
    __syncthreads();
    // score dots for all heads from staged Xs (2 threads per node)
    {
        int r = tid >> 1, hf = (tid & 1) * 32;
        float ssv[4] = {0.f, 0.f, 0.f, 0.f}, sdv[4] = {0.f, 0.f, 0.f, 0.f};
#pragma unroll 4
        for (int k = 0; k < 32; k++) {
            float x = __half2float(Xs[r * 72 + hf + k]);
#pragma unroll
            for (int hd = 0; hd < 4; hd++) {
                ssv[hd] += x * WA[(hd * 2 + 0) * 64 + hf + k];
                sdv[hd] += x * WA[(hd * 2 + 1) * 64 + hf + k];
            }
        }
#pragma unroll
        for (int hd = 0; hd < 4; hd++) {
            ssv[hd] += __shfl_xor_sync(0xffffffffu, ssv[hd], 1);
            sdv[hd] += __shfl_xor_sync(0xffffffffu, sdv[hd], 1);
        }
        if ((tid & 1) == 0) {
#pragma unroll
            for (int hd = 0; hd < 4; hd++) {
                g_ssrc[(size_t)(nb0 + r) * NH + hd] = ssv[hd];
                g_sdst[(size_t)(nb0 + r) * NH + hd] = sdv[hd];
            }
        }
    }
    // per-head GEMM + t-store
    for (int hd = 0; hd < NH; hd++) {
        wgemm<4, 72>(Xs, Wb4 + (size_t)hd * 64 * 72, O);
        __syncthreads();
        for (int i = tid; i < 128 * 32; i += 256) {
            int row = i >> 5, c2 = i & 31;
            float o0 = O[row * 72 + 2 * c2], o1 = O[row * 72 + 2 * c2 + 1];
            *reinterpret_cast<__half2*>(g_t + ((size_t)(nb0 + row) * NH + hd) * ND + 2 * c2) =
                __floats2half2_rn(o0, o1);
        }
        __syncthreads();
    }
}

// ---------------- GAT attention + aggregation (fp16 gather) ----------------
__global__ void k_gat_attn(const int* __restrict__ adj) {
    __shared__ float s_agg[4][NH][ND];
    int wid = threadIdx.x >> 5, lane = threadIdx.x & 31;
    int ni = wid >> 2, hd = wid & 3;
    int n = (blockIdx.x << 2) + ni;
    int b = n >> 14;

    float score = NEGV;
    int idx = NV;
    if (lane < NK) {
        idx = __ldg(&adj[(size_t)n * NK + lane]);
        if (idx < NV)
            score = __ldg(&g_ssrc[(size_t)n * NH + hd]) +
                    __ldg(&g_sdst[((size_t)(b << 14) + idx) * NH + hd]);
    }
    float mx = score;
#pragma unroll
    for (int o = 16; o > 0; o >>= 1) mx = fmaxf(mx, __shfl_xor_sync(0xffffffffu, mx, o));
    float e = (lane < NK) ? fexp(score - mx) : 0.0f;
    float s = e;
#pragma unroll
    for (int o = 16; o > 0; o >>= 1) s += __shfl_xor_sync(0xffffffffu, s, o);
    float attn = e / s;

    float ax = 0.0f, ay = 0.0f;
#pragma unroll
    for (int k = 0; k < NK; k++) {
        int j = __shfl_sync(0xffffffffu, idx, k);
        float a = __shfl_sync(0xffffffffu, attn, k);
        if (j < NV) {
            const __half2* tp =
                reinterpret_cast<const __half2*>(g_t + (((size_t)(b << 14) + j) * NH + hd) * ND);
            float2 tv = __half22float2(__ldg(tp + lane));
            ax += a * tv.x; ay += a * tv.y;
        }
    }
    s_agg[ni][hd][2 * lane] = ax;
    s_agg[ni][hd][2 * lane + 1] = ay;
    __syncthreads();
    if (threadIdx.x < 256) {
        int nn = threadIdx.x >> 6, j = threadIdx.x & 63;
        float t = s_agg[nn][0][j] + s_agg[nn][1][j] + s_agg[nn][2][j] + s_agg[nn][3][j];
        g_m[((size_t)(blockIdx.x << 2) + nn) * ND + j] = ftanh(t * 0.25f);
    }
}

// ---------------- fused GRU: 3 concat GEMMs, W prefetch, z in regs ----------------
#define GRU_SMEM (128 * 136 * 2 + 128 * 72 * 2 + 128 * 72 * 4)
__global__ void __launch_bounds__(256, 2)
k_gru(const float* __restrict__ Wz, const float* __restrict__ Uz, const float* __restrict__ bz,
      const float* __restrict__ Wr, const float* __restrict__ Ur, const float* __restrict__ br,
      const float* __restrict__ Wc, const float* __restrict__ Uc, const float* __restrict__ bc) {
    extern __shared__ __align__(16) char smraw[];
    __half* Xc = (__half*)smraw;                       // [128][136]: [m | h] -> [m | r*h]
    __half* Wb = (__half*)(smraw + 128 * 136 * 2);     // [128][72]
    float* O = (float*)(smraw + 128 * 136 * 2 + 128 * 72 * 2);
    int tid = threadIdx.x;
    int nb0 = blockIdx.x * 128;

    stage_x16(g_m + (size_t)nb0 * ND, Xc, 136, 0);
    stage_x16(g_h + (size_t)nb0 * ND, Xc, 136, 64);
    {  // stage Wz|Uz directly
        __half2 w0[16];
        wcat_ldg(Wz, Uz, w0);
        wcat_sts(Wb, w0);
    }
    __half2 wn[16];
    wcat_ldg(Wr, Ur, wn);  // prefetch r-phase W
    __syncthreads();
    // ---- z ----
    wgemm<8, 136>(Xc, Wb, O);
    __syncthreads();
    wcat_sts(Wb, wn);
    wcat_ldg(Wc, Uc, wn);  // prefetch c-phase W
    float zr[32];
#pragma unroll
    for (int p = 0; p < 8; p++) {
        int i = tid + p * 256;
        int row = i >> 4, c4 = (i & 15) * 4;
        float4 o = *reinterpret_cast<const float4*>(O + row * 72 + c4);
        zr[4 * p + 0] = fsig(o.x + __ldg(&bz[c4]));
        zr[4 * p + 1] = fsig(o.y + __ldg(&bz[c4 + 1]));
        zr[4 * p + 2] = fsig(o.z + __ldg(&bz[c4 + 2]));
        zr[4 * p + 3] = fsig(o.w + __ldg(&bz[c4 + 3]));
    }
    __syncthreads();
    // ---- r, r*h -> Xc right half ----
    wgemm<8, 136>(Xc, Wb, O);
    __syncthreads();
    wcat_sts(Wb, wn);
#pragma unroll
    for (int p = 0; p < 16; p++) {
        int i = tid + p * 256;
        int row = i >> 5, c2 = i & 31;
        float o0 = O[row * 72 + 2 * c2] + __ldg(&br[2 * c2]);
        float o1 = O[row * 72 + 2 * c2 + 1] + __ldg(&br[2 * c2 + 1]);
        __half2* hp = reinterpret_cast<__half2*>(Xc + row * 136 + 64 + 2 * c2);
        float2 hf = __half22float2(*hp);
        *hp = __floats2half2_rn(fsig(o0) * hf.x, fsig(o1) * hf.y);
    }
    __syncthreads();
    // ---- c + combine ----
    wgemm<8, 136>(Xc, Wb, O);
    __syncthreads();
#pragma unroll
    for (int p = 0; p < 8; p++) {
        int i = tid + p * 256;
        int row = i >> 4, c4 = (i & 15) * 4;
        float4 o = *reinterpret_cast<const float4*>(O + row * 72 + c4);
        float* hp = g_h + (size_t)(nb0 + row) * ND + c4;
        float4 h = *reinterpret_cast<const float4*>(hp);
        float4 r;
        r.x = h.x + zr[4 * p + 0] * (ftanh(o.x + __ldg(&bc[c4])) - h.x);
        r.y = h.y + zr[4 * p + 1] * (ftanh(o.y + __ldg(&bc[c4 + 1])) - h.y);
        r.z = h.z + zr[4 * p + 2] * (ftanh(o.z + __ldg(&bc[c4 + 2])) - h.z);
        r.w = h.w + zr[4 * p + 3] * (ftanh(o.w + __ldg(&bc[c4 + 3])) - h.w);
        *reinterpret_cast<float4*>(hp) = r;
    }
}

// ---------------- decoder ----------------
#define DEC_SMEM (128 * 72 * 2 + 64 * 72 * 2 + 128 * 72 * 4)
__global__ void __launch_bounds__(256)
k_decoder(const float* __restrict__ W1, const float* __restrict__ b1,
          const float* __restrict__ W2, const float* __restrict__ b2) {
    extern __shared__ __align__(16) char smraw[];
    __half* Xs = (__half*)smraw;
    __half* Wb = (__half*)(smraw + 128 * 72 * 2);
    float* O = (float*)(smraw + 128 * 72 * 2 + 64 * 72 * 2);
    int tid = threadIdx.x;
    int nb0 = blockIdx.x * 128;
    stage_x16(g_h + (size_t)nb0 * ND, Xs, 72, 0);
    stage_w16<64, 64>(W1, Wb);
    __syncthreads();
    wgemm<4, 72>(Xs, Wb, O);
    __syncthreads();
    {
        int r = tid >> 1, hf = (tid & 1) * 32;
        float w = 0.f;
        const float* orow = O + r * 72 + hf;
#pragma unroll 8
        for (int j = 0; j < 32; j++)
            w += ftanh(orow[j] + __ldg(&b1[hf + j])) * __ldg(&W2[hf + j]);
        w += __shfl_xor_sync(0xffffffffu, w, 1);
        if ((tid & 1) == 0) g_nodew[nb0 + r] = w + __ldg(&b2[0]);
    }
}

// ---------------- edge softmax + sumsq + flow0 scatter ----------------
__global__ void k_normw(const int* __restrict__ adj, const float* __restrict__ demands,
                        float* __restrict__ out_normw) {
    int n = blockIdx.x * blockDim.x + threadIdx.x;
    int base = (n >> 14) << 14;
    int idxv[NK];
    float sc[NK];
    float mx = NEGV;
#pragma unroll
    for (int k = 0; k < NK; k++) {
        int idx = __ldg(&adj[(size_t)n * NK + k]);
        idxv[k] = idx;
        float s = (idx < NV) ? __ldg(&g_nodew[(size_t)base + idx]) : NEGV;
        sc[k] = s;
        mx = fmaxf(mx, s);
    }
    float sum = 0.0f;
#pragma unroll
    for (int k = 0; k < NK; k++) { sc[k] = fexp(sc[k] - mx); sum += sc[k]; }
    float inv = 1.0f / sum;
    float nf0 = fmaxf(-__ldg(&demands[n]), 0.0f);
    float sn = 0.0f;
#pragma unroll
    for (int k = 0; k < NK; k++) {
        float nw = sc[k] * inv;
        sc[k] = nw;
        sn += nw * nw;
        out_normw[(size_t)n * NK + k] = nw;
    }
    g_sn[n] = sn;
#pragma unroll
    for (int k = 0; k < NK; k++)
        if (idxv[k] < NV) atomicAdd(&g_inflowA[base + idxv[k]], sc[k] * nf0);
}

// ---------------- fused 10-iteration flow solver (persistent, grid barrier) ----------------
__global__ void __launch_bounds__(256)
k_flow_all(const int* __restrict__ adj, const float* __restrict__ demands,
           const float* __restrict__ normw, float* bufA, float* bufB,
           float* __restrict__ out_flow, float* __restrict__ out_pflow,
           float* __restrict__ cost) {
    int n = blockIdx.x * 256 + threadIdx.x;
    int base = (n >> 14) << 14;
    int idxv[NK];
#pragma unroll
    for (int k = 0; k < NK; k++) idxv[k] = __ldg(&adj[(size_t)n * NK + k]);
    float nw[NK];
    const float4* nw4 = reinterpret_cast<const float4*>(normw + (size_t)n * NK);
#pragma unroll
    for (int k = 0; k < 4; k++) {
        float4 v = __ldg(nw4 + k);
        nw[4 * k] = v.x; nw[4 * k + 1] = v.y; nw[4 * k + 2] = v.z; nw[4 * k + 3] = v.w;
    }
    float dem = __ldg(&demands[n]);
    float* cur = bufA;
    float* nxt = bufB;
    for (int it = 0; it < 9; it++) {
        float nf = fmaxf(__ldcg(&cur[n]) - dem, 0.0f);
        cur[n] = 0.0f;
        if (it == 8) {
            float4* o4 = reinterpret_cast<float4*>(out_pflow + (size_t)n * NK);
#pragma unroll
            for (int k = 0; k < 4; k++)
                o4[k] = make_float4(nw[4 * k] * nf, nw[4 * k + 1] * nf,
                                    nw[4 * k + 2] * nf, nw[4 * k + 3] * nf);
        }
#pragma unroll
        for (int k = 0; k < NK; k++)
            if (idxv[k] < NV) atomicAdd(&nxt[base + idxv[k]], nw[k] * nf);
        __syncthreads();
        if (threadIdx.x == 0) {
            __threadfence();
            atomicAdd(&g_barc, 1u);
            unsigned tgt = (unsigned)(it + 1) * gridDim.x;
            while (*((volatile unsigned*)&g_barc) < tgt) {}
            __threadfence();
        }
        __syncthreads();
        float* t = cur; cur = nxt; nxt = t;
    }
    float nf = fmaxf(__ldcg(&cur[n]) - dem, 0.0f);
    {
        float4* o4 = reinterpret_cast<float4*>(out_flow + (size_t)n * NK);
#pragma unroll
        for (int k = 0; k < 4; k++)
            o4[k] = make_float4(nw[4 * k] * nf, nw[4 * k + 1] * nf,
                                nw[4 * k + 2] * nf, nw[4 * k + 3] * nf);
    }
    float val = nf * nf * __ldg(&g_sn[n]);
#pragma unroll
    for (int o = 16; o > 0; o >>= 1) val += __shfl_xor_sync(0xffffffffu, val, o);
    __shared__ float wsum[8];
    if ((threadIdx.x & 31) == 0) wsum[threadIdx.x >> 5] = val;
    __syncthreads();
    if (threadIdx.x == 0) {
        float t = 0.0f;
#pragma unroll
        for (int i = 0; i < 8; i++) t += wsum[i];
        atomicAdd(&cost[n >> 14], t);
    }
}

// ---------------- launch ----------------
extern "C" void kernel_launch(void* const* d_in, const int* in_sizes, int n_in,
                              void* d_out, int out_size) {
    const float* emb     = (const float*)d_in[0];
    const float* feat    = (const float*)d_in[1];
    const float* demands = (const float*)d_in[2];
    const int*   adj     = (const int*)d_in[3];
    int wb = (in_sizes[5] == 1) ? 6 : 5;
    const float* W_enc1 = (const float*)d_in[wb + 0];
    const float* b_enc1 = (const float*)d_in[wb + 1];
    const float* W_enc2 = (const float*)d_in[wb + 2];
    const float* b_enc2 = (const float*)d_in[wb + 3];
    const float* W_gat  = (const float*)d_in[wb + 4];
    const float* a_src  = (const float*)d_in[wb + 5];
    const float* a_dst  = (const float*)d_in[wb + 6];
    const float* W_z    = (const float*)d_in[wb + 7];
    const float* U_z    = (const float*)d_in[wb + 8];
    const float* b_z    = (const float*)d_in[wb + 9];
    const float* W_r    = (const float*)d_in[wb + 10];
    const float* U_r    = (const float*)d_in[wb + 11];
    const float* b_r    = (const float*)d_in[wb + 12];
    const float* W_c    = (const float*)d_in[wb + 13];
    const float* U_c    = (const float*)d_in[wb + 14];
    const float* b_c    = (const float*)d_in[wb + 15];
    const float* W_dec1 = (const float*)d_in[wb + 16];
    const float* b_dec1 = (const float*)d_in[wb + 17];
    const float* W_dec2 = (const float*)d_in[wb + 18];
    const float* b_dec2 = (const float*)d_in[wb + 19];

    float* out = (float*)d_out;
    float* out_flow  = out;                               // [B,V,K] f10
    float* out_cost  = out + (size_t)NB * NV * NK;        // [B]
    float* out_normw = out_cost + NB;                     // [B,V,K]
    float* out_pflow = out_normw + (size_t)NB * NV * NK;  // [B,V,K] f9

    float *pA, *pB;
    cudaGetSymbolAddress((void**)&pA, g_inflowA);
    cudaGetSymbolAddress((void**)&pB, g_inflowB);
    unsigned* pbar;
    cudaGetSymbolAddress((void**)&pbar, g_barc);

    cudaFuncSetAttribute(k_encoder, cudaFuncAttributeMaxDynamicSharedMemorySize, ENC_SMEM);
    cudaFuncSetAttribute(k_gat_t, cudaFuncAttributeMaxDynamicSharedMemorySize, GAT_SMEM);
    cudaFuncSetAttribute(k_gru, cudaFuncAttributeMaxDynamicSharedMemorySize, GRU_SMEM);
    cudaFuncSetAttribute(k_decoder, cudaFuncAttributeMaxDynamicSharedMemorySize, DEC_SMEM);

    k_encoder<<<512, 256, ENC_SMEM>>>(emb, feat, W_enc1, b_enc1, W_enc2, b_enc2);
    for (int l = 0; l < NL; l++) {
        k_gat_t<<<512, 256, GAT_SMEM>>>(W_gat, a_src, a_dst);
        k_gat_attn<<<NODES / 4, 512>>>(adj);
        k_gru<<<512, 256, GRU_SMEM>>>(W_z, U_z, b_z, W_r, U_r, b_r, W_c, U_c, b_c);
    }
    k_decoder<<<512, 256, DEC_SMEM>>>(W_dec1, b_dec1, W_dec2, b_dec2);
    k_normw<<<256, 256>>>(adj, demands, out_normw);

    cudaMemsetAsync(pbar, 0, sizeof(unsigned), 0);
    cudaMemsetAsync(out_cost, 0, NB * sizeof(float), 0);
    k_flow_all<<<256, 256>>>(adj, demands, out_normw, pA, pB, out_flow, out_pflow, out_cost);
}

// round 13
// speedup vs baseline: 2.5100x; 1.2102x over previous
#include <cuda_runtime.h>
#include <cuda_fp16.h>
#include <mma.h>
#include <math.h>

using namespace nvcuda;

#define NB 4
#define NV 16384
#define NK 16
#define NE 32
#define ND 64
#define NH 4
#define NL 2
#define NEGV (-1e9f)
#define NODES (NB * NV)

// ---------------- scratch ----------------
__device__ float g_h[NODES * ND];
__device__ __half g_t[(size_t)NODES * NH * ND];
__device__ float g_ssrc[NODES * NH];
__device__ float g_sdst[NODES * NH];
__device__ float g_m[NODES * ND];
__device__ float g_nodew[NODES];
__device__ float g_sn[NODES];
__device__ float g_inflowA[NODES];
__device__ float g_inflowB[NODES];
__device__ unsigned g_barc;

// ---------------- fast math (HW approx) ----------------
__device__ __forceinline__ float ftanh(float x) {
    float r; asm("tanh.approx.f32 %0, %1;" : "=f"(r) : "f"(x)); return r;
}
__device__ __forceinline__ float fexp(float x) {
    float r; asm("ex2.approx.f32 %0, %1;" : "=f"(r) : "f"(x * 1.4426950408889634f)); return r;
}
__device__ __forceinline__ float fsig(float x) {
    float e; asm("ex2.approx.f32 %0, %1;" : "=f"(e) : "f"(-x * 1.4426950408889634f));
    float r; asm("rcp.approx.f32 %0, %1;" : "=f"(r) : "f"(1.0f + e)); return r;
}

// ---------------- staging helpers (256 threads) ----------------
__device__ __forceinline__ void stage_x16(const float* __restrict__ g, __half* xs, int ld, int coff) {
    for (int i = threadIdx.x; i < 128 * 16; i += 256) {
        int r = i >> 4, c4 = (i & 15) * 4;
        float4 v = __ldg(reinterpret_cast<const float4*>(g + (size_t)r * ND + c4));
        __half2* d = reinterpret_cast<__half2*>(xs + (size_t)r * ld + coff + c4);
        d[0] = __floats2half2_rn(v.x, v.y);
        d[1] = __floats2half2_rn(v.z, v.w);
    }
}
template <int K, int KR>
__device__ __forceinline__ void stage_w16(const float* __restrict__ g, __half* ws) {
    for (int i = threadIdx.x; i < K * 32; i += 256) {
        int r = i >> 5, c2 = i & 31;
        float2 v = make_float2(0.f, 0.f);
        if (r < KR) v = __ldg(reinterpret_cast<const float2*>(g + r * 64 + 2 * c2));
        *reinterpret_cast<__half2*>(ws + r * 72 + 2 * c2) = __floats2half2_rn(v.x, v.y);
    }
}
__device__ __forceinline__ void wcat_ldg(const float* __restrict__ A, const float* __restrict__ B,
                                         __half2 wn[16]) {
#pragma unroll
    for (int p = 0; p < 16; p++) {
        int i = threadIdx.x + p * 256;
        int r = i >> 5, c2 = i & 31;
        const float* src = (r < 64) ? (A + r * 64 + 2 * c2) : (B + (r - 64) * 64 + 2 * c2);
        float2 v = __ldg(reinterpret_cast<const float2*>(src));
        wn[p] = __floats2half2_rn(v.x, v.y);
    }
}
__device__ __forceinline__ void wcat_sts(__half* ws, const __half2 wn[16]) {
#pragma unroll
    for (int p = 0; p < 16; p++) {
        int i = threadIdx.x + p * 256;
        int r = i >> 5, c2 = i & 31;
        *reinterpret_cast<__half2*>(ws + r * 72 + 2 * c2) = wn[p];
    }
}

// ---------------- WMMA GEMM (8 warps) ----------------
template <int KT, int ALD>
__device__ __forceinline__ void wgemm(const __half* Xs, const __half* Ws, float* Os) {
    int m0 = (threadIdx.x >> 5) * 16;
    wmma::fragment<wmma::accumulator, 16, 16, 16, float> c[4];
#pragma unroll
    for (int n = 0; n < 4; n++) wmma::fill_fragment(c[n], 0.0f);
#pragma unroll
    for (int kt = 0; kt < KT; kt++) {
        wmma::fragment<wmma::matrix_a, 16, 16, 16, __half, wmma::row_major> a;
        wmma::load_matrix_sync(a, Xs + m0 * ALD + kt * 16, ALD);
#pragma unroll
        for (int n = 0; n < 4; n++) {
            wmma::fragment<wmma::matrix_b, 16, 16, 16, __half, wmma::row_major> b;
            wmma::load_matrix_sync(b, Ws + kt * 16 * 72 + n * 16, 72);
            wmma::mma_sync(c[n], a, b, c[n]);
        }
    }
#pragma unroll
    for (int n = 0; n < 4; n++)
        wmma::store_matrix_sync(Os + m0 * 72 + n * 16, c[n], 72, wmma::mem_row_major);
}

// ---------------- encoder ----------------
#define ENC_SMEM (128 * 56 * 2 + 128 * 72 * 2 + 64 * 72 * 2 + 128 * 72 * 4)
__global__ void __launch_bounds__(256)
k_encoder(const float* __restrict__ emb, const float* __restrict__ feat,
          const float* __restrict__ W1, const float* __restrict__ b1,
          const float* __restrict__ W2, const float* __restrict__ b2) {
    extern __shared__ __align__(16) char smraw[];
    __half* X1 = (__half*)smraw;
    __half* X2 = (__half*)(smraw + 128 * 56 * 2);
    __half* Wb = (__half*)(smraw + 128 * 56 * 2 + 128 * 72 * 2);
    float* O = (float*)(smraw + 128 * 56 * 2 + 128 * 72 * 2 + 64 * 72 * 2);
    int tid = threadIdx.x;
    int nb0 = blockIdx.x * 128;

    __half2 w2r[8];
#pragma unroll
    for (int p = 0; p < 8; p++) {
        int i = tid + p * 256;
        int r = i >> 5, c2 = i & 31;
        float2 v = __ldg(reinterpret_cast<const float2*>(W2 + r * 64 + 2 * c2));
        w2r[p] = __floats2half2_rn(v.x, v.y);
    }
    {
        int r = tid >> 1, part = tid & 1;
        const float4* e4 = reinterpret_cast<const float4*>(emb + (size_t)(nb0 + r) * NE);
        __half2* row = reinterpret_cast<__half2*>(X1 + (size_t)r * 56);
#pragma unroll
        for (int c = part * 4; c < part * 4 + 4; c++) {
            float4 v = __ldg(e4 + c);
            row[2 * c] = __floats2half2_rn(v.x, v.y);
            row[2 * c + 1] = __floats2half2_rn(v.z, v.w);
        }
        if (part) {
            float2 fv = __ldg(reinterpret_cast<const float2*>(feat + (size_t)(nb0 + r) * 2));
            row[16] = __floats2half2_rn(fv.x, fv.y);
#pragma unroll
            for (int c2 = 17; c2 < 28; c2++) row[c2] = __floats2half2_rn(0.f, 0.f);
        }
    }
    stage_w16<48, 34>(W1, Wb);
    if (tid < 128) {
        g_inflowA[nb0 + tid] = 0.0f;
        g_inflowB[nb0 + tid] = 0.0f;
    }
    __syncthreads();
    wgemm<3, 56>(X1, Wb, O);
    __syncthreads();
#pragma unroll
    for (int p = 0; p < 8; p++) {
        int i = tid + p * 256;
        int r = i >> 5, c2 = i & 31;
        *reinterpret_cast<__half2*>(Wb + r * 72 + 2 * c2) = w2r[p];
    }
    for (int i = tid; i < 128 * 32; i += 256) {
        int row = i >> 5, c2 = i & 31;
        float o0 = O[row * 72 + 2 * c2] + __ldg(&b1[2 * c2]);
        float o1 = O[row * 72 + 2 * c2 + 1] + __ldg(&b1[2 * c2 + 1]);
        *reinterpret_cast<__half2*>(X2 + row * 72 + 2 * c2) =
            __floats2half2_rn(ftanh(o0), ftanh(o1));
    }
    __syncthreads();
    wgemm<4, 72>(X2, Wb, O);
    __syncthreads();
    for (int i = tid; i < 128 * 16; i += 256) {
        int row = i >> 4, c4 = (i & 15) * 4;
        float4 o = *reinterpret_cast<const float4*>(O + row * 72 + c4);
        float4 r;
        r.x = ftanh(o.x + __ldg(&b2[c4]));
        r.y = ftanh(o.y + __ldg(&b2[c4 + 1]));
        r.z = ftanh(o.z + __ldg(&b2[c4 + 2]));
        r.w = ftanh(o.w + __ldg(&b2[c4 + 3]));
        *reinterpret_cast<float4*>(g_h + (size_t)(nb0 + row) * ND + c4) = r;
    }
}

// ---------------- GAT transform: scores via h·(W@a), heads via WMMA ----------------
#define GAT_SMEM (128 * 72 * 2 + 4 * 64 * 72 * 2 + 128 * 72 * 4 + 8 * 64 * 4)
__global__ void __launch_bounds__(256)
k_gat_t(const float* __restrict__ Wgat, const float* __restrict__ asrc,
        const float* __restrict__ adst) {
    extern __shared__ __align__(16) char smraw[];
    __half* Xs = (__half*)smraw;
    __half* Wb4 = (__half*)(smraw + 128 * 72 * 2);
    float* O = (float*)(smraw + 128 * 72 * 2 + 4 * 64 * 72 * 2);
    float* WA = O + 128 * 72;
    int tid = threadIdx.x;
    int nb0 = blockIdx.x * 128;
    stage_x16(g_h + (size_t)nb0 * ND, Xs, 72, 0);
    for (int i = tid; i < 4 * 64 * 32; i += 256) {
        int hd = i >> 11, rem = i & 2047;
        int r = rem >> 5, c2 = rem & 31;
        float2 v = __ldg(reinterpret_cast<const float2*>(Wgat + (size_t)hd * ND * ND + r * 64 + 2 * c2));
        *reinterpret_cast<__half2*>(Wb4 + (size_t)hd * 64 * 72 + r * 72 + 2 * c2) =
            __floats2half2_rn(v.x, v.y);
    }
    {
        int hd = tid >> 6, k = tid & 63;
        const float* Wrow = Wgat + (size_t)hd * ND * ND + k * ND;
        float ss = 0.f, sd = 0.f;
#pragma unroll 8
        for (int c = 0; c < 64; c++) {
            float w = __ldg(&Wrow[c]);
            ss += w * __ldg(&asrc[hd * ND + c]);
            sd += w * __ldg(&adst[hd * ND + c]);
        }
        WA[(hd * 2 + 0) * 64 + k] = ss;
        WA[(hd * 2 + 1) * 64 + k] = sd;
    }
    __syncthreads();
    {
        int r = tid >> 1, hf = (tid & 1) * 32;
        float ssv[4] = {0.f, 0.f, 0.f, 0.f}, sdv[4] = {0.f, 0.f, 0.f, 0.f};
#pragma unroll 4
        for (int k = 0; k < 32; k++) {
            float x = __half2float(Xs[r * 72 + hf + k]);
#pragma unroll
            for (int hd = 0; hd < 4; hd++) {
                ssv[hd] += x * WA[(hd * 2 + 0) * 64 + hf + k];
                sdv[hd] += x * WA[(hd * 2 + 1) * 64 + hf + k];
            }
        }
#pragma unroll
        for (int hd = 0; hd < 4; hd++) {
            ssv[hd] += __shfl_xor_sync(0xffffffffu, ssv[hd], 1);
            sdv[hd] += __shfl_xor_sync(0xffffffffu, sdv[hd], 1);
        }
        if ((tid & 1) == 0) {
#pragma unroll
            for (int hd = 0; hd < 4; hd++) {
                g_ssrc[(size_t)(nb0 + r) * NH + hd] = ssv[hd];
                g_sdst[(size_t)(nb0 + r) * NH + hd] = sdv[hd];
            }
        }
    }
    for (int hd = 0; hd < NH; hd++) {
        wgemm<4, 72>(Xs, Wb4 + (size_t)hd * 64 * 72, O);
        __syncthreads();
        for (int i = tid; i < 128 * 32; i += 256) {
            int row = i >> 5, c2 = i & 31;
            float o0 = O[row * 72 + 2 * c2], o1 = O[row * 72 + 2 * c2 + 1];
            *reinterpret_cast<__half2*>(g_t + ((size_t)(nb0 + row) * NH + hd) * ND + 2 * c2) =
                __floats2half2_rn(o0, o1);
        }
        __syncthreads();
    }
}

// ---------------- GAT attention: ONE warp per node, all 4 heads ----------------
__global__ void __launch_bounds__(256)
k_gat_attn(const int* __restrict__ adj) {
    __shared__ float s_agg[8][NH][ND];
    int w = threadIdx.x >> 5, lane = threadIdx.x & 31;
    int n = blockIdx.x * 8 + w;
    int b = n >> 14;
    int hd = lane >> 3;

    // ---- score phase: lane k (<16) handles neighbor k, all 4 heads ----
    int idx = NV;
    if (lane < NK) idx = __ldg(&adj[(size_t)n * NK + lane]);
    bool valid = (idx < NV);
    float4 ss4 = __ldg(reinterpret_cast<const float4*>(&g_ssrc[(size_t)n * NH]));
    float s0 = NEGV, s1 = NEGV, s2 = NEGV, s3 = NEGV;
    if (valid) {
        float4 sd4 = __ldg(reinterpret_cast<const float4*>(&g_sdst[((size_t)(b << 14) + idx) * NH]));
        s0 = ss4.x + sd4.x; s1 = ss4.y + sd4.y; s2 = ss4.z + sd4.z; s3 = ss4.w + sd4.w;
    }
    float m0 = s0, m1 = s1, m2 = s2, m3 = s3;
#pragma unroll
    for (int o = 8; o > 0; o >>= 1) {
        m0 = fmaxf(m0, __shfl_xor_sync(0xffffffffu, m0, o));
        m1 = fmaxf(m1, __shfl_xor_sync(0xffffffffu, m1, o));
        m2 = fmaxf(m2, __shfl_xor_sync(0xffffffffu, m2, o));
        m3 = fmaxf(m3, __shfl_xor_sync(0xffffffffu, m3, o));
    }
    float e0 = fexp(s0 - m0), e1 = fexp(s1 - m1), e2 = fexp(s2 - m2), e3 = fexp(s3 - m3);
    float q0 = e0, q1 = e1, q2 = e2, q3 = e3;
#pragma unroll
    for (int o = 8; o > 0; o >>= 1) {
        q0 += __shfl_xor_sync(0xffffffffu, q0, o);
        q1 += __shfl_xor_sync(0xffffffffu, q1, o);
        q2 += __shfl_xor_sync(0xffffffffu, q2, o);
        q3 += __shfl_xor_sync(0xffffffffu, q3, o);
    }
    float at0 = e0 / q0, at1 = e1 / q1, at2 = e2 / q2, at3 = e3 / q3;

    // ---- gather phase: per k, whole warp loads neighbor's 512B t-block ----
    float acc[8] = {0.f, 0.f, 0.f, 0.f, 0.f, 0.f, 0.f, 0.f};
#pragma unroll
    for (int k = 0; k < NK; k++) {
        int j = __shfl_sync(0xffffffffu, idx, k);
        float a0 = __shfl_sync(0xffffffffu, at0, k);
        float a1 = __shfl_sync(0xffffffffu, at1, k);
        float a2 = __shfl_sync(0xffffffffu, at2, k);
        float a3 = __shfl_sync(0xffffffffu, at3, k);
        if (j < NV) {
            float a = (lane & 16) ? ((lane & 8) ? a3 : a2) : ((lane & 8) ? a1 : a0);
            const uint4* tp = reinterpret_cast<const uint4*>(
                g_t + ((size_t)(b << 14) + j) * (NH * ND));
            uint4 tv = __ldg(tp + lane);
            __half2 h0 = *reinterpret_cast<__half2*>(&tv.x);
            __half2 h1 = *reinterpret_cast<__half2*>(&tv.y);
            __half2 h2 = *reinterpret_cast<__half2*>(&tv.z);
            __half2 h3 = *reinterpret_cast<__half2*>(&tv.w);
            float2 f0 = __half22float2(h0), f1 = __half22float2(h1);
            float2 f2 = __half22float2(h2), f3 = __half22float2(h3);
            acc[0] += a * f0.x; acc[1] += a * f0.y;
            acc[2] += a * f1.x; acc[3] += a * f1.y;
            acc[4] += a * f2.x; acc[5] += a * f2.y;
            acc[6] += a * f3.x; acc[7] += a * f3.y;
        }
    }
    // lane covers head (lane>>3), columns (lane&7)*8 .. +7
    float* dst = &s_agg[w][hd][(lane & 7) * 8];
    *reinterpret_cast<float4*>(dst) = make_float4(acc[0], acc[1], acc[2], acc[3]);
    *reinterpret_cast<float4*>(dst + 4) = make_float4(acc[4], acc[5], acc[6], acc[7]);
    __syncthreads();
    for (int i = threadIdx.x; i < 8 * ND; i += 256) {
        int nn = i >> 6, j = i & 63;
        float t = s_agg[nn][0][j] + s_agg[nn][1][j] + s_agg[nn][2][j] + s_agg[nn][3][j];
        g_m[((size_t)(blockIdx.x * 8 + nn)) * ND + j] = ftanh(t * 0.25f);
    }
}

// ---------------- fused GRU: 3 concat GEMMs, W prefetch, z in regs ----------------
#define GRU_SMEM (128 * 136 * 2 + 128 * 72 * 2 + 128 * 72 * 4)
__global__ void __launch_bounds__(256, 2)
k_gru(const float* __restrict__ Wz, const float* __restrict__ Uz, const float* __restrict__ bz,
      const float* __restrict__ Wr, const float* __restrict__ Ur, const float* __restrict__ br,
      const float* __restrict__ Wc, const float* __restrict__ Uc, const float* __restrict__ bc) {
    extern __shared__ __align__(16) char smraw[];
    __half* Xc = (__half*)smraw;
    __half* Wb = (__half*)(smraw + 128 * 136 * 2);
    float* O = (float*)(smraw + 128 * 136 * 2 + 128 * 72 * 2);
    int tid = threadIdx.x;
    int nb0 = blockIdx.x * 128;

    stage_x16(g_m + (size_t)nb0 * ND, Xc, 136, 0);
    stage_x16(g_h + (size_t)nb0 * ND, Xc, 136, 64);
    {
        __half2 w0[16];
        wcat_ldg(Wz, Uz, w0);
        wcat_sts(Wb, w0);
    }
    __half2 wn[16];
    wcat_ldg(Wr, Ur, wn);
    __syncthreads();
    // ---- z ----
    wgemm<8, 136>(Xc, Wb, O);
    __syncthreads();
    wcat_sts(Wb, wn);
    wcat_ldg(Wc, Uc, wn);
    float zr[32];
#pragma unroll
    for (int p = 0; p < 8; p++) {
        int i = tid + p * 256;
        int row = i >> 4, c4 = (i & 15) * 4;
        float4 o = *reinterpret_cast<const float4*>(O + row * 72 + c4);
        zr[4 * p + 0] = fsig(o.x + __ldg(&bz[c4]));
        zr[4 * p + 1] = fsig(o.y + __ldg(&bz[c4 + 1]));
        zr[4 * p + 2] = fsig(o.z + __ldg(&bz[c4 + 2]));
        zr[4 * p + 3] = fsig(o.w + __ldg(&bz[c4 + 3]));
    }
    __syncthreads();
    // ---- r, r*h -> Xc right half ----
    wgemm<8, 136>(Xc, Wb, O);
    __syncthreads();
    wcat_sts(Wb, wn);
#pragma unroll
    for (int p = 0; p < 16; p++) {
        int i = tid + p * 256;
        int row = i >> 5, c2 = i & 31;
        float o0 = O[row * 72 + 2 * c2] + __ldg(&br[2 * c2]);
        float o1 = O[row * 72 + 2 * c2 + 1] + __ldg(&br[2 * c2 + 1]);
        __half2* hp = reinterpret_cast<__half2*>(Xc + row * 136 + 64 + 2 * c2);
        float2 hf = __half22float2(*hp);
        *hp = __floats2half2_rn(fsig(o0) * hf.x, fsig(o1) * hf.y);
    }
    __syncthreads();
    // ---- c + combine ----
    wgemm<8, 136>(Xc, Wb, O);
    __syncthreads();
#pragma unroll
    for (int p = 0; p < 8; p++) {
        int i = tid + p * 256;
        int row = i >> 4, c4 = (i & 15) * 4;
        float4 o = *reinterpret_cast<const float4*>(O + row * 72 + c4);
        float* hp = g_h + (size_t)(nb0 + row) * ND + c4;
        float4 h = *reinterpret_cast<const float4*>(hp);
        float4 r;
        r.x = h.x + zr[4 * p + 0] * (ftanh(o.x + __ldg(&bc[c4])) - h.x);
        r.y = h.y + zr[4 * p + 1] * (ftanh(o.y + __ldg(&bc[c4 + 1])) - h.y);
        r.z = h.z + zr[4 * p + 2] * (ftanh(o.z + __ldg(&bc[c4 + 2])) - h.z);
        r.w = h.w + zr[4 * p + 3] * (ftanh(o.w + __ldg(&bc[c4 + 3])) - h.w);
        *reinterpret_cast<float4*>(hp) = r;
    }
}

// ---------------- decoder ----------------
#define DEC_SMEM (128 * 72 * 2 + 64 * 72 * 2 + 128 * 72 * 4)
__global__ void __launch_bounds__(256)
k_decoder(const float* __restrict__ W1, const float* __restrict__ b1,
          const float* __restrict__ W2, const float* __restrict__ b2) {
    extern __shared__ __align__(16) char smraw[];
    __half* Xs = (__half*)smraw;
    __half* Wb = (__half*)(smraw + 128 * 72 * 2);
    float* O = (float*)(smraw + 128 * 72 * 2 + 64 * 72 * 2);
    int tid = threadIdx.x;
    int nb0 = blockIdx.x * 128;
    stage_x16(g_h + (size_t)nb0 * ND, Xs, 72, 0);
    stage_w16<64, 64>(W1, Wb);
    __syncthreads();
    wgemm<4, 72>(Xs, Wb, O);
    __syncthreads();
    {
        int r = tid >> 1, hf = (tid & 1) * 32;
        float w = 0.f;
        const float* orow = O + r * 72 + hf;
#pragma unroll 8
        for (int j = 0; j < 32; j++)
            w += ftanh(orow[j] + __ldg(&b1[hf + j])) * __ldg(&W2[hf + j]);
        w += __shfl_xor_sync(0xffffffffu, w, 1);
        if ((tid & 1) == 0) g_nodew[nb0 + r] = w + __ldg(&b2[0]);
    }
}

// ---------------- edge softmax + sumsq + flow0 scatter ----------------
__global__ void k_normw(const int* __restrict__ adj, const float* __restrict__ demands,
                        float* __restrict__ out_normw) {
    int n = blockIdx.x * blockDim.x + threadIdx.x;
    int base = (n >> 14) << 14;
    int idxv[NK];
    float sc[NK];
    float mx = NEGV;
#pragma unroll
    for (int k = 0; k < NK; k++) {
        int idx = __ldg(&adj[(size_t)n * NK + k]);
        idxv[k] = idx;
        float s = (idx < NV) ? __ldg(&g_nodew[(size_t)base + idx]) : NEGV;
        sc[k] = s;
        mx = fmaxf(mx, s);
    }
    float sum = 0.0f;
#pragma unroll
    for (int k = 0; k < NK; k++) { sc[k] = fexp(sc[k] - mx); sum += sc[k]; }
    float inv = 1.0f / sum;
    float nf0 = fmaxf(-__ldg(&demands[n]), 0.0f);
    float sn = 0.0f;
#pragma unroll
    for (int k = 0; k < NK; k++) {
        float nw = sc[k] * inv;
        sc[k] = nw;
        sn += nw * nw;
        out_normw[(size_t)n * NK + k] = nw;
    }
    g_sn[n] = sn;
#pragma unroll
    for (int k = 0; k < NK; k++)
        if (idxv[k] < NV) atomicAdd(&g_inflowA[base + idxv[k]], sc[k] * nf0);
}

// ---------------- fused 10-iteration flow solver (persistent, grid barrier) ----------------
__global__ void __launch_bounds__(256)
k_flow_all(const int* __restrict__ adj, const float* __restrict__ demands,
           const float* __restrict__ normw, float* bufA, float* bufB,
           float* __restrict__ out_flow, float* __restrict__ out_pflow,
           float* __restrict__ cost) {
    int n = blockIdx.x * 256 + threadIdx.x;
    int base = (n >> 14) << 14;
    int idxv[NK];
#pragma unroll
    for (int k = 0; k < NK; k++) idxv[k] = __ldg(&adj[(size_t)n * NK + k]);
    float nw[NK];
    const float4* nw4 = reinterpret_cast<const float4*>(normw + (size_t)n * NK);
#pragma unroll
    for (int k = 0; k < 4; k++) {
        float4 v = __ldg(nw4 + k);
        nw[4 * k] = v.x; nw[4 * k + 1] = v.y; nw[4 * k + 2] = v.z; nw[4 * k + 3] = v.w;
    }
    float dem = __ldg(&demands[n]);
    float* cur = bufA;
    float* nxt = bufB;
    for (int it = 0; it < 9; it++) {
        float nf = fmaxf(__ldcg(&cur[n]) - dem, 0.0f);
        cur[n] = 0.0f;
        if (it == 8) {
            float4* o4 = reinterpret_cast<float4*>(out_pflow + (size_t)n * NK);
#pragma unroll
            for (int k = 0; k < 4; k++)
                o4[k] = make_float4(nw[4 * k] * nf, nw[4 * k + 1] * nf,
                                    nw[4 * k + 2] * nf, nw[4 * k + 3] * nf);
        }
#pragma unroll
        for (int k = 0; k < NK; k++)
            if (idxv[k] < NV) atomicAdd(&nxt[base + idxv[k]], nw[k] * nf);
        __syncthreads();
        if (threadIdx.x == 0) {
            __threadfence();
            atomicAdd(&g_barc, 1u);
            unsigned tgt = (unsigned)(it + 1) * gridDim.x;
            while (*((volatile unsigned*)&g_barc) < tgt) {}
            __threadfence();
        }
        __syncthreads();
        float* t = cur; cur = nxt; nxt = t;
    }
    float nf = fmaxf(__ldcg(&cur[n]) - dem, 0.0f);
    {
        float4* o4 = reinterpret_cast<float4*>(out_flow + (size_t)n * NK);
#pragma unroll
        for (int k = 0; k < 4; k++)
            o4[k] = make_float4(nw[4 * k] * nf, nw[4 * k + 1] * nf,
                                nw[4 * k + 2] * nf, nw[4 * k + 3] * nf);
    }
    float val = nf * nf * __ldg(&g_sn[n]);
#pragma unroll
    for (int o = 16; o > 0; o >>= 1) val += __shfl_xor_sync(0xffffffffu, val, o);
    __shared__ float wsum[8];
    if ((threadIdx.x & 31) == 0) wsum[threadIdx.x >> 5] = val;
    __syncthreads();
    if (threadIdx.x == 0) {
        float t = 0.0f;
#pragma unroll
        for (int i = 0; i < 8; i++) t += wsum[i];
        atomicAdd(&cost[n >> 14], t);
    }
}

// ---------------- launch ----------------
extern "C" void kernel_launch(void* const* d_in, const int* in_sizes, int n_in,
                              void* d_out, int out_size) {
    const float* emb     = (const float*)d_in[0];
    const float* feat    = (const float*)d_in[1];
    const float* demands = (const float*)d_in[2];
    const int*   adj     = (const int*)d_in[3];
    int wb = (in_sizes[5] == 1) ? 6 : 5;
    const float* W_enc1 = (const float*)d_in[wb + 0];
    const float* b_enc1 = (const float*)d_in[wb + 1];
    const float* W_enc2 = (const float*)d_in[wb + 2];
    const float* b_enc2 = (const float*)d_in[wb + 3];
    const float* W_gat  = (const float*)d_in[wb + 4];
    const float* a_src  = (const float*)d_in[wb + 5];
    const float* a_dst  = (const float*)d_in[wb + 6];
    const float* W_z    = (const float*)d_in[wb + 7];
    const float* U_z    = (const float*)d_in[wb + 8];
    const float* b_z    = (const float*)d_in[wb + 9];
    const float* W_r    = (const float*)d_in[wb + 10];
    const float* U_r    = (const float*)d_in[wb + 11];
    const float* b_r    = (const float*)d_in[wb + 12];
    const float* W_c    = (const float*)d_in[wb + 13];
    const float* U_c    = (const float*)d_in[wb + 14];
    const float* b_c    = (const float*)d_in[wb + 15];
    const float* W_dec1 = (const float*)d_in[wb + 16];
    const float* b_dec1 = (const float*)d_in[wb + 17];
    const float* W_dec2 = (const float*)d_in[wb + 18];
    const float* b_dec2 = (const float*)d_in[wb + 19];

    float* out = (float*)d_out;
    float* out_flow  = out;                               // [B,V,K] f10
    float* out_cost  = out + (size_t)NB * NV * NK;        // [B]
    float* out_normw = out_cost + NB;                     // [B,V,K]
    float* out_pflow = out_normw + (size_t)NB * NV * NK;  // [B,V,K] f9

    float *pA, *pB;
    cudaGetSymbolAddress((void**)&pA, g_inflowA);
    cudaGetSymbolAddress((void**)&pB, g_inflowB);
    unsigned* pbar;
    cudaGetSymbolAddress((void**)&pbar, g_barc);

    cudaFuncSetAttribute(k_encoder, cudaFuncAttributeMaxDynamicSharedMemorySize, ENC_SMEM);
    cudaFuncSetAttribute(k_gat_t, cudaFuncAttributeMaxDynamicSharedMemorySize, GAT_SMEM);
    cudaFuncSetAttribute(k_gru, cudaFuncAttributeMaxDynamicSharedMemorySize, GRU_SMEM);
    cudaFuncSetAttribute(k_decoder, cudaFuncAttributeMaxDynamicSharedMemorySize, DEC_SMEM);

    k_encoder<<<512, 256, ENC_SMEM>>>(emb, feat, W_enc1, b_enc1, W_enc2, b_enc2);
    for (int l = 0; l < NL; l++) {
        k_gat_t<<<512, 256, GAT_SMEM>>>(W_gat, a_src, a_dst);
        k_gat_attn<<<NODES / 8, 256>>>(adj);
        k_gru<<<512, 256, GRU_SMEM>>>(W_z, U_z, b_z, W_r, U_r, b_r, W_c, U_c, b_c);
    }
    k_decoder<<<512, 256, DEC_SMEM>>>(W_dec1, b_dec1, W_dec2, b_dec2);
    k_normw<<<256, 256>>>(adj, demands, out_normw);

    cudaMemsetAsync(pbar, 0, sizeof(unsigned), 0);
    cudaMemsetAsync(out_cost, 0, NB * sizeof(float), 0);
    k_flow_all<<<256, 256>>>(adj, demands, out_normw, pA, pB, out_flow, out_pflow, out_cost);
}

// round 14
// speedup vs baseline: 2.6755x; 1.0659x over previous
#include <cuda_runtime.h>
#include <cuda_fp16.h>
#include <mma.h>
#include <math.h>

using namespace nvcuda;

#define NB 4
#define NV 16384
#define NK 16
#define NE 32
#define ND 64
#define NH 4
#define NL 2
#define NEGV (-1e9f)
#define NODES (NB * NV)

// ---------------- scratch ----------------
__device__ float g_h[NODES * ND];
__device__ __half g_t[(size_t)NODES * NH * ND];
__device__ float g_ssrc[NODES * NH];
__device__ float g_sdst[NODES * NH];
__device__ float g_m[NODES * ND];
__device__ float g_nodew[NODES];
__device__ float g_inflowA[NODES];
__device__ float g_inflowB[NODES];
__device__ unsigned g_barc;

// ---------------- fast math (HW approx) ----------------
__device__ __forceinline__ float ftanh(float x) {
    float r; asm("tanh.approx.f32 %0, %1;" : "=f"(r) : "f"(x)); return r;
}
__device__ __forceinline__ float fexp(float x) {
    float r; asm("ex2.approx.f32 %0, %1;" : "=f"(r) : "f"(x * 1.4426950408889634f)); return r;
}
__device__ __forceinline__ float fsig(float x) {
    float e; asm("ex2.approx.f32 %0, %1;" : "=f"(e) : "f"(-x * 1.4426950408889634f));
    float r; asm("rcp.approx.f32 %0, %1;" : "=f"(r) : "f"(1.0f + e)); return r;
}

// ---------------- staging helpers (256 threads) ----------------
__device__ __forceinline__ void stage_x16(const float* __restrict__ g, __half* xs, int ld, int coff) {
    for (int i = threadIdx.x; i < 128 * 16; i += 256) {
        int r = i >> 4, c4 = (i & 15) * 4;
        float4 v = __ldg(reinterpret_cast<const float4*>(g + (size_t)r * ND + c4));
        __half2* d = reinterpret_cast<__half2*>(xs + (size_t)r * ld + coff + c4);
        d[0] = __floats2half2_rn(v.x, v.y);
        d[1] = __floats2half2_rn(v.z, v.w);
    }
}
template <int K, int KR>
__device__ __forceinline__ void stage_w16(const float* __restrict__ g, __half* ws) {
    for (int i = threadIdx.x; i < K * 32; i += 256) {
        int r = i >> 5, c2 = i & 31;
        float2 v = make_float2(0.f, 0.f);
        if (r < KR) v = __ldg(reinterpret_cast<const float2*>(g + r * 64 + 2 * c2));
        *reinterpret_cast<__half2*>(ws + r * 72 + 2 * c2) = __floats2half2_rn(v.x, v.y);
    }
}
__device__ __forceinline__ void wcat_ldg(const float* __restrict__ A, const float* __restrict__ B,
                                         __half2 wn[16]) {
#pragma unroll
    for (int p = 0; p < 16; p++) {
        int i = threadIdx.x + p * 256;
        int r = i >> 5, c2 = i & 31;
        const float* src = (r < 64) ? (A + r * 64 + 2 * c2) : (B + (r - 64) * 64 + 2 * c2);
        float2 v = __ldg(reinterpret_cast<const float2*>(src));
        wn[p] = __floats2half2_rn(v.x, v.y);
    }
}
__device__ __forceinline__ void wcat_sts(__half* ws, const __half2 wn[16]) {
#pragma unroll
    for (int p = 0; p < 16; p++) {
        int i = threadIdx.x + p * 256;
        int r = i >> 5, c2 = i & 31;
        *reinterpret_cast<__half2*>(ws + r * 72 + 2 * c2) = wn[p];
    }
}

// ---------------- WMMA GEMM (8 warps) ----------------
template <int KT, int ALD>
__device__ __forceinline__ void wgemm(const __half* Xs, const __half* Ws, float* Os) {
    int m0 = (threadIdx.x >> 5) * 16;
    wmma::fragment<wmma::accumulator, 16, 16, 16, float> c[4];
#pragma unroll
    for (int n = 0; n < 4; n++) wmma::fill_fragment(c[n], 0.0f);
#pragma unroll
    for (int kt = 0; kt < KT; kt++) {
        wmma::fragment<wmma::matrix_a, 16, 16, 16, __half, wmma::row_major> a;
        wmma::load_matrix_sync(a, Xs + m0 * ALD + kt * 16, ALD);
#pragma unroll
        for (int n = 0; n < 4; n++) {
            wmma::fragment<wmma::matrix_b, 16, 16, 16, __half, wmma::row_major> b;
            wmma::load_matrix_sync(b, Ws + kt * 16 * 72 + n * 16, 72);
            wmma::mma_sync(c[n], a, b, c[n]);
        }
    }
#pragma unroll
    for (int n = 0; n < 4; n++)
        wmma::store_matrix_sync(Os + m0 * 72 + n * 16, c[n], 72, wmma::mem_row_major);
}

// ---------------- GAT tail: scores + 4 head GEMMs from resident h tile (fp16, ld=ALD) ----------------
template <int ALD>
__device__ __forceinline__ void gat_tail(const __half* Xs, __half* Wb, float* O, float* WA,
                                         const float* __restrict__ Wgat,
                                         const float* __restrict__ asrc,
                                         const float* __restrict__ adst, int nb0) {
    int tid = threadIdx.x;
    // WA[hd][0/1][k] = sum_c Wgat[hd][k][c] * a{src,dst}[hd][c]
    {
        int hd = tid >> 6, k = tid & 63;
        const float* Wrow = Wgat + (size_t)hd * ND * ND + k * ND;
        float ss = 0.f, sd = 0.f;
#pragma unroll 8
        for (int c = 0; c < 64; c++) {
            float w = __ldg(&Wrow[c]);
            ss += w * __ldg(&asrc[hd * ND + c]);
            sd += w * __ldg(&adst[hd * ND + c]);
        }
        WA[(hd * 2 + 0) * 64 + k] = ss;
        WA[(hd * 2 + 1) * 64 + k] = sd;
    }
    __syncthreads();  // also covers h-writes into Xs
    // scores: 2 threads per node, all 4 heads
    {
        int r = tid >> 1, hf = (tid & 1) * 32;
        float ssv[4] = {0.f, 0.f, 0.f, 0.f}, sdv[4] = {0.f, 0.f, 0.f, 0.f};
#pragma unroll 4
        for (int k = 0; k < 32; k++) {
            float x = __half2float(Xs[r * ALD + hf + k]);
#pragma unroll
            for (int hd = 0; hd < 4; hd++) {
                ssv[hd] += x * WA[(hd * 2 + 0) * 64 + hf + k];
                sdv[hd] += x * WA[(hd * 2 + 1) * 64 + hf + k];
            }
        }
#pragma unroll
        for (int hd = 0; hd < 4; hd++) {
            ssv[hd] += __shfl_xor_sync(0xffffffffu, ssv[hd], 1);
            sdv[hd] += __shfl_xor_sync(0xffffffffu, sdv[hd], 1);
        }
        if ((tid & 1) == 0) {
#pragma unroll
            for (int hd = 0; hd < 4; hd++) {
                g_ssrc[(size_t)(nb0 + r) * NH + hd] = ssv[hd];
                g_sdst[(size_t)(nb0 + r) * NH + hd] = sdv[hd];
            }
        }
    }
    // 4 head GEMMs -> g_t fp16
    for (int hd = 0; hd < NH; hd++) {
        __syncthreads();
        stage_w16<64, 64>(Wgat + (size_t)hd * ND * ND, Wb);
        __syncthreads();
        wgemm<4, ALD>(Xs, Wb, O);
        __syncthreads();
        for (int i = tid; i < 128 * 32; i += 256) {
            int row = i >> 5, c2 = i & 31;
            float o0 = O[row * 72 + 2 * c2], o1 = O[row * 72 + 2 * c2 + 1];
            *reinterpret_cast<__half2*>(g_t + ((size_t)(nb0 + row) * NH + hd) * ND + 2 * c2) =
                __floats2half2_rn(o0, o1);
        }
    }
}

// ---------------- encoder + layer-0 GAT transform ----------------
#define ENC_SMEM (128 * 56 * 2 + 128 * 72 * 2 + 64 * 72 * 2 + 128 * 72 * 4 + 8 * 64 * 4)
__global__ void __launch_bounds__(256)
k_encoder(const float* __restrict__ emb, const float* __restrict__ feat,
          const float* __restrict__ W1, const float* __restrict__ b1,
          const float* __restrict__ W2, const float* __restrict__ b2,
          const float* __restrict__ Wgat, const float* __restrict__ asrc,
          const float* __restrict__ adst) {
    extern __shared__ __align__(16) char smraw[];
    __half* X1 = (__half*)smraw;
    __half* X2 = (__half*)(smraw + 128 * 56 * 2);
    __half* Wb = (__half*)(smraw + 128 * 56 * 2 + 128 * 72 * 2);
    float* O = (float*)(smraw + 128 * 56 * 2 + 128 * 72 * 2 + 64 * 72 * 2);
    float* WA = O + 128 * 72;
    int tid = threadIdx.x;
    int nb0 = blockIdx.x * 128;

    __half2 w2r[8];
#pragma unroll
    for (int p = 0; p < 8; p++) {
        int i = tid + p * 256;
        int r = i >> 5, c2 = i & 31;
        float2 v = __ldg(reinterpret_cast<const float2*>(W2 + r * 64 + 2 * c2));
        w2r[p] = __floats2half2_rn(v.x, v.y);
    }
    {
        int r = tid >> 1, part = tid & 1;
        const float4* e4 = reinterpret_cast<const float4*>(emb + (size_t)(nb0 + r) * NE);
        __half2* row = reinterpret_cast<__half2*>(X1 + (size_t)r * 56);
#pragma unroll
        for (int c = part * 4; c < part * 4 + 4; c++) {
            float4 v = __ldg(e4 + c);
            row[2 * c] = __floats2half2_rn(v.x, v.y);
            row[2 * c + 1] = __floats2half2_rn(v.z, v.w);
        }
        if (part) {
            float2 fv = __ldg(reinterpret_cast<const float2*>(feat + (size_t)(nb0 + r) * 2));
            row[16] = __floats2half2_rn(fv.x, fv.y);
#pragma unroll
            for (int c2 = 17; c2 < 28; c2++) row[c2] = __floats2half2_rn(0.f, 0.f);
        }
    }
    stage_w16<48, 34>(W1, Wb);
    if (tid < 128) {
        g_inflowA[nb0 + tid] = 0.0f;
        g_inflowB[nb0 + tid] = 0.0f;
    }
    __syncthreads();
    wgemm<3, 56>(X1, Wb, O);
    __syncthreads();
#pragma unroll
    for (int p = 0; p < 8; p++) {
        int i = tid + p * 256;
        int r = i >> 5, c2 = i & 31;
        *reinterpret_cast<__half2*>(Wb + r * 72 + 2 * c2) = w2r[p];
    }
    for (int i = tid; i < 128 * 32; i += 256) {
        int row = i >> 5, c2 = i & 31;
        float o0 = O[row * 72 + 2 * c2] + __ldg(&b1[2 * c2]);
        float o1 = O[row * 72 + 2 * c2 + 1] + __ldg(&b1[2 * c2 + 1]);
        *reinterpret_cast<__half2*>(X2 + row * 72 + 2 * c2) =
            __floats2half2_rn(ftanh(o0), ftanh(o1));
    }
    __syncthreads();
    wgemm<4, 72>(X2, Wb, O);
    __syncthreads();
    // h epilogue: write g_h and overwrite X2 with h (fp16)
    for (int i = tid; i < 128 * 16; i += 256) {
        int row = i >> 4, c4 = (i & 15) * 4;
        float4 o = *reinterpret_cast<const float4*>(O + row * 72 + c4);
        float4 r;
        r.x = ftanh(o.x + __ldg(&b2[c4]));
        r.y = ftanh(o.y + __ldg(&b2[c4 + 1]));
        r.z = ftanh(o.z + __ldg(&b2[c4 + 2]));
        r.w = ftanh(o.w + __ldg(&b2[c4 + 3]));
        *reinterpret_cast<float4*>(g_h + (size_t)(nb0 + row) * ND + c4) = r;
        __half2* xp = reinterpret_cast<__half2*>(X2 + row * 72 + c4);
        xp[0] = __floats2half2_rn(r.x, r.y);
        xp[1] = __floats2half2_rn(r.z, r.w);
    }
    gat_tail<72>(X2, Wb, O, WA, Wgat, asrc, adst, nb0);
}

// ---------------- GAT attention: ONE warp per node, all 4 heads ----------------
__global__ void __launch_bounds__(256)
k_gat_attn(const int* __restrict__ adj) {
    __shared__ float s_agg[8][NH][ND];
    int w = threadIdx.x >> 5, lane = threadIdx.x & 31;
    int n = blockIdx.x * 8 + w;
    int b = n >> 14;
    int hd = lane >> 3;

    int idx = NV;
    if (lane < NK) idx = __ldg(&adj[(size_t)n * NK + lane]);
    bool valid = (idx < NV);
    float4 ss4 = __ldg(reinterpret_cast<const float4*>(&g_ssrc[(size_t)n * NH]));
    float s0 = NEGV, s1 = NEGV, s2 = NEGV, s3 = NEGV;
    if (valid) {
        float4 sd4 = __ldg(reinterpret_cast<const float4*>(&g_sdst[((size_t)(b << 14) + idx) * NH]));
        s0 = ss4.x + sd4.x; s1 = ss4.y + sd4.y; s2 = ss4.z + sd4.z; s3 = ss4.w + sd4.w;
    }
    float m0 = s0, m1 = s1, m2 = s2, m3 = s3;
#pragma unroll
    for (int o = 8; o > 0; o >>= 1) {
        m0 = fmaxf(m0, __shfl_xor_sync(0xffffffffu, m0, o));
        m1 = fmaxf(m1, __shfl_xor_sync(0xffffffffu, m1, o));
        m2 = fmaxf(m2, __shfl_xor_sync(0xffffffffu, m2, o));
        m3 = fmaxf(m3, __shfl_xor_sync(0xffffffffu, m3, o));
    }
    float e0 = fexp(s0 - m0), e1 = fexp(s1 - m1), e2 = fexp(s2 - m2), e3 = fexp(s3 - m3);
    float q0 = e0, q1 = e1, q2 = e2, q3 = e3;
#pragma unroll
    for (int o = 8; o > 0; o >>= 1) {
        q0 += __shfl_xor_sync(0xffffffffu, q0, o);
        q1 += __shfl_xor_sync(0xffffffffu, q1, o);
        q2 += __shfl_xor_sync(0xffffffffu, q2, o);
        q3 += __shfl_xor_sync(0xffffffffu, q3, o);
    }
    float at0 = e0 / q0, at1 = e1 / q1, at2 = e2 / q2, at3 = e3 / q3;

    float acc[8] = {0.f, 0.f, 0.f, 0.f, 0.f, 0.f, 0.f, 0.f};
#pragma unroll
    for (int k = 0; k < NK; k++) {
        int j = __shfl_sync(0xffffffffu, idx, k);
        float a0 = __shfl_sync(0xffffffffu, at0, k);
        float a1 = __shfl_sync(0xffffffffu, at1, k);
        float a2 = __shfl_sync(0xffffffffu, at2, k);
        float a3 = __shfl_sync(0xffffffffu, at3, k);
        if (j < NV) {
            float a = (lane & 16) ? ((lane & 8) ? a3 : a2) : ((lane & 8) ? a1 : a0);
            const uint4* tp = reinterpret_cast<const uint4*>(
                g_t + ((size_t)(b << 14) + j) * (NH * ND));
            uint4 tv = __ldg(tp + lane);
            __half2 h0 = *reinterpret_cast<__half2*>(&tv.x);
            __half2 h1 = *reinterpret_cast<__half2*>(&tv.y);
            __half2 h2 = *reinterpret_cast<__half2*>(&tv.z);
            __half2 h3 = *reinterpret_cast<__half2*>(&tv.w);
            float2 f0 = __half22float2(h0), f1 = __half22float2(h1);
            float2 f2 = __half22float2(h2), f3 = __half22float2(h3);
            acc[0] += a * f0.x; acc[1] += a * f0.y;
            acc[2] += a * f1.x; acc[3] += a * f1.y;
            acc[4] += a * f2.x; acc[5] += a * f2.y;
            acc[6] += a * f3.x; acc[7] += a * f3.y;
        }
    }
    float* dst = &s_agg[w][hd][(lane & 7) * 8];
    *reinterpret_cast<float4*>(dst) = make_float4(acc[0], acc[1], acc[2], acc[3]);
    *reinterpret_cast<float4*>(dst + 4) = make_float4(acc[4], acc[5], acc[6], acc[7]);
    __syncthreads();
    for (int i = threadIdx.x; i < 8 * ND; i += 256) {
        int nn = i >> 6, j = i & 63;
        float t = s_agg[nn][0][j] + s_agg[nn][1][j] + s_agg[nn][2][j] + s_agg[nn][3][j];
        g_m[((size_t)(blockIdx.x * 8 + nn)) * ND + j] = ftanh(t * 0.25f);
    }
}

// ---------------- fused GRU + (gat tail | decoder tail) ----------------
#define GRU_SMEM (128 * 136 * 2 + 128 * 72 * 2 + 128 * 72 * 4 + 8 * 64 * 4)
__global__ void __launch_bounds__(256, 2)
k_gru(const float* __restrict__ Wz, const float* __restrict__ Uz, const float* __restrict__ bz,
      const float* __restrict__ Wr, const float* __restrict__ Ur, const float* __restrict__ br,
      const float* __restrict__ Wc, const float* __restrict__ Uc, const float* __restrict__ bc,
      const float* __restrict__ Wgat, const float* __restrict__ asrc,
      const float* __restrict__ adst,
      const float* __restrict__ Wd1, const float* __restrict__ bd1,
      const float* __restrict__ Wd2, const float* __restrict__ bd2, int mode) {
    extern __shared__ __align__(16) char smraw[];
    __half* Xc = (__half*)smraw;                       // [128][136]: [m|h] -> [m|r*h] -> [h|r*h]
    __half* Wb = (__half*)(smraw + 128 * 136 * 2);     // [128][72]
    float* O = (float*)(smraw + 128 * 136 * 2 + 128 * 72 * 2);
    float* WA = O + 128 * 72;
    int tid = threadIdx.x;
    int nb0 = blockIdx.x * 128;

    stage_x16(g_m + (size_t)nb0 * ND, Xc, 136, 0);
    stage_x16(g_h + (size_t)nb0 * ND, Xc, 136, 64);
    {
        __half2 w0[16];
        wcat_ldg(Wz, Uz, w0);
        wcat_sts(Wb, w0);
    }
    __half2 wn[16];
    wcat_ldg(Wr, Ur, wn);
    __syncthreads();
    // ---- z ----
    wgemm<8, 136>(Xc, Wb, O);
    __syncthreads();
    wcat_sts(Wb, wn);
    wcat_ldg(Wc, Uc, wn);
    float zr[32];
#pragma unroll
    for (int p = 0; p < 8; p++) {
        int i = tid + p * 256;
        int row = i >> 4, c4 = (i & 15) * 4;
        float4 o = *reinterpret_cast<const float4*>(O + row * 72 + c4);
        zr[4 * p + 0] = fsig(o.x + __ldg(&bz[c4]));
        zr[4 * p + 1] = fsig(o.y + __ldg(&bz[c4 + 1]));
        zr[4 * p + 2] = fsig(o.z + __ldg(&bz[c4 + 2]));
        zr[4 * p + 3] = fsig(o.w + __ldg(&bz[c4 + 3]));
    }
    __syncthreads();
    // ---- r, r*h -> Xc right half ----
    wgemm<8, 136>(Xc, Wb, O);
    __syncthreads();
    wcat_sts(Wb, wn);
#pragma unroll
    for (int p = 0; p < 16; p++) {
        int i = tid + p * 256;
        int row = i >> 5, c2 = i & 31;
        float o0 = O[row * 72 + 2 * c2] + __ldg(&br[2 * c2]);
        float o1 = O[row * 72 + 2 * c2 + 1] + __ldg(&br[2 * c2 + 1]);
        __half2* hp = reinterpret_cast<__half2*>(Xc + row * 136 + 64 + 2 * c2);
        float2 hf = __half22float2(*hp);
        *hp = __floats2half2_rn(fsig(o0) * hf.x, fsig(o1) * hf.y);
    }
    __syncthreads();
    // ---- c + combine; new h -> g_h and Xc left half (fp16) ----
    wgemm<8, 136>(Xc, Wb, O);
    __syncthreads();
#pragma unroll
    for (int p = 0; p < 8; p++) {
        int i = tid + p * 256;
        int row = i >> 4, c4 = (i & 15) * 4;
        float4 o = *reinterpret_cast<const float4*>(O + row * 72 + c4);
        float* hp = g_h + (size_t)(nb0 + row) * ND + c4;
        float4 h = *reinterpret_cast<const float4*>(hp);
        float4 r;
        r.x = h.x + zr[4 * p + 0] * (ftanh(o.x + __ldg(&bc[c4])) - h.x);
        r.y = h.y + zr[4 * p + 1] * (ftanh(o.y + __ldg(&bc[c4 + 1])) - h.y);
        r.z = h.z + zr[4 * p + 2] * (ftanh(o.z + __ldg(&bc[c4 + 2])) - h.z);
        r.w = h.w + zr[4 * p + 3] * (ftanh(o.w + __ldg(&bc[c4 + 3])) - h.w);
        *reinterpret_cast<float4*>(hp) = r;
        __half2* xp = reinterpret_cast<__half2*>(Xc + row * 136 + c4);
        xp[0] = __floats2half2_rn(r.x, r.y);
        xp[1] = __floats2half2_rn(r.z, r.w);
    }
    if (mode == 0) {
        // next layer's GAT transform from resident h
        gat_tail<136>(Xc, Wb, O, WA, Wgat, asrc, adst, nb0);
    } else {
        // decoder from resident h
        __syncthreads();  // O reads done, Xc h-writes done
        stage_w16<64, 64>(Wd1, Wb);
        __syncthreads();
        wgemm<4, 136>(Xc, Wb, O);
        __syncthreads();
        int r = tid >> 1, hf = (tid & 1) * 32;
        float w = 0.f;
        const float* orow = O + r * 72 + hf;
#pragma unroll 8
        for (int j = 0; j < 32; j++)
            w += ftanh(orow[j] + __ldg(&bd1[hf + j])) * __ldg(&Wd2[hf + j]);
        w += __shfl_xor_sync(0xffffffffu, w, 1);
        if ((tid & 1) == 0) g_nodew[nb0 + r] = w + __ldg(&bd2[0]);
    }
}

// ---------------- fused normw + 10-iteration flow solver (persistent, grid barrier) ----------------
__global__ void __launch_bounds__(256)
k_flow_all(const int* __restrict__ adj, const float* __restrict__ demands,
           float* __restrict__ out_normw, float* bufA, float* bufB,
           float* __restrict__ out_flow, float* __restrict__ out_pflow,
           float* __restrict__ cost) {
    int n = blockIdx.x * 256 + threadIdx.x;
    int base = (n >> 14) << 14;
    int idxv[NK];
#pragma unroll
    for (int k = 0; k < NK; k++) idxv[k] = __ldg(&adj[(size_t)n * NK + k]);
    float dem = __ldg(&demands[n]);

    // ---- edge softmax (normw) ----
    float nw[NK];
    float mx = NEGV;
#pragma unroll
    for (int k = 0; k < NK; k++) {
        float s = (idxv[k] < NV) ? __ldg(&g_nodew[(size_t)base + idxv[k]]) : NEGV;
        nw[k] = s;
        mx = fmaxf(mx, s);
    }
    float sum = 0.0f;
#pragma unroll
    for (int k = 0; k < NK; k++) { nw[k] = fexp(nw[k] - mx); sum += nw[k]; }
    float inv = 1.0f / sum;
    float sn = 0.0f;
#pragma unroll
    for (int k = 0; k < NK; k++) {
        nw[k] *= inv;
        sn += nw[k] * nw[k];
    }
    {
        float4* o4 = reinterpret_cast<float4*>(out_normw + (size_t)n * NK);
#pragma unroll
        for (int k = 0; k < 4; k++)
            o4[k] = make_float4(nw[4 * k], nw[4 * k + 1], nw[4 * k + 2], nw[4 * k + 3]);
    }
    // ---- flow0 scatter ----
    float nf0 = fmaxf(-dem, 0.0f);
#pragma unroll
    for (int k = 0; k < NK; k++)
        if (idxv[k] < NV) atomicAdd(&bufA[base + idxv[k]], nw[k] * nf0);

    float* cur = bufA;
    float* nxt = bufB;
    int ev = 0;
#pragma unroll 1
    for (int it = 0; it < 10; it++) {
        // grid barrier
        __syncthreads();
        if (threadIdx.x == 0) {
            __threadfence();
            atomicAdd(&g_barc, 1u);
            unsigned tgt = (unsigned)(ev + 1) * gridDim.x;
            while (*((volatile unsigned*)&g_barc) < tgt) {}
            __threadfence();
        }
        __syncthreads();
        ev++;
        if (it == 9) break;
        float nf = fmaxf(__ldcg(&cur[n]) - dem, 0.0f);
        cur[n] = 0.0f;
        if (it == 8) {
            float4* o4 = reinterpret_cast<float4*>(out_pflow + (size_t)n * NK);
#pragma unroll
            for (int k = 0; k < 4; k++)
                o4[k] = make_float4(nw[4 * k] * nf, nw[4 * k + 1] * nf,
                                    nw[4 * k + 2] * nf, nw[4 * k + 3] * nf);
        }
#pragma unroll
        for (int k = 0; k < NK; k++)
            if (idxv[k] < NV) atomicAdd(&nxt[base + idxv[k]], nw[k] * nf);
        float* t = cur; cur = nxt; nxt = t;
    }
    float nf = fmaxf(__ldcg(&cur[n]) - dem, 0.0f);
    cur[n] = 0.0f;
    {
        float4* o4 = reinterpret_cast<float4*>(out_flow + (size_t)n * NK);
#pragma unroll
        for (int k = 0; k < 4; k++)
            o4[k] = make_float4(nw[4 * k] * nf, nw[4 * k + 1] * nf,
                                nw[4 * k + 2] * nf, nw[4 * k + 3] * nf);
    }
    float val = nf * nf * sn;
#pragma unroll
    for (int o = 16; o > 0; o >>= 1) val += __shfl_xor_sync(0xffffffffu, val, o);
    __shared__ float wsum[8];
    if ((threadIdx.x & 31) == 0) wsum[threadIdx.x >> 5] = val;
    __syncthreads();
    if (threadIdx.x == 0) {
        float t = 0.0f;
#pragma unroll
        for (int i = 0; i < 8; i++) t += wsum[i];
        atomicAdd(&cost[n >> 14], t);
    }
}

// ---------------- launch ----------------
extern "C" void kernel_launch(void* const* d_in, const int* in_sizes, int n_in,
                              void* d_out, int out_size) {
    const float* emb     = (const float*)d_in[0];
    const float* feat    = (const float*)d_in[1];
    const float* demands = (const float*)d_in[2];
    const int*   adj     = (const int*)d_in[3];
    int wb = (in_sizes[5] == 1) ? 6 : 5;
    const float* W_enc1 = (const float*)d_in[wb + 0];
    const float* b_enc1 = (const float*)d_in[wb + 1];
    const float* W_enc2 = (const float*)d_in[wb + 2];
    const float* b_enc2 = (const float*)d_in[wb + 3];
    const float* W_gat  = (const float*)d_in[wb + 4];
    const float* a_src  = (const float*)d_in[wb + 5];
    const float* a_dst  = (const float*)d_in[wb + 6];
    const float* W_z    = (const float*)d_in[wb + 7];
    const float* U_z    = (const float*)d_in[wb + 8];
    const float* b_z    = (const float*)d_in[wb + 9];
    const float* W_r    = (const float*)d_in[wb + 10];
    const float* U_r    = (const float*)d_in[wb + 11];
    const float* b_r    = (const float*)d_in[wb + 12];
    const float* W_c    = (const float*)d_in[wb + 13];
    const float* U_c    = (const float*)d_in[wb + 14];
    const float* b_c    = (const float*)d_in[wb + 15];
    const float* W_dec1 = (const float*)d_in[wb + 16];
    const float* b_dec1 = (const float*)d_in[wb + 17];
    const float* W_dec2 = (const float*)d_in[wb + 18];
    const float* b_dec2 = (const float*)d_in[wb + 19];

    float* out = (float*)d_out;
    float* out_flow  = out;                               // [B,V,K] f10
    float* out_cost  = out + (size_t)NB * NV * NK;        // [B]
    float* out_normw = out_cost + NB;                     // [B,V,K]
    float* out_pflow = out_normw + (size_t)NB * NV * NK;  // [B,V,K] f9

    float *pA, *pB;
    cudaGetSymbolAddress((void**)&pA, g_inflowA);
    cudaGetSymbolAddress((void**)&pB, g_inflowB);
    unsigned* pbar;
    cudaGetSymbolAddress((void**)&pbar, g_barc);

    cudaFuncSetAttribute(k_encoder, cudaFuncAttributeMaxDynamicSharedMemorySize, ENC_SMEM);
    cudaFuncSetAttribute(k_gru, cudaFuncAttributeMaxDynamicSharedMemorySize, GRU_SMEM);

    k_encoder<<<512, 256, ENC_SMEM>>>(emb, feat, W_enc1, b_enc1, W_enc2, b_enc2,
                                      W_gat, a_src, a_dst);
    k_gat_attn<<<NODES / 8, 256>>>(adj);
    k_gru<<<512, 256, GRU_SMEM>>>(W_z, U_z, b_z, W_r, U_r, b_r, W_c, U_c, b_c,
                                  W_gat, a_src, a_dst, W_dec1, b_dec1, W_dec2, b_dec2, 0);
    k_gat_attn<<<NODES / 8, 256>>>(adj);
    k_gru<<<512, 256, GRU_SMEM>>>(W_z, U_z, b_z, W_r, U_r, b_r, W_c, U_c, b_c,
                                  W_gat, a_src, a_dst, W_dec1, b_dec1, W_dec2, b_dec2, 1);

    cudaMemsetAsync(pbar, 0, sizeof(unsigned), 0);
    cudaMemsetAsync(out_cost, 0, NB * sizeof(float), 0);
    k_flow_all<<<256, 256>>>(adj, demands, out_normw, pA, pB, out_flow, out_pflow, out_cost);
}

// round 15
// speedup vs baseline: 3.0236x; 1.1301x over previous
#include <cuda_runtime.h>
#include <cuda_fp16.h>
#include <mma.h>
#include <math.h>

using namespace nvcuda;

#define NB 4
#define NV 16384
#define NK 16
#define NE 32
#define ND 64
#define NH 4
#define NL 2
#define NEGV (-1e9f)
#define NODES (NB * NV)

// ---------------- scratch ----------------
__device__ float g_h[NODES * ND];
__device__ __half g_t[(size_t)NODES * NH * ND];
__device__ float g_ssrc[NODES * NH];
__device__ float g_sdst[NODES * NH];
__device__ __half g_m16[NODES * ND];
__device__ float g_nodew[NODES];
__device__ float g_inflowA[NODES];
__device__ float g_inflowB[NODES];
__device__ unsigned g_barc;

// ---------------- fast math (HW approx) ----------------
__device__ __forceinline__ float ftanh(float x) {
    float r; asm("tanh.approx.f32 %0, %1;" : "=f"(r) : "f"(x)); return r;
}
__device__ __forceinline__ float fexp(float x) {
    float r; asm("ex2.approx.f32 %0, %1;" : "=f"(r) : "f"(x * 1.4426950408889634f)); return r;
}
__device__ __forceinline__ float fsig(float x) {
    float e; asm("ex2.approx.f32 %0, %1;" : "=f"(e) : "f"(-x * 1.4426950408889634f));
    float r; asm("rcp.approx.f32 %0, %1;" : "=f"(r) : "f"(1.0f + e)); return r;
}

// ---------------- staging helpers (256 threads) ----------------
__device__ __forceinline__ void stage_x16(const float* __restrict__ g, __half* xs, int ld, int coff) {
    for (int i = threadIdx.x; i < 128 * 16; i += 256) {
        int r = i >> 4, c4 = (i & 15) * 4;
        float4 v = __ldg(reinterpret_cast<const float4*>(g + (size_t)r * ND + c4));
        __half2* d = reinterpret_cast<__half2*>(xs + (size_t)r * ld + coff + c4);
        d[0] = __floats2half2_rn(v.x, v.y);
        d[1] = __floats2half2_rn(v.z, v.w);
    }
}
// copy 128 rows x 64 halves from g16 into xs[128][ld] at column offset coff
__device__ __forceinline__ void stage_h16(const __half* __restrict__ g16, __half* xs, int ld,
                                          int coff) {
    for (int i = threadIdx.x; i < 128 * 8; i += 256) {
        int r = i >> 3, c8 = (i & 7) * 8;
        uint4 v = __ldg(reinterpret_cast<const uint4*>(g16 + (size_t)r * ND + c8));
        *reinterpret_cast<uint4*>(xs + (size_t)r * ld + coff + c8) = v;
    }
}
template <int K, int KR>
__device__ __forceinline__ void stage_w16(const float* __restrict__ g, __half* ws) {
    for (int i = threadIdx.x; i < K * 32; i += 256) {
        int r = i >> 5, c2 = i & 31;
        float2 v = make_float2(0.f, 0.f);
        if (r < KR) v = __ldg(reinterpret_cast<const float2*>(g + r * 64 + 2 * c2));
        *reinterpret_cast<__half2*>(ws + r * 72 + 2 * c2) = __floats2half2_rn(v.x, v.y);
    }
}
__device__ __forceinline__ void wcat_ldg(const float* __restrict__ A, const float* __restrict__ B,
                                         __half2 wn[16]) {
#pragma unroll
    for (int p = 0; p < 16; p++) {
        int i = threadIdx.x + p * 256;
        int r = i >> 5, c2 = i & 31;
        const float* src = (r < 64) ? (A + r * 64 + 2 * c2) : (B + (r - 64) * 64 + 2 * c2);
        float2 v = __ldg(reinterpret_cast<const float2*>(src));
        wn[p] = __floats2half2_rn(v.x, v.y);
    }
}
__device__ __forceinline__ void wcat_sts(__half* ws, const __half2 wn[16]) {
#pragma unroll
    for (int p = 0; p < 16; p++) {
        int i = threadIdx.x + p * 256;
        int r = i >> 5, c2 = i & 31;
        *reinterpret_cast<__half2*>(ws + r * 72 + 2 * c2) = wn[p];
    }
}

// ---------------- WMMA GEMM (8 warps) ----------------
template <int KT, int ALD>
__device__ __forceinline__ void wgemm(const __half* Xs, const __half* Ws, float* Os) {
    int m0 = (threadIdx.x >> 5) * 16;
    wmma::fragment<wmma::accumulator, 16, 16, 16, float> c[4];
#pragma unroll
    for (int n = 0; n < 4; n++) wmma::fill_fragment(c[n], 0.0f);
#pragma unroll
    for (int kt = 0; kt < KT; kt++) {
        wmma::fragment<wmma::matrix_a, 16, 16, 16, __half, wmma::row_major> a;
        wmma::load_matrix_sync(a, Xs + m0 * ALD + kt * 16, ALD);
#pragma unroll
        for (int n = 0; n < 4; n++) {
            wmma::fragment<wmma::matrix_b, 16, 16, 16, __half, wmma::row_major> b;
            wmma::load_matrix_sync(b, Ws + kt * 16 * 72 + n * 16, 72);
            wmma::mma_sync(c[n], a, b, c[n]);
        }
    }
#pragma unroll
    for (int n = 0; n < 4; n++)
        wmma::store_matrix_sync(Os + m0 * 72 + n * 16, c[n], 72, wmma::mem_row_major);
}

// ---------------- GAT tail: scores + 4 head GEMMs from resident h tile ----------------
template <int ALD>
__device__ __forceinline__ void gat_tail(const __half* Xs, __half* Wb, float* O, float* WA,
                                         const float* __restrict__ Wgat,
                                         const float* __restrict__ asrc,
                                         const float* __restrict__ adst, int nb0) {
    int tid = threadIdx.x;
    {
        int hd = tid >> 6, k = tid & 63;
        const float* Wrow = Wgat + (size_t)hd * ND * ND + k * ND;
        float ss = 0.f, sd = 0.f;
#pragma unroll 8
        for (int c = 0; c < 64; c++) {
            float w = __ldg(&Wrow[c]);
            ss += w * __ldg(&asrc[hd * ND + c]);
            sd += w * __ldg(&adst[hd * ND + c]);
        }
        WA[(hd * 2 + 0) * 64 + k] = ss;
        WA[(hd * 2 + 1) * 64 + k] = sd;
    }
    __syncthreads();
    {
        int r = tid >> 1, hf = (tid & 1) * 32;
        float ssv[4] = {0.f, 0.f, 0.f, 0.f}, sdv[4] = {0.f, 0.f, 0.f, 0.f};
#pragma unroll 4
        for (int k = 0; k < 32; k++) {
            float x = __half2float(Xs[r * ALD + hf + k]);
#pragma unroll
            for (int hd = 0; hd < 4; hd++) {
                ssv[hd] += x * WA[(hd * 2 + 0) * 64 + hf + k];
                sdv[hd] += x * WA[(hd * 2 + 1) * 64 + hf + k];
            }
        }
#pragma unroll
        for (int hd = 0; hd < 4; hd++) {
            ssv[hd] += __shfl_xor_sync(0xffffffffu, ssv[hd], 1);
            sdv[hd] += __shfl_xor_sync(0xffffffffu, sdv[hd], 1);
        }
        if ((tid & 1) == 0) {
#pragma unroll
            for (int hd = 0; hd < 4; hd++) {
                g_ssrc[(size_t)(nb0 + r) * NH + hd] = ssv[hd];
                g_sdst[(size_t)(nb0 + r) * NH + hd] = sdv[hd];
            }
        }
    }
    for (int hd = 0; hd < NH; hd++) {
        __syncthreads();
        stage_w16<64, 64>(Wgat + (size_t)hd * ND * ND, Wb);
        __syncthreads();
        wgemm<4, ALD>(Xs, Wb, O);
        __syncthreads();
        for (int i = tid; i < 128 * 32; i += 256) {
            int row = i >> 5, c2 = i & 31;
            float o0 = O[row * 72 + 2 * c2], o1 = O[row * 72 + 2 * c2 + 1];
            *reinterpret_cast<__half2*>(g_t + ((size_t)(nb0 + row) * NH + hd) * ND + 2 * c2) =
                __floats2half2_rn(o0, o1);
        }
    }
}

// ---------------- encoder + layer-0 GAT transform ----------------
#define ENC_SMEM (128 * 56 * 2 + 128 * 72 * 2 + 64 * 72 * 2 + 128 * 72 * 4 + 8 * 64 * 4)
__global__ void __launch_bounds__(256)
k_encoder(const float* __restrict__ emb, const float* __restrict__ feat,
          const float* __restrict__ W1, const float* __restrict__ b1,
          const float* __restrict__ W2, const float* __restrict__ b2,
          const float* __restrict__ Wgat, const float* __restrict__ asrc,
          const float* __restrict__ adst) {
    extern __shared__ __align__(16) char smraw[];
    __half* X1 = (__half*)smraw;
    __half* X2 = (__half*)(smraw + 128 * 56 * 2);
    __half* Wb = (__half*)(smraw + 128 * 56 * 2 + 128 * 72 * 2);
    float* O = (float*)(smraw + 128 * 56 * 2 + 128 * 72 * 2 + 64 * 72 * 2);
    float* WA = O + 128 * 72;
    int tid = threadIdx.x;
    int nb0 = blockIdx.x * 128;

    __half2 w2r[8];
#pragma unroll
    for (int p = 0; p < 8; p++) {
        int i = tid + p * 256;
        int r = i >> 5, c2 = i & 31;
        float2 v = __ldg(reinterpret_cast<const float2*>(W2 + r * 64 + 2 * c2));
        w2r[p] = __floats2half2_rn(v.x, v.y);
    }
    {
        int r = tid >> 1, part = tid & 1;
        const float4* e4 = reinterpret_cast<const float4*>(emb + (size_t)(nb0 + r) * NE);
        __half2* row = reinterpret_cast<__half2*>(X1 + (size_t)r * 56);
#pragma unroll
        for (int c = part * 4; c < part * 4 + 4; c++) {
            float4 v = __ldg(e4 + c);
            row[2 * c] = __floats2half2_rn(v.x, v.y);
            row[2 * c + 1] = __floats2half2_rn(v.z, v.w);
        }
        if (part) {
            float2 fv = __ldg(reinterpret_cast<const float2*>(feat + (size_t)(nb0 + r) * 2));
            row[16] = __floats2half2_rn(fv.x, fv.y);
#pragma unroll
            for (int c2 = 17; c2 < 28; c2++) row[c2] = __floats2half2_rn(0.f, 0.f);
        }
    }
    stage_w16<48, 34>(W1, Wb);
    if (tid < 128) {
        g_inflowA[nb0 + tid] = 0.0f;
        g_inflowB[nb0 + tid] = 0.0f;
    }
    __syncthreads();
    wgemm<3, 56>(X1, Wb, O);
    __syncthreads();
#pragma unroll
    for (int p = 0; p < 8; p++) {
        int i = tid + p * 256;
        int r = i >> 5, c2 = i & 31;
        *reinterpret_cast<__half2*>(Wb + r * 72 + 2 * c2) = w2r[p];
    }
    for (int i = tid; i < 128 * 32; i += 256) {
        int row = i >> 5, c2 = i & 31;
        float o0 = O[row * 72 + 2 * c2] + __ldg(&b1[2 * c2]);
        float o1 = O[row * 72 + 2 * c2 + 1] + __ldg(&b1[2 * c2 + 1]);
        *reinterpret_cast<__half2*>(X2 + row * 72 + 2 * c2) =
            __floats2half2_rn(ftanh(o0), ftanh(o1));
    }
    __syncthreads();
    wgemm<4, 72>(X2, Wb, O);
    __syncthreads();
    for (int i = tid; i < 128 * 16; i += 256) {
        int row = i >> 4, c4 = (i & 15) * 4;
        float4 o = *reinterpret_cast<const float4*>(O + row * 72 + c4);
        float4 r;
        r.x = ftanh(o.x + __ldg(&b2[c4]));
        r.y = ftanh(o.y + __ldg(&b2[c4 + 1]));
        r.z = ftanh(o.z + __ldg(&b2[c4 + 2]));
        r.w = ftanh(o.w + __ldg(&b2[c4 + 3]));
        *reinterpret_cast<float4*>(g_h + (size_t)(nb0 + row) * ND + c4) = r;
        __half2* xp = reinterpret_cast<__half2*>(X2 + row * 72 + c4);
        xp[0] = __floats2half2_rn(r.x, r.y);
        xp[1] = __floats2half2_rn(r.z, r.w);
    }
    gat_tail<72>(X2, Wb, O, WA, Wgat, asrc, adst, nb0);
}

// ---------------- GAT attention: warp per node, smem broadcast, half2 accumulation ----------------
__global__ void __launch_bounds__(256)
k_gat_attn(const int* __restrict__ adj) {
    __shared__ float s_agg[8][NH][ND];
    __shared__ int s_idx[8][NK];
    __shared__ __half s_at[8][NK][NH];
    int w = threadIdx.x >> 5, lane = threadIdx.x & 31;
    int n = blockIdx.x * 8 + w;
    int b = n >> 14;
    int hd = lane >> 3;

    // ---- score phase (lanes 0..15) ----
    int idx = NV;
    if (lane < NK) idx = __ldg(&adj[(size_t)n * NK + lane]);
    bool valid = (idx < NV);
    float4 ss4 = __ldg(reinterpret_cast<const float4*>(&g_ssrc[(size_t)n * NH]));
    float s0 = NEGV, s1 = NEGV, s2 = NEGV, s3 = NEGV;
    if (valid) {
        float4 sd4 = __ldg(reinterpret_cast<const float4*>(&g_sdst[((size_t)(b << 14) + idx) * NH]));
        s0 = ss4.x + sd4.x; s1 = ss4.y + sd4.y; s2 = ss4.z + sd4.z; s3 = ss4.w + sd4.w;
    }
    float m0 = s0, m1 = s1, m2 = s2, m3 = s3;
#pragma unroll
    for (int o = 8; o > 0; o >>= 1) {
        m0 = fmaxf(m0, __shfl_xor_sync(0xffffffffu, m0, o));
        m1 = fmaxf(m1, __shfl_xor_sync(0xffffffffu, m1, o));
        m2 = fmaxf(m2, __shfl_xor_sync(0xffffffffu, m2, o));
        m3 = fmaxf(m3, __shfl_xor_sync(0xffffffffu, m3, o));
    }
    float e0 = fexp(s0 - m0), e1 = fexp(s1 - m1), e2 = fexp(s2 - m2), e3 = fexp(s3 - m3);
    float q0 = e0, q1 = e1, q2 = e2, q3 = e3;
#pragma unroll
    for (int o = 8; o > 0; o >>= 1) {
        q0 += __shfl_xor_sync(0xffffffffu, q0, o);
        q1 += __shfl_xor_sync(0xffffffffu, q1, o);
        q2 += __shfl_xor_sync(0xffffffffu, q2, o);
        q3 += __shfl_xor_sync(0xffffffffu, q3, o);
    }
    if (lane < NK) {
        s_idx[w][lane] = idx;
        __half2* ap = reinterpret_cast<__half2*>(&s_at[w][lane][0]);
        ap[0] = __floats2half2_rn(e0 / q0, e1 / q1);
        ap[1] = __floats2half2_rn(e2 / q2, e3 / q3);
    }
    __syncwarp();

    // ---- gather phase: HFMA2 accumulation, 512B block per neighbor ----
    __half2 acc[4];
#pragma unroll
    for (int q = 0; q < 4; q++) acc[q] = __floats2half2_rn(0.f, 0.f);
    const __half* tbase = g_t + (size_t)(b << 14) * (NH * ND);
#pragma unroll
    for (int k = 0; k < NK; k++) {
        int j = s_idx[w][k];
        if (j < NV) {
            __half2 ah = __half2half2(s_at[w][k][hd]);
            const uint4* tp = reinterpret_cast<const uint4*>(tbase + (size_t)j * (NH * ND));
            uint4 tv = __ldg(tp + lane);
            acc[0] = __hfma2(ah, *reinterpret_cast<__half2*>(&tv.x), acc[0]);
            acc[1] = __hfma2(ah, *reinterpret_cast<__half2*>(&tv.y), acc[1]);
            acc[2] = __hfma2(ah, *reinterpret_cast<__half2*>(&tv.z), acc[2]);
            acc[3] = __hfma2(ah, *reinterpret_cast<__half2*>(&tv.w), acc[3]);
        }
    }
    float2 f0 = __half22float2(acc[0]), f1 = __half22float2(acc[1]);
    float2 f2 = __half22float2(acc[2]), f3 = __half22float2(acc[3]);
    float* dst = &s_agg[w][hd][(lane & 7) * 8];
    *reinterpret_cast<float4*>(dst) = make_float4(f0.x, f0.y, f1.x, f1.y);
    *reinterpret_cast<float4*>(dst + 4) = make_float4(f2.x, f2.y, f3.x, f3.y);
    __syncthreads();
    for (int i = threadIdx.x; i < 8 * 32; i += 256) {
        int nn = i >> 5, c2 = i & 31;
        float t0 = s_agg[nn][0][2 * c2] + s_agg[nn][1][2 * c2] + s_agg[nn][2][2 * c2] +
                   s_agg[nn][3][2 * c2];
        float t1 = s_agg[nn][0][2 * c2 + 1] + s_agg[nn][1][2 * c2 + 1] + s_agg[nn][2][2 * c2 + 1] +
                   s_agg[nn][3][2 * c2 + 1];
        *reinterpret_cast<__half2*>(g_m16 + ((size_t)(blockIdx.x * 8 + nn)) * ND + 2 * c2) =
            __floats2half2_rn(ftanh(t0 * 0.25f), ftanh(t1 * 0.25f));
    }
}

// ---------------- fused GRU + (gat tail | decoder tail) ----------------
#define GRU_SMEM (128 * 136 * 2 + 128 * 72 * 2 + 128 * 72 * 4 + 8 * 64 * 4)
__global__ void __launch_bounds__(256, 2)
k_gru(const float* __restrict__ Wz, const float* __restrict__ Uz, const float* __restrict__ bz,
      const float* __restrict__ Wr, const float* __restrict__ Ur, const float* __restrict__ br,
      const float* __restrict__ Wc, const float* __restrict__ Uc, const float* __restrict__ bc,
      const float* __restrict__ Wgat, const float* __restrict__ asrc,
      const float* __restrict__ adst,
      const float* __restrict__ Wd1, const float* __restrict__ bd1,
      const float* __restrict__ Wd2, const float* __restrict__ bd2, int mode) {
    extern __shared__ __align__(16) char smraw[];
    __half* Xc = (__half*)smraw;                       // [128][136]: [m|h] -> [m|r*h] -> [h|r*h]
    __half* Wb = (__half*)(smraw + 128 * 136 * 2);
    float* O = (float*)(smraw + 128 * 136 * 2 + 128 * 72 * 2);
    float* WA = O + 128 * 72;
    int tid = threadIdx.x;
    int nb0 = blockIdx.x * 128;

    stage_h16(g_m16 + (size_t)nb0 * ND, Xc, 136, 0);
    stage_x16(g_h + (size_t)nb0 * ND, Xc, 136, 64);
    {
        __half2 w0[16];
        wcat_ldg(Wz, Uz, w0);
        wcat_sts(Wb, w0);
    }
    __half2 wn[16];
    wcat_ldg(Wr, Ur, wn);
    __syncthreads();
    // ---- z ----
    wgemm<8, 136>(Xc, Wb, O);
    __syncthreads();
    wcat_sts(Wb, wn);
    wcat_ldg(Wc, Uc, wn);
    float zr[32];
#pragma unroll
    for (int p = 0; p < 8; p++) {
        int i = tid + p * 256;
        int row = i >> 4, c4 = (i & 15) * 4;
        float4 o = *reinterpret_cast<const float4*>(O + row * 72 + c4);
        zr[4 * p + 0] = fsig(o.x + __ldg(&bz[c4]));
        zr[4 * p + 1] = fsig(o.y + __ldg(&bz[c4 + 1]));
        zr[4 * p + 2] = fsig(o.z + __ldg(&bz[c4 + 2]));
        zr[4 * p + 3] = fsig(o.w + __ldg(&bz[c4 + 3]));
    }
    __syncthreads();
    // ---- r, r*h -> Xc right half ----
    wgemm<8, 136>(Xc, Wb, O);
    __syncthreads();
    wcat_sts(Wb, wn);
#pragma unroll
    for (int p = 0; p < 16; p++) {
        int i = tid + p * 256;
        int row = i >> 5, c2 = i & 31;
        float o0 = O[row * 72 + 2 * c2] + __ldg(&br[2 * c2]);
        float o1 = O[row * 72 + 2 * c2 + 1] + __ldg(&br[2 * c2 + 1]);
        __half2* hp = reinterpret_cast<__half2*>(Xc + row * 136 + 64 + 2 * c2);
        float2 hf = __half22float2(*hp);
        *hp = __floats2half2_rn(fsig(o0) * hf.x, fsig(o1) * hf.y);
    }
    __syncthreads();
    // ---- c + combine; new h -> g_h and Xc left half ----
    wgemm<8, 136>(Xc, Wb, O);
    __syncthreads();
#pragma unroll
    for (int p = 0; p < 8; p++) {
        int i = tid + p * 256;
        int row = i >> 4, c4 = (i & 15) * 4;
        float4 o = *reinterpret_cast<const float4*>(O + row * 72 + c4);
        float* hp = g_h + (size_t)(nb0 + row) * ND + c4;
        float4 h = *reinterpret_cast<const float4*>(hp);
        float4 r;
        r.x = h.x + zr[4 * p + 0] * (ftanh(o.x + __ldg(&bc[c4])) - h.x);
        r.y = h.y + zr[4 * p + 1] * (ftanh(o.y + __ldg(&bc[c4 + 1])) - h.y);
        r.z = h.z + zr[4 * p + 2] * (ftanh(o.z + __ldg(&bc[c4 + 2])) - h.z);
        r.w = h.w + zr[4 * p + 3] * (ftanh(o.w + __ldg(&bc[c4 + 3])) - h.w);
        *reinterpret_cast<float4*>(hp) = r;
        __half2* xp = reinterpret_cast<__half2*>(Xc + row * 136 + c4);
        xp[0] = __floats2half2_rn(r.x, r.y);
        xp[1] = __floats2half2_rn(r.z, r.w);
    }
    if (mode == 0) {
        gat_tail<136>(Xc, Wb, O, WA, Wgat, asrc, adst, nb0);
    } else {
        __syncthreads();
        stage_w16<64, 64>(Wd1, Wb);
        __syncthreads();
        wgemm<4, 136>(Xc, Wb, O);
        __syncthreads();
        int r = tid >> 1, hf = (tid & 1) * 32;
        float w = 0.f;
        const float* orow = O + r * 72 + hf;
#pragma unroll 8
        for (int j = 0; j < 32; j++)
            w += ftanh(orow[j] + __ldg(&bd1[hf + j])) * __ldg(&Wd2[hf + j]);
        w += __shfl_xor_sync(0xffffffffu, w, 1);
        if ((tid & 1) == 0) g_nodew[nb0 + r] = w + __ldg(&bd2[0]);
    }
}

// ---------------- fused normw + 10-iteration flow solver ----------------
__global__ void __launch_bounds__(256)
k_flow_all(const int* __restrict__ adj, const float* __restrict__ demands,
           float* __restrict__ out_normw, float* bufA, float* bufB,
           float* __restrict__ out_flow, float* __restrict__ out_pflow,
           float* __restrict__ cost) {
    int n = blockIdx.x * 256 + threadIdx.x;
    int base = (n >> 14) << 14;
    int idxv[NK];
#pragma unroll
    for (int k = 0; k < NK; k++) idxv[k] = __ldg(&adj[(size_t)n * NK + k]);
    float dem = __ldg(&demands[n]);

    float nw[NK];
    float mx = NEGV;
#pragma unroll
    for (int k = 0; k < NK; k++) {
        float s = (idxv[k] < NV) ? __ldg(&g_nodew[(size_t)base + idxv[k]]) : NEGV;
        nw[k] = s;
        mx = fmaxf(mx, s);
    }
    float sum = 0.0f;
#pragma unroll
    for (int k = 0; k < NK; k++) { nw[k] = fexp(nw[k] - mx); sum += nw[k]; }
    float inv = 1.0f / sum;
    float sn = 0.0f;
#pragma unroll
    for (int k = 0; k < NK; k++) {
        nw[k] *= inv;
        sn += nw[k] * nw[k];
    }
    {
        float4* o4 = reinterpret_cast<float4*>(out_normw + (size_t)n * NK);
#pragma unroll
        for (int k = 0; k < 4; k++)
            o4[k] = make_float4(nw[4 * k], nw[4 * k + 1], nw[4 * k + 2], nw[4 * k + 3]);
    }
    float nf0 = fmaxf(-dem, 0.0f);
    if (nf0 > 0.0f) {
#pragma unroll
        for (int k = 0; k < NK; k++)
            if (idxv[k] < NV) atomicAdd(&bufA[base + idxv[k]], nw[k] * nf0);
    }

    float* cur = bufA;
    float* nxt = bufB;
    int ev = 0;
#pragma unroll 1
    for (int it = 0; it < 10; it++) {
        __syncthreads();
        if (threadIdx.x == 0) {
            __threadfence();
            atomicAdd(&g_barc, 1u);
            unsigned tgt = (unsigned)(ev + 1) * gridDim.x;
            while (*((volatile unsigned*)&g_barc) < tgt) {}
            __threadfence();
        }
        __syncthreads();
        ev++;
        if (it == 9) break;
        float nf = fmaxf(__ldcg(&cur[n]) - dem, 0.0f);
        cur[n] = 0.0f;
        if (it == 8) {
            float4* o4 = reinterpret_cast<float4*>(out_pflow + (size_t)n * NK);
#pragma unroll
            for (int k = 0; k < 4; k++)
                o4[k] = make_float4(nw[4 * k] * nf, nw[4 * k + 1] * nf,
                                    nw[4 * k + 2] * nf, nw[4 * k + 3] * nf);
        }
        if (nf > 0.0f) {
#pragma unroll
            for (int k = 0; k < NK; k++)
                if (idxv[k] < NV) atomicAdd(&nxt[base + idxv[k]], nw[k] * nf);
        }
        float* t = cur; cur = nxt; nxt = t;
    }
    float nf = fmaxf(__ldcg(&cur[n]) - dem, 0.0f);
    cur[n] = 0.0f;
    {
        float4* o4 = reinterpret_cast<float4*>(out_flow + (size_t)n * NK);
#pragma unroll
        for (int k = 0; k < 4; k++)
            o4[k] = make_float4(nw[4 * k] * nf, nw[4 * k + 1] * nf,
                                nw[4 * k + 2] * nf, nw[4 * k + 3] * nf);
    }
    float val = nf * nf * sn;
#pragma unroll
    for (int o = 16; o > 0; o >>= 1) val += __shfl_xor_sync(0xffffffffu, val, o);
    __shared__ float wsum[8];
    if ((threadIdx.x & 31) == 0) wsum[threadIdx.x >> 5] = val;
    __syncthreads();
    if (threadIdx.x == 0) {
        float t = 0.0f;
#pragma unroll
        for (int i = 0; i < 8; i++) t += wsum[i];
        atomicAdd(&cost[n >> 14], t);
    }
}

// ---------------- launch ----------------
extern "C" void kernel_launch(void* const* d_in, const int* in_sizes, int n_in,
                              void* d_out, int out_size) {
    const float* emb     = (const float*)d_in[0];
    const float* feat    = (const float*)d_in[1];
    const float* demands = (const float*)d_in[2];
    const int*   adj     = (const int*)d_in[3];
    int wb = (in_sizes[5] == 1) ? 6 : 5;
    const float* W_enc1 = (const float*)d_in[wb + 0];
    const float* b_enc1 = (const float*)d_in[wb + 1];
    const float* W_enc2 = (const float*)d_in[wb + 2];
    const float* b_enc2 = (const float*)d_in[wb + 3];
    const float* W_gat  = (const float*)d_in[wb + 4];
    const float* a_src  = (const float*)d_in[wb + 5];
    const float* a_dst  = (const float*)d_in[wb + 6];
    const float* W_z    = (const float*)d_in[wb + 7];
    const float* U_z    = (const float*)d_in[wb + 8];
    const float* b_z    = (const float*)d_in[wb + 9];
    const float* W_r    = (const float*)d_in[wb + 10];
    const float* U_r    = (const float*)d_in[wb + 11];
    const float* b_r    = (const float*)d_in[wb + 12];
    const float* W_c    = (const float*)d_in[wb + 13];
    const float* U_c    = (const float*)d_in[wb + 14];
    const float* b_c    = (const float*)d_in[wb + 15];
    const float* W_dec1 = (const float*)d_in[wb + 16];
    const float* b_dec1 = (const float*)d_in[wb + 17];
    const float* W_dec2 = (const float*)d_in[wb + 18];
    const float* b_dec2 = (const float*)d_in[wb + 19];

    float* out = (float*)d_out;
    float* out_flow  = out;                               // [B,V,K] f10
    float* out_cost  = out + (size_t)NB * NV * NK;        // [B]
    float* out_normw = out_cost + NB;                     // [B,V,K]
    float* out_pflow = out_normw + (size_t)NB * NV * NK;  // [B,V,K] f9

    float *pA, *pB;
    cudaGetSymbolAddress((void**)&pA, g_inflowA);
    cudaGetSymbolAddress((void**)&pB, g_inflowB);
    unsigned* pbar;
    cudaGetSymbolAddress((void**)&pbar, g_barc);

    cudaFuncSetAttribute(k_encoder, cudaFuncAttributeMaxDynamicSharedMemorySize, ENC_SMEM);
    cudaFuncSetAttribute(k_gru, cudaFuncAttributeMaxDynamicSharedMemorySize, GRU_SMEM);

    k_encoder<<<512, 256, ENC_SMEM>>>(emb, feat, W_enc1, b_enc1, W_enc2, b_enc2,
                                      W_gat, a_src, a_dst);
    k_gat_attn<<<NODES / 8, 256>>>(adj);
    k_gru<<<512, 256, GRU_SMEM>>>(W_z, U_z, b_z, W_r, U_r, b_r, W_c, U_c, b_c,
                                  W_gat, a_src, a_dst, W_dec1, b_dec1, W_dec2, b_dec2, 0);
    k_gat_attn<<<NODES / 8, 256>>>(adj);
    k_gru<<<512, 256, GRU_SMEM>>>(W_z, U_z, b_z, W_r, U_r, b_r, W_c, U_c, b_c,
                                  W_gat, a_src, a_dst, W_dec1, b_dec1, W_dec2, b_dec2, 1);

    cudaMemsetAsync(pbar, 0, sizeof(unsigned), 0);
    cudaMemsetAsync(out_cost, 0, NB * sizeof(float), 0);
    k_flow_all<<<256, 256>>>(adj, demands, out_normw, pA, pB, out_flow, out_pflow, out_cost);
}

// round 16
// speedup vs baseline: 3.0373x; 1.0045x over previous
#include <cuda_runtime.h>
#include <cuda_fp16.h>
#include <mma.h>
#include <math.h>

using namespace nvcuda;

#define NB 4
#define NV 16384
#define NK 16
#define NE 32
#define ND 64
#define NH 4
#define NL 2
#define NEGV (-1e9f)
#define NODES (NB * NV)

// ---------------- scratch ----------------
__device__ float g_h[NODES * ND];
__device__ __half g_h16[NODES * ND];
__device__ __half g_aggH[(size_t)NODES * NH * ND];
__device__ float g_ssrc[NODES * NH];
__device__ float g_sdst[NODES * NH];
__device__ __half g_m16[NODES * ND];
__device__ float g_nodew[NODES];
__device__ float g_inflowA[NODES];
__device__ float g_inflowB[NODES];
__device__ unsigned g_barc;

// ---------------- fast math (HW approx) ----------------
__device__ __forceinline__ float ftanh(float x) {
    float r; asm("tanh.approx.f32 %0, %1;" : "=f"(r) : "f"(x)); return r;
}
__device__ __forceinline__ float fexp(float x) {
    float r; asm("ex2.approx.f32 %0, %1;" : "=f"(r) : "f"(x * 1.4426950408889634f)); return r;
}
__device__ __forceinline__ float fsig(float x) {
    float e; asm("ex2.approx.f32 %0, %1;" : "=f"(e) : "f"(-x * 1.4426950408889634f));
    float r; asm("rcp.approx.f32 %0, %1;" : "=f"(r) : "f"(1.0f + e)); return r;
}

// ---------------- staging helpers (256 threads) ----------------
__device__ __forceinline__ void stage_x16(const float* __restrict__ g, __half* xs, int ld, int coff) {
    for (int i = threadIdx.x; i < 128 * 16; i += 256) {
        int r = i >> 4, c4 = (i & 15) * 4;
        float4 v = __ldg(reinterpret_cast<const float4*>(g + (size_t)r * ND + c4));
        __half2* d = reinterpret_cast<__half2*>(xs + (size_t)r * ld + coff + c4);
        d[0] = __floats2half2_rn(v.x, v.y);
        d[1] = __floats2half2_rn(v.z, v.w);
    }
}
__device__ __forceinline__ void stage_h16(const __half* __restrict__ g16, __half* xs, int ld,
                                          int coff) {
    for (int i = threadIdx.x; i < 128 * 8; i += 256) {
        int r = i >> 3, c8 = (i & 7) * 8;
        uint4 v = __ldg(reinterpret_cast<const uint4*>(g16 + (size_t)r * ND + c8));
        *reinterpret_cast<uint4*>(xs + (size_t)r * ld + coff + c8) = v;
    }
}
template <int K, int KR>
__device__ __forceinline__ void stage_w16(const float* __restrict__ g, __half* ws) {
    for (int i = threadIdx.x; i < K * 32; i += 256) {
        int r = i >> 5, c2 = i & 31;
        float2 v = make_float2(0.f, 0.f);
        if (r < KR) v = __ldg(reinterpret_cast<const float2*>(g + r * 64 + 2 * c2));
        *reinterpret_cast<__half2*>(ws + r * 72 + 2 * c2) = __floats2half2_rn(v.x, v.y);
    }
}
__device__ __forceinline__ void wcat_ldg(const float* __restrict__ A, const float* __restrict__ B,
                                         __half2 wn[16]) {
#pragma unroll
    for (int p = 0; p < 16; p++) {
        int i = threadIdx.x + p * 256;
        int r = i >> 5, c2 = i & 31;
        const float* src = (r < 64) ? (A + r * 64 + 2 * c2) : (B + (r - 64) * 64 + 2 * c2);
        float2 v = __ldg(reinterpret_cast<const float2*>(src));
        wn[p] = __floats2half2_rn(v.x, v.y);
    }
}
__device__ __forceinline__ void wcat_sts(__half* ws, const __half2 wn[16]) {
#pragma unroll
    for (int p = 0; p < 16; p++) {
        int i = threadIdx.x + p * 256;
        int r = i >> 5, c2 = i & 31;
        *reinterpret_cast<__half2*>(ws + r * 72 + 2 * c2) = wn[p];
    }
}

// ---------------- WMMA GEMM (8 warps); ACC: accumulate into existing O ----------------
template <int KT, int ALD, bool ACC>
__device__ __forceinline__ void wgemm(const __half* Xs, const __half* Ws, float* Os) {
    int m0 = (threadIdx.x >> 5) * 16;
    wmma::fragment<wmma::accumulator, 16, 16, 16, float> c[4];
#pragma unroll
    for (int n = 0; n < 4; n++) {
        if (ACC)
            wmma::load_matrix_sync(c[n], Os + m0 * 72 + n * 16, 72, wmma::mem_row_major);
        else
            wmma::fill_fragment(c[n], 0.0f);
    }
#pragma unroll
    for (int kt = 0; kt < KT; kt++) {
        wmma::fragment<wmma::matrix_a, 16, 16, 16, __half, wmma::row_major> a;
        wmma::load_matrix_sync(a, Xs + m0 * ALD + kt * 16, ALD);
#pragma unroll
        for (int n = 0; n < 4; n++) {
            wmma::fragment<wmma::matrix_b, 16, 16, 16, __half, wmma::row_major> b;
            wmma::load_matrix_sync(b, Ws + kt * 16 * 72 + n * 16, 72);
            wmma::mma_sync(c[n], a, b, c[n]);
        }
    }
#pragma unroll
    for (int n = 0; n < 4; n++)
        wmma::store_matrix_sync(Os + m0 * 72 + n * 16, c[n], 72, wmma::mem_row_major);
}

// ---------------- score tail: WA trick scores + h16 store (no GEMMs) ----------------
template <int ALD>
__device__ __forceinline__ void score_tail(const __half* Xs, float* WA,
                                           const float* __restrict__ Wgat,
                                           const float* __restrict__ asrc,
                                           const float* __restrict__ adst, int nb0) {
    int tid = threadIdx.x;
    {
        int hd = tid >> 6, k = tid & 63;
        const float* Wrow = Wgat + (size_t)hd * ND * ND + k * ND;
        float ss = 0.f, sd = 0.f;
#pragma unroll 8
        for (int c = 0; c < 64; c++) {
            float w = __ldg(&Wrow[c]);
            ss += w * __ldg(&asrc[hd * ND + c]);
            sd += w * __ldg(&adst[hd * ND + c]);
        }
        WA[(hd * 2 + 0) * 64 + k] = ss;
        WA[(hd * 2 + 1) * 64 + k] = sd;
    }
    __syncthreads();  // WA ready; also covers h-writes into Xs
    {
        int r = tid >> 1, hf = (tid & 1) * 32;
        float ssv[4] = {0.f, 0.f, 0.f, 0.f}, sdv[4] = {0.f, 0.f, 0.f, 0.f};
#pragma unroll 4
        for (int k = 0; k < 32; k++) {
            float x = __half2float(Xs[r * ALD + hf + k]);
#pragma unroll
            for (int hd = 0; hd < 4; hd++) {
                ssv[hd] += x * WA[(hd * 2 + 0) * 64 + hf + k];
                sdv[hd] += x * WA[(hd * 2 + 1) * 64 + hf + k];
            }
        }
#pragma unroll
        for (int hd = 0; hd < 4; hd++) {
            ssv[hd] += __shfl_xor_sync(0xffffffffu, ssv[hd], 1);
            sdv[hd] += __shfl_xor_sync(0xffffffffu, sdv[hd], 1);
        }
        if ((tid & 1) == 0) {
#pragma unroll
            for (int hd = 0; hd < 4; hd++) {
                g_ssrc[(size_t)(nb0 + r) * NH + hd] = ssv[hd];
                g_sdst[(size_t)(nb0 + r) * NH + hd] = sdv[hd];
            }
        }
    }
    for (int i = tid; i < 128 * 8; i += 256) {
        int r = i >> 3, c8 = (i & 7) * 8;
        *reinterpret_cast<uint4*>(g_h16 + (size_t)(nb0 + r) * ND + c8) =
            *reinterpret_cast<const uint4*>(Xs + r * ALD + c8);
    }
}

// ---------------- encoder + layer-0 scores/h16 ----------------
#define ENC_SMEM (128 * 56 * 2 + 128 * 72 * 2 + 64 * 72 * 2 + 128 * 72 * 4 + 8 * 64 * 4)
__global__ void __launch_bounds__(256)
k_encoder(const float* __restrict__ emb, const float* __restrict__ feat,
          const float* __restrict__ W1, const float* __restrict__ b1,
          const float* __restrict__ W2, const float* __restrict__ b2,
          const float* __restrict__ Wgat, const float* __restrict__ asrc,
          const float* __restrict__ adst) {
    extern __shared__ __align__(16) char smraw[];
    __half* X1 = (__half*)smraw;
    __half* X2 = (__half*)(smraw + 128 * 56 * 2);
    __half* Wb = (__half*)(smraw + 128 * 56 * 2 + 128 * 72 * 2);
    float* O = (float*)(smraw + 128 * 56 * 2 + 128 * 72 * 2 + 64 * 72 * 2);
    float* WA = O + 128 * 72;
    int tid = threadIdx.x;
    int nb0 = blockIdx.x * 128;

    __half2 w2r[8];
#pragma unroll
    for (int p = 0; p < 8; p++) {
        int i = tid + p * 256;
        int r = i >> 5, c2 = i & 31;
        float2 v = __ldg(reinterpret_cast<const float2*>(W2 + r * 64 + 2 * c2));
        w2r[p] = __floats2half2_rn(v.x, v.y);
    }
    {
        int r = tid >> 1, part = tid & 1;
        const float4* e4 = reinterpret_cast<const float4*>(emb + (size_t)(nb0 + r) * NE);
        __half2* row = reinterpret_cast<__half2*>(X1 + (size_t)r * 56);
#pragma unroll
        for (int c = part * 4; c < part * 4 + 4; c++) {
            float4 v = __ldg(e4 + c);
            row[2 * c] = __floats2half2_rn(v.x, v.y);
            row[2 * c + 1] = __floats2half2_rn(v.z, v.w);
        }
        if (part) {
            float2 fv = __ldg(reinterpret_cast<const float2*>(feat + (size_t)(nb0 + r) * 2));
            row[16] = __floats2half2_rn(fv.x, fv.y);
#pragma unroll
            for (int c2 = 17; c2 < 28; c2++) row[c2] = __floats2half2_rn(0.f, 0.f);
        }
    }
    stage_w16<48, 34>(W1, Wb);
    if (tid < 128) {
        g_inflowA[nb0 + tid] = 0.0f;
        g_inflowB[nb0 + tid] = 0.0f;
    }
    __syncthreads();
    wgemm<3, 56, false>(X1, Wb, O);
    __syncthreads();
#pragma unroll
    for (int p = 0; p < 8; p++) {
        int i = tid + p * 256;
        int r = i >> 5, c2 = i & 31;
        *reinterpret_cast<__half2*>(Wb + r * 72 + 2 * c2) = w2r[p];
    }
    for (int i = tid; i < 128 * 32; i += 256) {
        int row = i >> 5, c2 = i & 31;
        float o0 = O[row * 72 + 2 * c2] + __ldg(&b1[2 * c2]);
        float o1 = O[row * 72 + 2 * c2 + 1] + __ldg(&b1[2 * c2 + 1]);
        *reinterpret_cast<__half2*>(X2 + row * 72 + 2 * c2) =
            __floats2half2_rn(ftanh(o0), ftanh(o1));
    }
    __syncthreads();
    wgemm<4, 72, false>(X2, Wb, O);
    __syncthreads();
    for (int i = tid; i < 128 * 16; i += 256) {
        int row = i >> 4, c4 = (i & 15) * 4;
        float4 o = *reinterpret_cast<const float4*>(O + row * 72 + c4);
        float4 r;
        r.x = ftanh(o.x + __ldg(&b2[c4]));
        r.y = ftanh(o.y + __ldg(&b2[c4 + 1]));
        r.z = ftanh(o.z + __ldg(&b2[c4 + 2]));
        r.w = ftanh(o.w + __ldg(&b2[c4 + 3]));
        *reinterpret_cast<float4*>(g_h + (size_t)(nb0 + row) * ND + c4) = r;
        __half2* xp = reinterpret_cast<__half2*>(X2 + row * 72 + c4);
        xp[0] = __floats2half2_rn(r.x, r.y);
        xp[1] = __floats2half2_rn(r.z, r.w);
    }
    score_tail<72>(X2, WA, Wgat, asrc, adst, nb0);
}

// ---------------- GAT attention: gather h (128B/neighbor), 4 head-weighted sums ----------------
__global__ void __launch_bounds__(256)
k_gat_attn(const int* __restrict__ adj) {
    __shared__ int s_idx[8][NK];
    __shared__ __half s_at[8][NK][NH];
    int w = threadIdx.x >> 5, lane = threadIdx.x & 31;
    int n = blockIdx.x * 8 + w;
    int b = n >> 14;

    // ---- score phase (lanes 0..15) ----
    int idx = NV;
    if (lane < NK) idx = __ldg(&adj[(size_t)n * NK + lane]);
    bool valid = (idx < NV);
    float4 ss4 = __ldg(reinterpret_cast<const float4*>(&g_ssrc[(size_t)n * NH]));
    float s0 = NEGV, s1 = NEGV, s2 = NEGV, s3 = NEGV;
    if (valid) {
        float4 sd4 = __ldg(reinterpret_cast<const float4*>(&g_sdst[((size_t)(b << 14) + idx) * NH]));
        s0 = ss4.x + sd4.x; s1 = ss4.y + sd4.y; s2 = ss4.z + sd4.z; s3 = ss4.w + sd4.w;
    }
    float m0 = s0, m1 = s1, m2 = s2, m3 = s3;
#pragma unroll
    for (int o = 8; o > 0; o >>= 1) {
        m0 = fmaxf(m0, __shfl_xor_sync(0xffffffffu, m0, o));
        m1 = fmaxf(m1, __shfl_xor_sync(0xffffffffu, m1, o));
        m2 = fmaxf(m2, __shfl_xor_sync(0xffffffffu, m2, o));
        m3 = fmaxf(m3, __shfl_xor_sync(0xffffffffu, m3, o));
    }
    float e0 = fexp(s0 - m0), e1 = fexp(s1 - m1), e2 = fexp(s2 - m2), e3 = fexp(s3 - m3);
    float q0 = e0, q1 = e1, q2 = e2, q3 = e3;
#pragma unroll
    for (int o = 8; o > 0; o >>= 1) {
        q0 += __shfl_xor_sync(0xffffffffu, q0, o);
        q1 += __shfl_xor_sync(0xffffffffu, q1, o);
        q2 += __shfl_xor_sync(0xffffffffu, q2, o);
        q3 += __shfl_xor_sync(0xffffffffu, q3, o);
    }
    if (lane < NK) {
        s_idx[w][lane] = idx;
        __half2* ap = reinterpret_cast<__half2*>(&s_at[w][lane][0]);
        ap[0] = __floats2half2_rn(e0 / q0, e1 / q1);
        ap[1] = __floats2half2_rn(e2 / q2, e3 / q3);
    }
    __syncwarp();

    // ---- gather h16: lane covers cols 2*lane..2*lane+1, accumulates 4 head sums ----
    __half2 acc[4];
#pragma unroll
    for (int q = 0; q < 4; q++) acc[q] = __floats2half2_rn(0.f, 0.f);
    const __half* hbase = g_h16 + (size_t)(b << 14) * ND;
#pragma unroll
    for (int k = 0; k < NK; k++) {
        int j = s_idx[w][k];
        if (j < NV) {
            const __half2* ap = reinterpret_cast<const __half2*>(&s_at[w][k][0]);
            __half2 a01 = ap[0], a23 = ap[1];
            __half2 hv = __ldg(reinterpret_cast<const __half2*>(hbase + (size_t)j * ND) + lane);
            acc[0] = __hfma2(__half2half2(__low2half(a01)), hv, acc[0]);
            acc[1] = __hfma2(__half2half2(__high2half(a01)), hv, acc[1]);
            acc[2] = __hfma2(__half2half2(__low2half(a23)), hv, acc[2]);
            acc[3] = __hfma2(__half2half2(__high2half(a23)), hv, acc[3]);
        }
    }
    __half* obase = g_aggH + (size_t)n * (NH * ND);
#pragma unroll
    for (int hd = 0; hd < 4; hd++)
        *reinterpret_cast<__half2*>(obase + hd * ND + 2 * lane) = acc[hd];
}

// ---------------- m GEMM: m = tanh(0.25 * aggHcat @ [W0;W1;W2;W3]) ----------------
#define MG_SMEM (128 * 136 * 2 + 128 * 72 * 2 + 128 * 72 * 4)
__global__ void __launch_bounds__(256)
k_mgemm(const float* __restrict__ Wgat) {
    extern __shared__ __align__(16) char smraw[];
    __half* Xt = (__half*)smraw;                     // [128][136]
    __half* Wb = (__half*)(smraw + 128 * 136 * 2);   // [128][72]
    float* O = (float*)(smraw + 128 * 136 * 2 + 128 * 72 * 2);
    int tid = threadIdx.x;
    int nb0 = blockIdx.x * 128;

    // pass 1: heads 0,1
    for (int i = tid; i < 128 * 16; i += 256) {
        int r = i >> 4, c8 = (i & 15) * 8;
        uint4 v = __ldg(reinterpret_cast<const uint4*>(g_aggH + (size_t)(nb0 + r) * 256 + c8));
        *reinterpret_cast<uint4*>(Xt + r * 136 + c8) = v;
    }
    {
        __half2 w0[16];
        wcat_ldg(Wgat, Wgat + 64 * 64, w0);
        wcat_sts(Wb, w0);
    }
    __half2 wn[16];
    wcat_ldg(Wgat + 2 * 64 * 64, Wgat + 3 * 64 * 64, wn);  // prefetch pass-2 W
    __syncthreads();
    wgemm<8, 136, false>(Xt, Wb, O);
    __syncthreads();
    // pass 2: heads 2,3
    for (int i = tid; i < 128 * 16; i += 256) {
        int r = i >> 4, c8 = (i & 15) * 8;
        uint4 v = __ldg(reinterpret_cast<const uint4*>(g_aggH + (size_t)(nb0 + r) * 256 + 128 + c8));
        *reinterpret_cast<uint4*>(Xt + r * 136 + c8) = v;
    }
    wcat_sts(Wb, wn);
    __syncthreads();
    wgemm<8, 136, true>(Xt, Wb, O);
    __syncthreads();
    for (int i = tid; i < 128 * 32; i += 256) {
        int row = i >> 5, c2 = i & 31;
        float t0 = O[row * 72 + 2 * c2] * 0.25f;
        float t1 = O[row * 72 + 2 * c2 + 1] * 0.25f;
        *reinterpret_cast<__half2*>(g_m16 + (size_t)(nb0 + row) * ND + 2 * c2) =
            __floats2half2_rn(ftanh(t0), ftanh(t1));
    }
}

// ---------------- fused GRU + (score tail | decoder tail) ----------------
#define GRU_SMEM (128 * 136 * 2 + 128 * 72 * 2 + 128 * 72 * 4 + 8 * 64 * 4)
__global__ void __launch_bounds__(256, 2)
k_gru(const float* __restrict__ Wz, const float* __restrict__ Uz, const float* __restrict__ bz,
      const float* __restrict__ Wr, const float* __restrict__ Ur, const float* __restrict__ br,
      const float* __restrict__ Wc, const float* __restrict__ Uc, const float* __restrict__ bc,
      const float* __restrict__ Wgat, const float* __restrict__ asrc,
      const float* __restrict__ adst,
      const float* __restrict__ Wd1, const float* __restrict__ bd1,
      const float* __restrict__ Wd2, const float* __restrict__ bd2, int mode) {
    extern __shared__ __align__(16) char smraw[];
    __half* Xc = (__half*)smraw;                       // [128][136]: [m|h] -> [m|r*h] -> [h|r*h]
    __half* Wb = (__half*)(smraw + 128 * 136 * 2);
    float* O = (float*)(smraw + 128 * 136 * 2 + 128 * 72 * 2);
    float* WA = O + 128 * 72;
    int tid = threadIdx.x;
    int nb0 = blockIdx.x * 128;

    stage_h16(g_m16 + (size_t)nb0 * ND, Xc, 136, 0);
    stage_x16(g_h + (size_t)nb0 * ND, Xc, 136, 64);
    {
        __half2 w0[16];
        wcat_ldg(Wz, Uz, w0);
        wcat_sts(Wb, w0);
    }
    __half2 wn[16];
    wcat_ldg(Wr, Ur, wn);
    __syncthreads();
    // ---- z ----
    wgemm<8, 136, false>(Xc, Wb, O);
    __syncthreads();
    wcat_sts(Wb, wn);
    wcat_ldg(Wc, Uc, wn);
    float zr[32];
#pragma unroll
    for (int p = 0; p < 8; p++) {
        int i = tid + p * 256;
        int row = i >> 4, c4 = (i & 15) * 4;
        float4 o = *reinterpret_cast<const float4*>(O + row * 72 + c4);
        zr[4 * p + 0] = fsig(o.x + __ldg(&bz[c4]));
        zr[4 * p + 1] = fsig(o.y + __ldg(&bz[c4 + 1]));
        zr[4 * p + 2] = fsig(o.z + __ldg(&bz[c4 + 2]));
        zr[4 * p + 3] = fsig(o.w + __ldg(&bz[c4 + 3]));
    }
    __syncthreads();
    // ---- r, r*h -> Xc right half ----
    wgemm<8, 136, false>(Xc, Wb, O);
    __syncthreads();
    wcat_sts(Wb, wn);
#pragma unroll
    for (int p = 0; p < 16; p++) {
        int i = tid + p * 256;
        int row = i >> 5, c2 = i & 31;
        float o0 = O[row * 72 + 2 * c2] + __ldg(&br[2 * c2]);
        float o1 = O[row * 72 + 2 * c2 + 1] + __ldg(&br[2 * c2 + 1]);
        __half2* hp = reinterpret_cast<__half2*>(Xc + row * 136 + 64 + 2 * c2);
        float2 hf = __half22float2(*hp);
        *hp = __floats2half2_rn(fsig(o0) * hf.x, fsig(o1) * hf.y);
    }
    __syncthreads();
    // ---- c + combine; new h -> g_h and Xc left half ----
    wgemm<8, 136, false>(Xc, Wb, O);
    __syncthreads();
#pragma unroll
    for (int p = 0; p < 8; p++) {
        int i = tid + p * 256;
        int row = i >> 4, c4 = (i & 15) * 4;
        float4 o = *reinterpret_cast<const float4*>(O + row * 72 + c4);
        float* hp = g_h + (size_t)(nb0 + row) * ND + c4;
        float4 h = *reinterpret_cast<const float4*>(hp);
        float4 r;
        r.x = h.x + zr[4 * p + 0] * (ftanh(o.x + __ldg(&bc[c4])) - h.x);
        r.y = h.y + zr[4 * p + 1] * (ftanh(o.y + __ldg(&bc[c4 + 1])) - h.y);
        r.z = h.z + zr[4 * p + 2] * (ftanh(o.z + __ldg(&bc[c4 + 2])) - h.z);
        r.w = h.w + zr[4 * p + 3] * (ftanh(o.w + __ldg(&bc[c4 + 3])) - h.w);
        *reinterpret_cast<float4*>(hp) = r;
        __half2* xp = reinterpret_cast<__half2*>(Xc + row * 136 + c4);
        xp[0] = __floats2half2_rn(r.x, r.y);
        xp[1] = __floats2half2_rn(r.z, r.w);
    }
    if (mode == 0) {
        score_tail<136>(Xc, WA, Wgat, asrc, adst, nb0);
    } else {
        __syncthreads();
        stage_w16<64, 64>(Wd1, Wb);
        __syncthreads();
        wgemm<4, 136, false>(Xc, Wb, O);
        __syncthreads();
        int r = tid >> 1, hf = (tid & 1) * 32;
        float w = 0.f;
        const float* orow = O + r * 72 + hf;
#pragma unroll 8
        for (int j = 0; j < 32; j++)
            w += ftanh(orow[j] + __ldg(&bd1[hf + j])) * __ldg(&Wd2[hf + j]);
        w += __shfl_xor_sync(0xffffffffu, w, 1);
        if ((tid & 1) == 0) g_nodew[nb0 + r] = w + __ldg(&bd2[0]);
    }
}

// ---------------- fused normw + 10-iteration flow solver ----------------
__global__ void __launch_bounds__(256)
k_flow_all(const int* __restrict__ adj, const float* __restrict__ demands,
           float* __restrict__ out_normw, float* bufA, float* bufB,
           float* __restrict__ out_flow, float* __restrict__ out_pflow,
           float* __restrict__ cost) {
    int n = blockIdx.x * 256 + threadIdx.x;
    int base = (n >> 14) << 14;
    int idxv[NK];
#pragma unroll
    for (int k = 0; k < NK; k++) idxv[k] = __ldg(&adj[(size_t)n * NK + k]);
    float dem = __ldg(&demands[n]);

    float nw[NK];
    float mx = NEGV;
#pragma unroll
    for (int k = 0; k < NK; k++) {
        float s = (idxv[k] < NV) ? __ldg(&g_nodew[(size_t)base + idxv[k]]) : NEGV;
        nw[k] = s;
        mx = fmaxf(mx, s);
    }
    float sum = 0.0f;
#pragma unroll
    for (int k = 0; k < NK; k++) { nw[k] = fexp(nw[k] - mx); sum += nw[k]; }
    float inv = 1.0f / sum;
    float sn = 0.0f;
#pragma unroll
    for (int k = 0; k < NK; k++) {
        nw[k] *= inv;
        sn += nw[k] * nw[k];
    }
    {
        float4* o4 = reinterpret_cast<float4*>(out_normw + (size_t)n * NK);
#pragma unroll
        for (int k = 0; k < 4; k++)
            o4[k] = make_float4(nw[4 * k], nw[4 * k + 1], nw[4 * k + 2], nw[4 * k + 3]);
    }
    float nf0 = fmaxf(-dem, 0.0f);
    if (nf0 > 0.0f) {
#pragma unroll
        for (int k = 0; k < NK; k++)
            if (idxv[k] < NV) atomicAdd(&bufA[base + idxv[k]], nw[k] * nf0);
    }

    float* cur = bufA;
    float* nxt = bufB;
    int ev = 0;
#pragma unroll 1
    for (int it = 0; it < 10; it++) {
        __syncthreads();
        if (threadIdx.x == 0) {
            __threadfence();
            atomicAdd(&g_barc, 1u);
            unsigned tgt = (unsigned)(ev + 1) * gridDim.x;
            while (*((volatile unsigned*)&g_barc) < tgt) {}
            __threadfence();
        }
        __syncthreads();
        ev++;
        if (it == 9) break;
        float nf = fmaxf(__ldcg(&cur[n]) - dem, 0.0f);
        cur[n] = 0.0f;
        if (it == 8) {
            float4* o4 = reinterpret_cast<float4*>(out_pflow + (size_t)n * NK);
#pragma unroll
            for (int k = 0; k < 4; k++)
                o4[k] = make_float4(nw[4 * k] * nf, nw[4 * k + 1] * nf,
                                    nw[4 * k + 2] * nf, nw[4 * k + 3] * nf);
        }
        if (nf > 0.0f) {
#pragma unroll
            for (int k = 0; k < NK; k++)
                if (idxv[k] < NV) atomicAdd(&nxt[base + idxv[k]], nw[k] * nf);
        }
        float* t = cur; cur = nxt; nxt = t;
    }
    float nf = fmaxf(__ldcg(&cur[n]) - dem, 0.0f);
    cur[n] = 0.0f;
    {
        float4* o4 = reinterpret_cast<float4*>(out_flow + (size_t)n * NK);
#pragma unroll
        for (int k = 0; k < 4; k++)
            o4[k] = make_float4(nw[4 * k] * nf, nw[4 * k + 1] * nf,
                                nw[4 * k + 2] * nf, nw[4 * k + 3] * nf);
    }
    float val = nf * nf * sn;
#pragma unroll
    for (int o = 16; o > 0; o >>= 1) val += __shfl_xor_sync(0xffffffffu, val, o);
    __shared__ float wsum[8];
    if ((threadIdx.x & 31) == 0) wsum[threadIdx.x >> 5] = val;
    __syncthreads();
    if (threadIdx.x == 0) {
        float t = 0.0f;
#pragma unroll
        for (int i = 0; i < 8; i++) t += wsum[i];
        atomicAdd(&cost[n >> 14], t);
    }
}

// ---------------- launch ----------------
extern "C" void kernel_launch(void* const* d_in, const int* in_sizes, int n_in,
                              void* d_out, int out_size) {
    const float* emb     = (const float*)d_in[0];
    const float* feat    = (const float*)d_in[1];
    const float* demands = (const float*)d_in[2];
    const int*   adj     = (const int*)d_in[3];
    int wb = (in_sizes[5] == 1) ? 6 : 5;
    const float* W_enc1 = (const float*)d_in[wb + 0];
    const float* b_enc1 = (const float*)d_in[wb + 1];
    const float* W_enc2 = (const float*)d_in[wb + 2];
    const float* b_enc2 = (const float*)d_in[wb + 3];
    const float* W_gat  = (const float*)d_in[wb + 4];
    const float* a_src  = (const float*)d_in[wb + 5];
    const float* a_dst  = (const float*)d_in[wb + 6];
    const float* W_z    = (const float*)d_in[wb + 7];
    const float* U_z    = (const float*)d_in[wb + 8];
    const float* b_z    = (const float*)d_in[wb + 9];
    const float* W_r    = (const float*)d_in[wb + 10];
    const float* U_r    = (const float*)d_in[wb + 11];
    const float* b_r    = (const float*)d_in[wb + 12];
    const float* W_c    = (const float*)d_in[wb + 13];
    const float* U_c    = (const float*)d_in[wb + 14];
    const float* b_c    = (const float*)d_in[wb + 15];
    const float* W_dec1 = (const float*)d_in[wb + 16];
    const float* b_dec1 = (const float*)d_in[wb + 17];
    const float* W_dec2 = (const float*)d_in[wb + 18];
    const float* b_dec2 = (const float*)d_in[wb + 19];

    float* out = (float*)d_out;
    float* out_flow  = out;                               // [B,V,K] f10
    float* out_cost  = out + (size_t)NB * NV * NK;        // [B]
    float* out_normw = out_cost + NB;                     // [B,V,K]
    float* out_pflow = out_normw + (size_t)NB * NV * NK;  // [B,V,K] f9

    float *pA, *pB;
    cudaGetSymbolAddress((void**)&pA, g_inflowA);
    cudaGetSymbolAddress((void**)&pB, g_inflowB);
    unsigned* pbar;
    cudaGetSymbolAddress((void**)&pbar, g_barc);

    cudaFuncSetAttribute(k_encoder, cudaFuncAttributeMaxDynamicSharedMemorySize, ENC_SMEM);
    cudaFuncSetAttribute(k_mgemm, cudaFuncAttributeMaxDynamicSharedMemorySize, MG_SMEM);
    cudaFuncSetAttribute(k_gru, cudaFuncAttributeMaxDynamicSharedMemorySize, GRU_SMEM);

    k_encoder<<<512, 256, ENC_SMEM>>>(emb, feat, W_enc1, b_enc1, W_enc2, b_enc2,
                                      W_gat, a_src, a_dst);
    k_gat_attn<<<NODES / 8, 256>>>(adj);
    k_mgemm<<<512, 256, MG_SMEM>>>(W_gat);
    k_gru<<<512, 256, GRU_SMEM>>>(W_z, U_z, b_z, W_r, U_r, b_r, W_c, U_c, b_c,
                                  W_gat, a_src, a_dst, W_dec1, b_dec1, W_dec2, b_dec2, 0);
    k_gat_attn<<<NODES / 8, 256>>>(adj);
    k_mgemm<<<512, 256, MG_SMEM>>>(W_gat);
    k_gru<<<512, 256, GRU_SMEM>>>(W_z, U_z, b_z, W_r, U_r, b_r, W_c, U_c, b_c,
                                  W_gat, a_src, a_dst, W_dec1, b_dec1, W_dec2, b_dec2, 1);

    cudaMemsetAsync(pbar, 0, sizeof(unsigned), 0);
    cudaMemsetAsync(out_cost, 0, NB * sizeof(float), 0);
    k_flow_all<<<256, 256>>>(adj, demands, out_normw, pA, pB, out_flow, out_pflow, out_cost);
}

// round 17
// speedup vs baseline: 3.7438x; 1.2326x over previous
#include <cuda_runtime.h>
#include <cuda_fp16.h>
#include <mma.h>
#include <math.h>

using namespace nvcuda;

#define NB 4
#define NV 16384
#define NK 16
#define NE 32
#define ND 64
#define NH 4
#define NL 2
#define NEGV (-1e9f)
#define NODES (NB * NV)

// ---------------- scratch ----------------
__device__ float g_h[NODES * ND];
__device__ __half g_h16[NODES * ND];
__device__ __half g_aggH[(size_t)NODES * NH * ND];
__device__ float g_ssrc[NODES * NH];
__device__ float g_sdst[NODES * NH];
__device__ float g_nodew[NODES];
__device__ float g_inflowA[NODES];
__device__ float g_inflowB[NODES];
__device__ float g_WA[8 * 64];
__device__ unsigned g_barc;

// ---------------- fast math (HW approx) ----------------
__device__ __forceinline__ float ftanh(float x) {
    float r; asm("tanh.approx.f32 %0, %1;" : "=f"(r) : "f"(x)); return r;
}
__device__ __forceinline__ float fexp(float x) {
    float r; asm("ex2.approx.f32 %0, %1;" : "=f"(r) : "f"(x * 1.4426950408889634f)); return r;
}
__device__ __forceinline__ float fsig(float x) {
    float e; asm("ex2.approx.f32 %0, %1;" : "=f"(e) : "f"(-x * 1.4426950408889634f));
    float r; asm("rcp.approx.f32 %0, %1;" : "=f"(r) : "f"(1.0f + e)); return r;
}

// ---------------- staging helpers (256 threads) ----------------
__device__ __forceinline__ void stage_x16(const float* __restrict__ g, __half* xs, int ld, int coff) {
    for (int i = threadIdx.x; i < 128 * 16; i += 256) {
        int r = i >> 4, c4 = (i & 15) * 4;
        float4 v = __ldg(reinterpret_cast<const float4*>(g + (size_t)r * ND + c4));
        __half2* d = reinterpret_cast<__half2*>(xs + (size_t)r * ld + coff + c4);
        d[0] = __floats2half2_rn(v.x, v.y);
        d[1] = __floats2half2_rn(v.z, v.w);
    }
}
template <int K, int KR>
__device__ __forceinline__ void stage_w16(const float* __restrict__ g, __half* ws) {
    for (int i = threadIdx.x; i < K * 32; i += 256) {
        int r = i >> 5, c2 = i & 31;
        float2 v = make_float2(0.f, 0.f);
        if (r < KR) v = __ldg(reinterpret_cast<const float2*>(g + r * 64 + 2 * c2));
        *reinterpret_cast<__half2*>(ws + r * 72 + 2 * c2) = __floats2half2_rn(v.x, v.y);
    }
}
__device__ __forceinline__ void wcat_ldg(const float* __restrict__ A, const float* __restrict__ B,
                                         __half2 wn[16]) {
#pragma unroll
    for (int p = 0; p < 16; p++) {
        int i = threadIdx.x + p * 256;
        int r = i >> 5, c2 = i & 31;
        const float* src = (r < 64) ? (A + r * 64 + 2 * c2) : (B + (r - 64) * 64 + 2 * c2);
        float2 v = __ldg(reinterpret_cast<const float2*>(src));
        wn[p] = __floats2half2_rn(v.x, v.y);
    }
}
__device__ __forceinline__ void wcat_sts(__half* ws, const __half2 wn[16]) {
#pragma unroll
    for (int p = 0; p < 16; p++) {
        int i = threadIdx.x + p * 256;
        int r = i >> 5, c2 = i & 31;
        *reinterpret_cast<__half2*>(ws + r * 72 + 2 * c2) = wn[p];
    }
}

// ---------------- WMMA GEMM (8 warps); ACC: accumulate into existing O ----------------
template <int KT, int ALD, bool ACC>
__device__ __forceinline__ void wgemm(const __half* Xs, const __half* Ws, float* Os) {
    int m0 = (threadIdx.x >> 5) * 16;
    wmma::fragment<wmma::accumulator, 16, 16, 16, float> c[4];
#pragma unroll
    for (int n = 0; n < 4; n++) {
        if (ACC)
            wmma::load_matrix_sync(c[n], Os + m0 * 72 + n * 16, 72, wmma::mem_row_major);
        else
            wmma::fill_fragment(c[n], 0.0f);
    }
#pragma unroll
    for (int kt = 0; kt < KT; kt++) {
        wmma::fragment<wmma::matrix_a, 16, 16, 16, __half, wmma::row_major> a;
        wmma::load_matrix_sync(a, Xs + m0 * ALD + kt * 16, ALD);
#pragma unroll
        for (int n = 0; n < 4; n++) {
            wmma::fragment<wmma::matrix_b, 16, 16, 16, __half, wmma::row_major> b;
            wmma::load_matrix_sync(b, Ws + kt * 16 * 72 + n * 16, 72);
            wmma::mma_sync(c[n], a, b, c[n]);
        }
    }
#pragma unroll
    for (int n = 0; n < 4; n++)
        wmma::store_matrix_sync(Os + m0 * 72 + n * 16, c[n], 72, wmma::mem_row_major);
}

// ---------------- WA precompute (one block): WA[hd][0/1][k] = Wgat[hd][k]·a{src,dst}[hd] ----------------
__global__ void k_wa(const float* __restrict__ Wgat, const float* __restrict__ asrc,
                     const float* __restrict__ adst) {
    int hd = threadIdx.x >> 6, k = threadIdx.x & 63;
    const float* Wrow = Wgat + (size_t)hd * ND * ND + k * ND;
    float ss = 0.f, sd = 0.f;
#pragma unroll 8
    for (int c = 0; c < 64; c++) {
        float w = __ldg(&Wrow[c]);
        ss += w * __ldg(&asrc[hd * ND + c]);
        sd += w * __ldg(&adst[hd * ND + c]);
    }
    g_WA[(hd * 2 + 0) * 64 + k] = ss;
    g_WA[(hd * 2 + 1) * 64 + k] = sd;
}

// ---------------- score tail: scores from g_WA + h16 store ----------------
template <int ALD>
__device__ __forceinline__ void score_tail(const __half* Xs, float* WA, int nb0) {
    int tid = threadIdx.x;
    for (int i = tid; i < 512; i += 256) WA[i] = __ldg(&g_WA[i]);
    __syncthreads();  // WA ready; also covers h-writes into Xs
    {
        int r = tid >> 1, hf = (tid & 1) * 32;
        float ssv[4] = {0.f, 0.f, 0.f, 0.f}, sdv[4] = {0.f, 0.f, 0.f, 0.f};
#pragma unroll 4
        for (int k = 0; k < 32; k++) {
            float x = __half2float(Xs[r * ALD + hf + k]);
#pragma unroll
            for (int hd = 0; hd < 4; hd++) {
                ssv[hd] += x * WA[(hd * 2 + 0) * 64 + hf + k];
                sdv[hd] += x * WA[(hd * 2 + 1) * 64 + hf + k];
            }
        }
#pragma unroll
        for (int hd = 0; hd < 4; hd++) {
            ssv[hd] += __shfl_xor_sync(0xffffffffu, ssv[hd], 1);
            sdv[hd] += __shfl_xor_sync(0xffffffffu, sdv[hd], 1);
        }
        if ((tid & 1) == 0) {
#pragma unroll
            for (int hd = 0; hd < 4; hd++) {
                g_ssrc[(size_t)(nb0 + r) * NH + hd] = ssv[hd];
                g_sdst[(size_t)(nb0 + r) * NH + hd] = sdv[hd];
            }
        }
    }
    for (int i = tid; i < 128 * 8; i += 256) {
        int r = i >> 3, c8 = (i & 7) * 8;
        *reinterpret_cast<uint4*>(g_h16 + (size_t)(nb0 + r) * ND + c8) =
            *reinterpret_cast<const uint4*>(Xs + r * ALD + c8);
    }
}

// ---------------- encoder + layer-0 scores/h16 ----------------
#define ENC_SMEM (128 * 56 * 2 + 128 * 72 * 2 + 64 * 72 * 2 + 128 * 72 * 4 + 8 * 64 * 4)
__global__ void __launch_bounds__(256)
k_encoder(const float* __restrict__ emb, const float* __restrict__ feat,
          const float* __restrict__ W1, const float* __restrict__ b1,
          const float* __restrict__ W2, const float* __restrict__ b2) {
    extern __shared__ __align__(16) char smraw[];
    __half* X1 = (__half*)smraw;
    __half* X2 = (__half*)(smraw + 128 * 56 * 2);
    __half* Wb = (__half*)(smraw + 128 * 56 * 2 + 128 * 72 * 2);
    float* O = (float*)(smraw + 128 * 56 * 2 + 128 * 72 * 2 + 64 * 72 * 2);
    float* WA = O + 128 * 72;
    int tid = threadIdx.x;
    int nb0 = blockIdx.x * 128;

    __half2 w2r[8];
#pragma unroll
    for (int p = 0; p < 8; p++) {
        int i = tid + p * 256;
        int r = i >> 5, c2 = i & 31;
        float2 v = __ldg(reinterpret_cast<const float2*>(W2 + r * 64 + 2 * c2));
        w2r[p] = __floats2half2_rn(v.x, v.y);
    }
    {
        int r = tid >> 1, part = tid & 1;
        const float4* e4 = reinterpret_cast<const float4*>(emb + (size_t)(nb0 + r) * NE);
        __half2* row = reinterpret_cast<__half2*>(X1 + (size_t)r * 56);
#pragma unroll
        for (int c = part * 4; c < part * 4 + 4; c++) {
            float4 v = __ldg(e4 + c);
            row[2 * c] = __floats2half2_rn(v.x, v.y);
            row[2 * c + 1] = __floats2half2_rn(v.z, v.w);
        }
        if (part) {
            float2 fv = __ldg(reinterpret_cast<const float2*>(feat + (size_t)(nb0 + r) * 2));
            row[16] = __floats2half2_rn(fv.x, fv.y);
#pragma unroll
            for (int c2 = 17; c2 < 28; c2++) row[c2] = __floats2half2_rn(0.f, 0.f);
        }
    }
    stage_w16<48, 34>(W1, Wb);
    if (tid < 128) {
        g_inflowA[nb0 + tid] = 0.0f;
        g_inflowB[nb0 + tid] = 0.0f;
    }
    __syncthreads();
    wgemm<3, 56, false>(X1, Wb, O);
    __syncthreads();
#pragma unroll
    for (int p = 0; p < 8; p++) {
        int i = tid + p * 256;
        int r = i >> 5, c2 = i & 31;
        *reinterpret_cast<__half2*>(Wb + r * 72 + 2 * c2) = w2r[p];
    }
    for (int i = tid; i < 128 * 32; i += 256) {
        int row = i >> 5, c2 = i & 31;
        float o0 = O[row * 72 + 2 * c2] + __ldg(&b1[2 * c2]);
        float o1 = O[row * 72 + 2 * c2 + 1] + __ldg(&b1[2 * c2 + 1]);
        *reinterpret_cast<__half2*>(X2 + row * 72 + 2 * c2) =
            __floats2half2_rn(ftanh(o0), ftanh(o1));
    }
    __syncthreads();
    wgemm<4, 72, false>(X2, Wb, O);
    __syncthreads();
    for (int i = tid; i < 128 * 16; i += 256) {
        int row = i >> 4, c4 = (i & 15) * 4;
        float4 o = *reinterpret_cast<const float4*>(O + row * 72 + c4);
        float4 r;
        r.x = ftanh(o.x + __ldg(&b2[c4]));
        r.y = ftanh(o.y + __ldg(&b2[c4 + 1]));
        r.z = ftanh(o.z + __ldg(&b2[c4 + 2]));
        r.w = ftanh(o.w + __ldg(&b2[c4 + 3]));
        *reinterpret_cast<float4*>(g_h + (size_t)(nb0 + row) * ND + c4) = r;
        __half2* xp = reinterpret_cast<__half2*>(X2 + row * 72 + c4);
        xp[0] = __floats2half2_rn(r.x, r.y);
        xp[1] = __floats2half2_rn(r.z, r.w);
    }
    score_tail<72>(X2, WA, nb0);
}

// ---------------- GAT attention: gather h (128B/neighbor), 4 head-weighted sums ----------------
__global__ void __launch_bounds__(256)
k_gat_attn(const int* __restrict__ adj) {
    __shared__ int s_idx[8][NK];
    __shared__ __half s_at[8][NK][NH];
    int w = threadIdx.x >> 5, lane = threadIdx.x & 31;
    int n = blockIdx.x * 8 + w;
    int b = n >> 14;

    int idx = NV;
    if (lane < NK) idx = __ldg(&adj[(size_t)n * NK + lane]);
    bool valid = (idx < NV);
    float4 ss4 = __ldg(reinterpret_cast<const float4*>(&g_ssrc[(size_t)n * NH]));
    float s0 = NEGV, s1 = NEGV, s2 = NEGV, s3 = NEGV;
    if (valid) {
        float4 sd4 = __ldg(reinterpret_cast<const float4*>(&g_sdst[((size_t)(b << 14) + idx) * NH]));
        s0 = ss4.x + sd4.x; s1 = ss4.y + sd4.y; s2 = ss4.z + sd4.z; s3 = ss4.w + sd4.w;
    }
    float m0 = s0, m1 = s1, m2 = s2, m3 = s3;
#pragma unroll
    for (int o = 8; o > 0; o >>= 1) {
        m0 = fmaxf(m0, __shfl_xor_sync(0xffffffffu, m0, o));
        m1 = fmaxf(m1, __shfl_xor_sync(0xffffffffu, m1, o));
        m2 = fmaxf(m2, __shfl_xor_sync(0xffffffffu, m2, o));
        m3 = fmaxf(m3, __shfl_xor_sync(0xffffffffu, m3, o));
    }
    float e0 = fexp(s0 - m0), e1 = fexp(s1 - m1), e2 = fexp(s2 - m2), e3 = fexp(s3 - m3);
    float q0 = e0, q1 = e1, q2 = e2, q3 = e3;
#pragma unroll
    for (int o = 8; o > 0; o >>= 1) {
        q0 += __shfl_xor_sync(0xffffffffu, q0, o);
        q1 += __shfl_xor_sync(0xffffffffu, q1, o);
        q2 += __shfl_xor_sync(0xffffffffu, q2, o);
        q3 += __shfl_xor_sync(0xffffffffu, q3, o);
    }
    if (lane < NK) {
        s_idx[w][lane] = idx;
        __half2* ap = reinterpret_cast<__half2*>(&s_at[w][lane][0]);
        ap[0] = __floats2half2_rn(e0 / q0, e1 / q1);
        ap[1] = __floats2half2_rn(e2 / q2, e3 / q3);
    }
    __syncwarp();

    __half2 acc[4];
#pragma unroll
    for (int q = 0; q < 4; q++) acc[q] = __floats2half2_rn(0.f, 0.f);
    const __half* hbase = g_h16 + (size_t)(b << 14) * ND;
#pragma unroll
    for (int k = 0; k < NK; k++) {
        int j = s_idx[w][k];
        if (j < NV) {
            const __half2* ap = reinterpret_cast<const __half2*>(&s_at[w][k][0]);
            __half2 a01 = ap[0], a23 = ap[1];
            __half2 hv = __ldg(reinterpret_cast<const __half2*>(hbase + (size_t)j * ND) + lane);
            acc[0] = __hfma2(__half2half2(__low2half(a01)), hv, acc[0]);
            acc[1] = __hfma2(__half2half2(__high2half(a01)), hv, acc[1]);
            acc[2] = __hfma2(__half2half2(__low2half(a23)), hv, acc[2]);
            acc[3] = __hfma2(__half2half2(__high2half(a23)), hv, acc[3]);
        }
    }
    __half* obase = g_aggH + (size_t)n * (NH * ND);
#pragma unroll
    for (int hd = 0; hd < 4; hd++)
        *reinterpret_cast<__half2*>(obase + hd * ND + 2 * lane) = acc[hd];
}

// ---------------- fused m-GEMM + GRU + (score tail | decoder tail) ----------------
#define GRU_SMEM (128 * 136 * 2 + 128 * 72 * 2 + 128 * 72 * 4 + 8 * 64 * 4)
__global__ void __launch_bounds__(256, 2)
k_gru(const float* __restrict__ Wz, const float* __restrict__ Uz, const float* __restrict__ bz,
      const float* __restrict__ Wr, const float* __restrict__ Ur, const float* __restrict__ br,
      const float* __restrict__ Wc, const float* __restrict__ Uc, const float* __restrict__ bc,
      const float* __restrict__ Wgat,
      const float* __restrict__ Wd1, const float* __restrict__ bd1,
      const float* __restrict__ Wd2, const float* __restrict__ bd2, int mode) {
    extern __shared__ __align__(16) char smraw[];
    __half* Xc = (__half*)smraw;                       // [128][136]
    __half* Wb = (__half*)(smraw + 128 * 136 * 2);
    float* O = (float*)(smraw + 128 * 136 * 2 + 128 * 72 * 2);
    float* WA = O + 128 * 72;
    int tid = threadIdx.x;
    int nb0 = blockIdx.x * 128;

    // ==== m-GEMM prologue: m = tanh(0.25 * aggH @ [W0;W1;W2;W3]) ====
    // pass 1: heads 0,1
    for (int i = tid; i < 128 * 16; i += 256) {
        int r = i >> 4, c8 = (i & 15) * 8;
        uint4 v = __ldg(reinterpret_cast<const uint4*>(g_aggH + (size_t)(nb0 + r) * 256 + c8));
        *reinterpret_cast<uint4*>(Xc + r * 136 + c8) = v;
    }
    {
        __half2 w0[16];
        wcat_ldg(Wgat, Wgat + 64 * 64, w0);
        wcat_sts(Wb, w0);
    }
    __half2 wn[16];
    wcat_ldg(Wgat + 2 * 64 * 64, Wgat + 3 * 64 * 64, wn);
    __syncthreads();
    wgemm<8, 136, false>(Xc, Wb, O);
    __syncthreads();
    // pass 2: heads 2,3
    for (int i = tid; i < 128 * 16; i += 256) {
        int r = i >> 4, c8 = (i & 15) * 8;
        uint4 v = __ldg(reinterpret_cast<const uint4*>(g_aggH + (size_t)(nb0 + r) * 256 + 128 + c8));
        *reinterpret_cast<uint4*>(Xc + r * 136 + c8) = v;
    }
    wcat_sts(Wb, wn);
    wcat_ldg(Wz, Uz, wn);
    __syncthreads();
    wgemm<8, 136, true>(Xc, Wb, O);
    __syncthreads();
    // m -> Xc cols 0..63 (fp16); h -> cols 64..127
    for (int i = tid; i < 128 * 32; i += 256) {
        int row = i >> 5, c2 = i & 31;
        float t0 = O[row * 72 + 2 * c2] * 0.25f;
        float t1 = O[row * 72 + 2 * c2 + 1] * 0.25f;
        *reinterpret_cast<__half2*>(Xc + row * 136 + 2 * c2) =
            __floats2half2_rn(ftanh(t0), ftanh(t1));
    }
    stage_x16(g_h + (size_t)nb0 * ND, Xc, 136, 64);
    wcat_sts(Wb, wn);       // Wz|Uz
    wcat_ldg(Wr, Ur, wn);
    __syncthreads();
    // ==== z ====
    wgemm<8, 136, false>(Xc, Wb, O);
    __syncthreads();
    wcat_sts(Wb, wn);       // Wr|Ur
    wcat_ldg(Wc, Uc, wn);
    float zr[32];
#pragma unroll
    for (int p = 0; p < 8; p++) {
        int i = tid + p * 256;
        int row = i >> 4, c4 = (i & 15) * 4;
        float4 o = *reinterpret_cast<const float4*>(O + row * 72 + c4);
        zr[4 * p + 0] = fsig(o.x + __ldg(&bz[c4]));
        zr[4 * p + 1] = fsig(o.y + __ldg(&bz[c4 + 1]));
        zr[4 * p + 2] = fsig(o.z + __ldg(&bz[c4 + 2]));
        zr[4 * p + 3] = fsig(o.w + __ldg(&bz[c4 + 3]));
    }
    __syncthreads();
    // ==== r, r*h -> Xc right half ====
    wgemm<8, 136, false>(Xc, Wb, O);
    __syncthreads();
    wcat_sts(Wb, wn);       // Wc|Uc
#pragma unroll
    for (int p = 0; p < 16; p++) {
        int i = tid + p * 256;
        int row = i >> 5, c2 = i & 31;
        float o0 = O[row * 72 + 2 * c2] + __ldg(&br[2 * c2]);
        float o1 = O[row * 72 + 2 * c2 + 1] + __ldg(&br[2 * c2 + 1]);
        __half2* hp = reinterpret_cast<__half2*>(Xc + row * 136 + 64 + 2 * c2);
        float2 hf = __half22float2(*hp);
        *hp = __floats2half2_rn(fsig(o0) * hf.x, fsig(o1) * hf.y);
    }
    __syncthreads();
    // ==== c + combine; new h -> g_h and Xc left half ====
    wgemm<8, 136, false>(Xc, Wb, O);
    __syncthreads();
#pragma unroll
    for (int p = 0; p < 8; p++) {
        int i = tid + p * 256;
        int row = i >> 4, c4 = (i & 15) * 4;
        float4 o = *reinterpret_cast<const float4*>(O + row * 72 + c4);
        float* hp = g_h + (size_t)(nb0 + row) * ND + c4;
        float4 h = *reinterpret_cast<const float4*>(hp);
        float4 r;
        r.x = h.x + zr[4 * p + 0] * (ftanh(o.x + __ldg(&bc[c4])) - h.x);
        r.y = h.y + zr[4 * p + 1] * (ftanh(o.y + __ldg(&bc[c4 + 1])) - h.y);
        r.z = h.z + zr[4 * p + 2] * (ftanh(o.z + __ldg(&bc[c4 + 2])) - h.z);
        r.w = h.w + zr[4 * p + 3] * (ftanh(o.w + __ldg(&bc[c4 + 3])) - h.w);
        *reinterpret_cast<float4*>(hp) = r;
        __half2* xp = reinterpret_cast<__half2*>(Xc + row * 136 + c4);
        xp[0] = __floats2half2_rn(r.x, r.y);
        xp[1] = __floats2half2_rn(r.z, r.w);
    }
    if (mode == 0) {
        score_tail<136>(Xc, WA, nb0);
    } else {
        __syncthreads();
        stage_w16<64, 64>(Wd1, Wb);
        __syncthreads();
        wgemm<4, 136, false>(Xc, Wb, O);
        __syncthreads();
        int r = tid >> 1, hf = (tid & 1) * 32;
        float w = 0.f;
        const float* orow = O + r * 72 + hf;
#pragma unroll 8
        for (int j = 0; j < 32; j++)
            w += ftanh(orow[j] + __ldg(&bd1[hf + j])) * __ldg(&Wd2[hf + j]);
        w += __shfl_xor_sync(0xffffffffu, w, 1);
        if ((tid & 1) == 0) g_nodew[nb0 + r] = w + __ldg(&bd2[0]);
    }
}

// ---------------- fused normw + 10-iteration flow solver ----------------
__global__ void __launch_bounds__(256)
k_flow_all(const int* __restrict__ adj, const float* __restrict__ demands,
           float* __restrict__ out_normw, float* bufA, float* bufB,
           float* __restrict__ out_flow, float* __restrict__ out_pflow,
           float* __restrict__ cost) {
    int n = blockIdx.x * 256 + threadIdx.x;
    int base = (n >> 14) << 14;
    int idxv[NK];
#pragma unroll
    for (int k = 0; k < NK; k++) idxv[k] = __ldg(&adj[(size_t)n * NK + k]);
    float dem = __ldg(&demands[n]);

    float nw[NK];
    float mx = NEGV;
#pragma unroll
    for (int k = 0; k < NK; k++) {
        float s = (idxv[k] < NV) ? __ldg(&g_nodew[(size_t)base + idxv[k]]) : NEGV;
        nw[k] = s;
        mx = fmaxf(mx, s);
    }
    float sum = 0.0f;
#pragma unroll
    for (int k = 0; k < NK; k++) { nw[k] = fexp(nw[k] - mx); sum += nw[k]; }
    float inv = 1.0f / sum;
    float sn = 0.0f;
#pragma unroll
    for (int k = 0; k < NK; k++) {
        nw[k] *= inv;
        sn += nw[k] * nw[k];
    }
    {
        float4* o4 = reinterpret_cast<float4*>(out_normw + (size_t)n * NK);
#pragma unroll
        for (int k = 0; k < 4; k++)
            o4[k] = make_float4(nw[4 * k], nw[4 * k + 1], nw[4 * k + 2], nw[4 * k + 3]);
    }
    float nf0 = fmaxf(-dem, 0.0f);
    if (nf0 > 0.0f) {
#pragma unroll
        for (int k = 0; k < NK; k++)
            if (idxv[k] < NV) atomicAdd(&bufA[base + idxv[k]], nw[k] * nf0);
    }

    float* cur = bufA;
    float* nxt = bufB;
    int ev = 0;
#pragma unroll 1
    for (int it = 0; it < 10; it++) {
        __syncthreads();
        if (threadIdx.x == 0) {
            __threadfence();
            atomicAdd(&g_barc, 1u);
            unsigned tgt = (unsigned)(ev + 1) * gridDim.x;
            while (*((volatile unsigned*)&g_barc) < tgt) {}
            __threadfence();
        }
        __syncthreads();
        ev++;
        if (it == 9) break;
        float nf = fmaxf(__ldcg(&cur[n]) - dem, 0.0f);
        cur[n] = 0.0f;
        if (it == 8) {
            float4* o4 = reinterpret_cast<float4*>(out_pflow + (size_t)n * NK);
#pragma unroll
            for (int k = 0; k < 4; k++)
                o4[k] = make_float4(nw[4 * k] * nf, nw[4 * k + 1] * nf,
                                    nw[4 * k + 2] * nf, nw[4 * k + 3] * nf);
        }
        if (nf > 0.0f) {
#pragma unroll
            for (int k = 0; k < NK; k++)
                if (idxv[k] < NV) atomicAdd(&nxt[base + idxv[k]], nw[k] * nf);
        }
        float* t = cur; cur = nxt; nxt = t;
    }
    float nf = fmaxf(__ldcg(&cur[n]) - dem, 0.0f);
    cur[n] = 0.0f;
    {
        float4* o4 = reinterpret_cast<float4*>(out_flow + (size_t)n * NK);
#pragma unroll
        for (int k = 0; k < 4; k++)
            o4[k] = make_float4(nw[4 * k] * nf, nw[4 * k + 1] * nf,
                                nw[4 * k + 2] * nf, nw[4 * k + 3] * nf);
    }
    float val = nf * nf * sn;
#pragma unroll
    for (int o = 16; o > 0; o >>= 1) val += __shfl_xor_sync(0xffffffffu, val, o);
    __shared__ float wsum[8];
    if ((threadIdx.x & 31) == 0) wsum[threadIdx.x >> 5] = val;
    __syncthreads();
    if (threadIdx.x == 0) {
        float t = 0.0f;
#pragma unroll
        for (int i = 0; i < 8; i++) t += wsum[i];
        atomicAdd(&cost[n >> 14], t);
    }
}

// ---------------- launch ----------------
extern "C" void kernel_launch(void* const* d_in, const int* in_sizes, int n_in,
                              void* d_out, int out_size) {
    const float* emb     = (const float*)d_in[0];
    const float* feat    = (const float*)d_in[1];
    const float* demands = (const float*)d_in[2];
    const int*   adj     = (const int*)d_in[3];
    int wb = (in_sizes[5] == 1) ? 6 : 5;
    const float* W_enc1 = (const float*)d_in[wb + 0];
    const float* b_enc1 = (const float*)d_in[wb + 1];
    const float* W_enc2 = (const float*)d_in[wb + 2];
    const float* b_enc2 = (const float*)d_in[wb + 3];
    const float* W_gat  = (const float*)d_in[wb + 4];
    const float* a_src  = (const float*)d_in[wb + 5];
    const float* a_dst  = (const float*)d_in[wb + 6];
    const float* W_z    = (const float*)d_in[wb + 7];
    const float* U_z    = (const float*)d_in[wb + 8];
    const float* b_z    = (const float*)d_in[wb + 9];
    const float* W_r    = (const float*)d_in[wb + 10];
    const float* U_r    = (const float*)d_in[wb + 11];
    const float* b_r    = (const float*)d_in[wb + 12];
    const float* W_c    = (const float*)d_in[wb + 13];
    const float* U_c    = (const float*)d_in[wb + 14];
    const float* b_c    = (const float*)d_in[wb + 15];
    const float* W_dec1 = (const float*)d_in[wb + 16];
    const float* b_dec1 = (const float*)d_in[wb + 17];
    const float* W_dec2 = (const float*)d_in[wb + 18];
    const float* b_dec2 = (const float*)d_in[wb + 19];

    float* out = (float*)d_out;
    float* out_flow  = out;                               // [B,V,K] f10
    float* out_cost  = out + (size_t)NB * NV * NK;        // [B]
    float* out_normw = out_cost + NB;                     // [B,V,K]
    float* out_pflow = out_normw + (size_t)NB * NV * NK;  // [B,V,K] f9

    float *pA, *pB;
    cudaGetSymbolAddress((void**)&pA, g_inflowA);
    cudaGetSymbolAddress((void**)&pB, g_inflowB);
    unsigned* pbar;
    cudaGetSymbolAddress((void**)&pbar, g_barc);

    cudaFuncSetAttribute(k_encoder, cudaFuncAttributeMaxDynamicSharedMemorySize, ENC_SMEM);
    cudaFuncSetAttribute(k_gru, cudaFuncAttributeMaxDynamicSharedMemorySize, GRU_SMEM);

    k_wa<<<1, 256>>>(W_gat, a_src, a_dst);
    k_encoder<<<512, 256, ENC_SMEM>>>(emb, feat, W_enc1, b_enc1, W_enc2, b_enc2);
    k_gat_attn<<<NODES / 8, 256>>>(adj);
    k_gru<<<512, 256, GRU_SMEM>>>(W_z, U_z, b_z, W_r, U_r, b_r, W_c, U_c, b_c,
                                  W_gat, W_dec1, b_dec1, W_dec2, b_dec2, 0);
    k_gat_attn<<<NODES / 8, 256>>>(adj);
    k_gru<<<512, 256, GRU_SMEM>>>(W_z, U_z, b_z, W_r, U_r, b_r, W_c, U_c, b_c,
                                  W_gat, W_dec1, b_dec1, W_dec2, b_dec2, 1);

    cudaMemsetAsync(pbar, 0, sizeof(unsigned), 0);
    cudaMemsetAsync(out_cost, 0, NB * sizeof(float), 0);
    k_flow_all<<<256, 256>>>(adj, demands, out_normw, pA, pB, out_flow, out_pflow, out_cost);
}